// round 9
// baseline (speedup 1.0000x reference)
#include <cuda_runtime.h>
#include <math.h>
#include <float.h>

// ---------------- problem constants ----------------
#define NPTS  4096
#define DIN   784
#define DHID  256
#define MH    4
#define DHEAD 64
#define KP1   11
#define SIGMA_C 0.1f
#define DE_C  0.30151134457776363f   // 1/sqrt(11)

// ---------------- device scratch ----------------
__device__ float g_dist[(size_t)NPTS * NPTS];  // 64MB; after topk reused as int nbr[4096][4096]
__device__ float g_sq[NPTS];
__device__ int   g_idx[NPTS * KP1];
__device__ int   g_deg[NPTS];
__device__ float g_dv[NPTS];
__device__ int   g_roff[NPTS + 1];
__device__ int   g_cursor[NPTS];
__device__ int   g_redge[NPTS * KP1];
__device__ int   g_ncnt[NPTS];
__device__ float g_XT[NPTS * DHID];
__device__ float g_Xe[NPTS * DHID];
__device__ float g_E[NPTS * DHID];
__device__ float g_nrm[NPTS];
__device__ float g_rho[NPTS];
__device__ float g_rhoe[NPTS];
__device__ float g_P[NPTS * DHID];
__device__ float g_Q[NPTS * DHID];
__device__ float g_svh[MH * NPTS];
__device__ float g_tvh[MH * NPTS];
__device__ float g_Enew[NPTS * DHID];
__device__ float g_Xcat[NPTS * DHID];
__device__ unsigned g_smax[32];   // encoded float maxima

__device__ __forceinline__ unsigned encf(float f) {
    unsigned u = __float_as_uint(f);
    return (u & 0x80000000u) ? ~u : (u | 0x80000000u);
}
__device__ __forceinline__ float decf(unsigned u) {
    return __uint_as_float((u & 0x80000000u) ? (u & 0x7fffffffu) : ~u);
}

// ---------------- rowsq + fused zero-init ----------------
__global__ void k_rowsq(const float* __restrict__ X) {
    int gid = blockIdx.x * 128 + threadIdx.x;
    if (gid < NPTS) g_deg[gid] = 0;
    if (gid < 32) g_smax[gid] = 0u;
    int row = blockIdx.x * 4 + (threadIdx.x >> 5);
    int lane = threadIdx.x & 31;
    const float4* r = (const float4*)&X[(size_t)row * DIN];
    float a = 0.f;
    for (int c = lane; c < DIN / 4; c += 32) {
        float4 v = r[c];
        a += v.x * v.x + v.y * v.y + v.z * v.z + v.w * v.w;
    }
    for (int o = 16; o; o >>= 1) a += __shfl_xor_sync(0xffffffffu, a, o);
    if (lane == 0) g_sq[row] = a;
}

// ---- symmetric dist GEMM: upper-tri 128x128 blocks, mirrored f4 writes ----
__global__ __launch_bounds__(256) void k_aat_dist_sym(const float* __restrict__ A) {
    __shared__ float As[2][16][128];
    __shared__ float Bs[2][16][128];
    int b = blockIdx.x, by = 0;
    while (b >= 32 - by) { b -= 32 - by; ++by; }
    int bx = by + b;
    int row0 = by * 128, col0 = bx * 128;
    int t = threadIdx.x;
    int ty = t >> 4, tx = t & 15;
    int ra = t >> 2, qa = (t & 3) * 4;

    float4 pa0, pa1, pb0, pb1;
    pa0 = *(const float4*)&A[(size_t)(row0 + ra) * DIN + qa];
    pa1 = *(const float4*)&A[(size_t)(row0 + ra + 64) * DIN + qa];
    pb0 = *(const float4*)&A[(size_t)(col0 + ra) * DIN + qa];
    pb1 = *(const float4*)&A[(size_t)(col0 + ra + 64) * DIN + qa];
    As[0][qa + 0][ra] = pa0.x; As[0][qa + 1][ra] = pa0.y; As[0][qa + 2][ra] = pa0.z; As[0][qa + 3][ra] = pa0.w;
    As[0][qa + 0][ra + 64] = pa1.x; As[0][qa + 1][ra + 64] = pa1.y; As[0][qa + 2][ra + 64] = pa1.z; As[0][qa + 3][ra + 64] = pa1.w;
    Bs[0][qa + 0][ra] = pb0.x; Bs[0][qa + 1][ra] = pb0.y; Bs[0][qa + 2][ra] = pb0.z; Bs[0][qa + 3][ra] = pb0.w;
    Bs[0][qa + 0][ra + 64] = pb1.x; Bs[0][qa + 1][ra + 64] = pb1.y; Bs[0][qa + 2][ra + 64] = pb1.z; Bs[0][qa + 3][ra + 64] = pb1.w;
    __syncthreads();

    float acc[8][8];
#pragma unroll
    for (int i = 0; i < 8; i++)
#pragma unroll
        for (int j = 0; j < 8; j++) acc[i][j] = 0.f;

    const int nIt = DIN / 16;
    for (int it = 0; it < nIt; ++it) {
        int k0n = (it + 1) * 16;
        if (it + 1 < nIt) {
            pa0 = *(const float4*)&A[(size_t)(row0 + ra) * DIN + k0n + qa];
            pa1 = *(const float4*)&A[(size_t)(row0 + ra + 64) * DIN + k0n + qa];
            pb0 = *(const float4*)&A[(size_t)(col0 + ra) * DIN + k0n + qa];
            pb1 = *(const float4*)&A[(size_t)(col0 + ra + 64) * DIN + k0n + qa];
        }
        int buf = it & 1;
#pragma unroll
        for (int kk = 0; kk < 16; ++kk) {
            float4 a0 = *(const float4*)&As[buf][kk][ty * 8];
            float4 a1 = *(const float4*)&As[buf][kk][ty * 8 + 4];
            float4 b0 = *(const float4*)&Bs[buf][kk][tx * 8];
            float4 b1 = *(const float4*)&Bs[buf][kk][tx * 8 + 4];
            float ar[8] = {a0.x, a0.y, a0.z, a0.w, a1.x, a1.y, a1.z, a1.w};
            float br[8] = {b0.x, b0.y, b0.z, b0.w, b1.x, b1.y, b1.z, b1.w};
#pragma unroll
            for (int i = 0; i < 8; i++)
#pragma unroll
                for (int j = 0; j < 8; j++) acc[i][j] += ar[i] * br[j];
        }
        if (it + 1 < nIt) {
            int nb = buf ^ 1;
            As[nb][qa + 0][ra] = pa0.x; As[nb][qa + 1][ra] = pa0.y; As[nb][qa + 2][ra] = pa0.z; As[nb][qa + 3][ra] = pa0.w;
            As[nb][qa + 0][ra + 64] = pa1.x; As[nb][qa + 1][ra + 64] = pa1.y; As[nb][qa + 2][ra + 64] = pa1.z; As[nb][qa + 3][ra + 64] = pa1.w;
            Bs[nb][qa + 0][ra] = pb0.x; Bs[nb][qa + 1][ra] = pb0.y; Bs[nb][qa + 2][ra] = pb0.z; Bs[nb][qa + 3][ra] = pb0.w;
            Bs[nb][qa + 0][ra + 64] = pb1.x; Bs[nb][qa + 1][ra + 64] = pb1.y; Bs[nb][qa + 2][ra + 64] = pb1.z; Bs[nb][qa + 3][ra + 64] = pb1.w;
        }
        __syncthreads();
    }

    float si_[8], sj_[8];
#pragma unroll
    for (int i = 0; i < 8; i++) si_[i] = g_sq[row0 + ty * 8 + i];
#pragma unroll
    for (int j = 0; j < 8; j++) sj_[j] = g_sq[col0 + tx * 8 + j];

#pragma unroll
    for (int i = 0; i < 8; i++) {
        int gi = row0 + ty * 8 + i;
        float4 w0, w1;
        w0.x = fabsf(si_[i] + sj_[0] - 2.f * acc[i][0]);
        w0.y = fabsf(si_[i] + sj_[1] - 2.f * acc[i][1]);
        w0.z = fabsf(si_[i] + sj_[2] - 2.f * acc[i][2]);
        w0.w = fabsf(si_[i] + sj_[3] - 2.f * acc[i][3]);
        w1.x = fabsf(si_[i] + sj_[4] - 2.f * acc[i][4]);
        w1.y = fabsf(si_[i] + sj_[5] - 2.f * acc[i][5]);
        w1.z = fabsf(si_[i] + sj_[6] - 2.f * acc[i][6]);
        w1.w = fabsf(si_[i] + sj_[7] - 2.f * acc[i][7]);
        *(float4*)&g_dist[(size_t)gi * NPTS + col0 + tx * 8] = w0;
        *(float4*)&g_dist[(size_t)gi * NPTS + col0 + tx * 8 + 4] = w1;
    }
#pragma unroll
    for (int j = 0; j < 8; j++) {
        int gj = col0 + tx * 8 + j;
        float4 w0, w1;
        w0.x = fabsf(si_[0] + sj_[j] - 2.f * acc[0][j]);
        w0.y = fabsf(si_[1] + sj_[j] - 2.f * acc[1][j]);
        w0.z = fabsf(si_[2] + sj_[j] - 2.f * acc[2][j]);
        w0.w = fabsf(si_[3] + sj_[j] - 2.f * acc[3][j]);
        w1.x = fabsf(si_[4] + sj_[j] - 2.f * acc[4][j]);
        w1.y = fabsf(si_[5] + sj_[j] - 2.f * acc[5][j]);
        w1.z = fabsf(si_[6] + sj_[j] - 2.f * acc[6][j]);
        w1.w = fabsf(si_[7] + sj_[j] - 2.f * acc[7][j]);
        *(float4*)&g_dist[(size_t)gj * NPTS + row0 + ty * 8] = w0;
        *(float4*)&g_dist[(size_t)gj * NPTS + row0 + ty * 8 + 4] = w1;
    }
}

// ---- 4-warps-per-row top-11: batched loads (MLP=8) + smem candidate merge ----
__device__ __forceinline__ bool pless(float av, int ai, float bv, int bi) {
    return av < bv || (av == bv && ai < bi);
}

__global__ __launch_bounds__(256) void k_topk4() {
    __shared__ float sv[2][4 * KP1];
    __shared__ int   si_[2][4 * KP1];
    int wid = threadIdx.x >> 5;        // 0..7
    int lane = threadIdx.x & 31;
    int rloc = wid >> 2;               // 0/1 : row within block
    int q = wid & 3;                   // quarter
    int row = blockIdx.x * 2 + rloc;
    const float4* drow = (const float4*)&g_dist[(size_t)row * NPTS];

    // batched loads: 8 independent float4s in flight per lane
    float4 buf[8];
#pragma unroll
    for (int s = 0; s < 8; s++) buf[s] = drow[q * 256 + s * 32 + lane];

    float lv[KP1]; int li[KP1];
#pragma unroll
    for (int p = 0; p < KP1; p++) { lv[p] = FLT_MAX; li[p] = 0x7fffffff; }
#pragma unroll
    for (int s = 0; s < 8; s++) {
        float vv[4] = {buf[s].x, buf[s].y, buf[s].z, buf[s].w};
        int jb = (q * 256 + s * 32 + lane) * 4;
#pragma unroll
        for (int c = 0; c < 4; c++) {
            float v = vv[c]; int j = jb + c;
            if (pless(v, j, lv[KP1 - 1], li[KP1 - 1])) {
                lv[KP1 - 1] = v; li[KP1 - 1] = j;
#pragma unroll
                for (int p = KP1 - 1; p > 0; p--) {
                    if (pless(lv[p], li[p], lv[p - 1], li[p - 1])) {
                        float tv_ = lv[p]; lv[p] = lv[p - 1]; lv[p - 1] = tv_;
                        int ti_ = li[p]; li[p] = li[p - 1]; li[p - 1] = ti_;
                    }
                }
            }
        }
    }
    // warp-local top-11 extraction into smem (sorted)
    for (int it = 0; it < KP1; ++it) {
        float v = lv[0]; int ix = li[0];
#pragma unroll
        for (int o = 16; o; o >>= 1) {
            float ov = __shfl_xor_sync(0xffffffffu, v, o);
            int oi = __shfl_xor_sync(0xffffffffu, ix, o);
            if (pless(ov, oi, v, ix)) { v = ov; ix = oi; }
        }
        if (li[0] == ix) {  // unique winner lane pops its head
#pragma unroll
            for (int p = 0; p < KP1 - 1; p++) { lv[p] = lv[p + 1]; li[p] = li[p + 1]; }
            lv[KP1 - 1] = FLT_MAX; li[KP1 - 1] = 0x7fffffff;
        }
        if (lane == 0) { sv[rloc][q * KP1 + it] = v; si_[rloc][q * KP1 + it] = ix; }
    }
    __syncthreads();
    // merge 44 candidates (warp q==0 of each row); 2 candidates/lane (lane, lane+22)
    if (q == 0) {
        float c0 = (lane < 22) ? sv[rloc][lane] : FLT_MAX;
        int   i0 = (lane < 22) ? si_[rloc][lane] : 0x7fffffff;
        float c1 = (lane < 22) ? sv[rloc][lane + 22] : FLT_MAX;
        int   i1 = (lane < 22) ? si_[rloc][lane + 22] : 0x7fffffff;
        for (int it = 0; it < KP1; ++it) {
            float v; int ix;
            if (pless(c0, i0, c1, i1)) { v = c0; ix = i0; } else { v = c1; ix = i1; }
#pragma unroll
            for (int o = 16; o; o >>= 1) {
                float ov = __shfl_xor_sync(0xffffffffu, v, o);
                int oi = __shfl_xor_sync(0xffffffffu, ix, o);
                if (pless(ov, oi, v, ix)) { v = ov; ix = oi; }
            }
            if (i0 == ix) { c0 = FLT_MAX; i0 = 0x7fffffff; }
            else if (i1 == ix) { c1 = FLT_MAX; i1 = 0x7fffffff; }
            if (lane == 0) {
                g_idx[row * KP1 + it] = ix;
                atomicAdd(&g_deg[ix], 1);
            }
        }
    }
}

// parallel scan of deg + dv + cursor + CSR fill, single block
__global__ void k_scanfill() {
    __shared__ int s[1024];
    int t = threadIdx.x;
    int base = t * 4;
    int v0 = g_deg[base], v1 = g_deg[base + 1], v2 = g_deg[base + 2], v3 = g_deg[base + 3];
    int sum = v0 + v1 + v2 + v3;
    s[t] = sum;
    __syncthreads();
    for (int off = 1; off < 1024; off <<= 1) {
        int x = (t >= off) ? s[t - off] : 0;
        __syncthreads();
        s[t] += x;
        __syncthreads();
    }
    int run = s[t] - sum;
    g_roff[base] = run; g_cursor[base] = run; g_dv[base] = rsqrtf((float)v0); run += v0;
    g_roff[base + 1] = run; g_cursor[base + 1] = run; g_dv[base + 1] = rsqrtf((float)v1); run += v1;
    g_roff[base + 2] = run; g_cursor[base + 2] = run; g_dv[base + 2] = rsqrtf((float)v2); run += v2;
    g_roff[base + 3] = run; g_cursor[base + 3] = run; g_dv[base + 3] = rsqrtf((float)v3); run += v3;
    if (t == 1023) g_roff[NPTS] = run;
    __syncthreads();
    for (int p = t; p < NPTS * KP1; p += 1024) {
        int i = g_idx[p];
        int pos = atomicAdd(&g_cursor[i], 1);
        g_redge[pos] = p / KP1;
    }
}

// dedup'd ascending neighbor lists into g_dist region
__global__ void k_nbr() {
    __shared__ unsigned bm[128];
    __shared__ int wsum[4];
    int i = blockIdx.x, t = threadIdx.x;
    bm[t] = 0u;
    __syncthreads();
    int beg = g_roff[i];
    int cnt = (g_roff[i + 1] - beg) * KP1;
    for (int p = t; p < cnt; p += 128) {
        int e = g_redge[beg + p / KP1];
        int m = g_idx[e * KP1 + p % KP1];
        atomicOr(&bm[m >> 5], 1u << (m & 31));
    }
    __syncthreads();
    if (t == 0) bm[i >> 5] &= ~(1u << (i & 31));
    __syncthreads();
    unsigned w = bm[t];
    int pc = __popc(w);
    int lane = t & 31, wid = t >> 5;
    int sc = pc;
    for (int o = 1; o < 32; o <<= 1) {
        int x = __shfl_up_sync(0xffffffffu, sc, o);
        if (lane >= o) sc += x;
    }
    if (lane == 31) wsum[wid] = sc;
    __syncthreads();
    int woff = 0;
    for (int q = 0; q < wid; q++) woff += wsum[q];
    int off = woff + sc - pc;
    int* nbr = (int*)g_dist + (size_t)i * NPTS;
    while (w) {
        int b = __ffs(w) - 1; w &= w - 1;
        nbr[off++] = t * 32 + b;
    }
    if (t == 127) g_ncnt[i] = woff + sc;
}

// ---- 128x64 GEMM, double buffered ----
__device__ __forceinline__ void gemm64_body(const float* __restrict__ A,
                                            const float* __restrict__ B, int ldb,
                                            float* __restrict__ C, int ldc,
                                            int K, int m0, int n0b) {
    __shared__ float As[2][16][128];
    __shared__ float Bs[2][16][64];
    int t = threadIdx.x;
    int ty = t >> 4, tx = t & 15;
    int ra = t >> 1, qa = (t & 1) * 8;
    int kb = t >> 4, cb = (t & 15) * 4;

    float4 pa0, pa1, pb;
    pa0 = *(const float4*)&A[(size_t)(m0 + ra) * K + qa];
    pa1 = *(const float4*)&A[(size_t)(m0 + ra) * K + qa + 4];
    pb = *(const float4*)&B[(size_t)kb * ldb + cb];
    As[0][qa + 0][ra] = pa0.x; As[0][qa + 1][ra] = pa0.y; As[0][qa + 2][ra] = pa0.z; As[0][qa + 3][ra] = pa0.w;
    As[0][qa + 4][ra] = pa1.x; As[0][qa + 5][ra] = pa1.y; As[0][qa + 6][ra] = pa1.z; As[0][qa + 7][ra] = pa1.w;
    *(float4*)&Bs[0][kb][cb] = pb;
    __syncthreads();

    float acc[8][4];
#pragma unroll
    for (int i = 0; i < 8; i++)
#pragma unroll
        for (int j = 0; j < 4; j++) acc[i][j] = 0.f;

    int nIt = K / 16;
    for (int it = 0; it < nIt; ++it) {
        int k0n = (it + 1) * 16;
        if (it + 1 < nIt) {
            pa0 = *(const float4*)&A[(size_t)(m0 + ra) * K + k0n + qa];
            pa1 = *(const float4*)&A[(size_t)(m0 + ra) * K + k0n + qa + 4];
            pb = *(const float4*)&B[(size_t)(k0n + kb) * ldb + cb];
        }
        int buf = it & 1;
#pragma unroll
        for (int kk = 0; kk < 16; ++kk) {
            float4 a0 = *(const float4*)&As[buf][kk][ty * 8];
            float4 a1 = *(const float4*)&As[buf][kk][ty * 8 + 4];
            float4 b0 = *(const float4*)&Bs[buf][kk][tx * 4];
            float ar[8] = {a0.x, a0.y, a0.z, a0.w, a1.x, a1.y, a1.z, a1.w};
            float br[4] = {b0.x, b0.y, b0.z, b0.w};
#pragma unroll
            for (int i = 0; i < 8; i++)
#pragma unroll
                for (int j = 0; j < 4; j++) acc[i][j] += ar[i] * br[j];
        }
        if (it + 1 < nIt) {
            int nb = buf ^ 1;
            As[nb][qa + 0][ra] = pa0.x; As[nb][qa + 1][ra] = pa0.y; As[nb][qa + 2][ra] = pa0.z; As[nb][qa + 3][ra] = pa0.w;
            As[nb][qa + 4][ra] = pa1.x; As[nb][qa + 5][ra] = pa1.y; As[nb][qa + 6][ra] = pa1.z; As[nb][qa + 7][ra] = pa1.w;
            *(float4*)&Bs[nb][kb][cb] = pb;
        }
        __syncthreads();
    }
#pragma unroll
    for (int i = 0; i < 8; i++) {
        float4 w0 = {acc[i][0], acc[i][1], acc[i][2], acc[i][3]};
        *(float4*)&C[(size_t)(m0 + ty * 8 + i) * ldc + n0b + tx * 4] = w0;
    }
}

__global__ __launch_bounds__(256) void k_gemm64(const float* __restrict__ A,
                                                const float* __restrict__ B,
                                                float* __restrict__ C, int K, int Np) {
    gemm64_body(A, B + blockIdx.x * 64, Np, C, Np, K, blockIdx.y * 128, blockIdx.x * 64);
}

__global__ __launch_bounds__(256) void k_gemm64h2(const float* __restrict__ A1,
                                                  const float* __restrict__ A2,
                                                  const float* __restrict__ Wh,
                                                  float* __restrict__ C1,
                                                  float* __restrict__ C2) {
    int half = blockIdx.y >> 5;
    int m0 = (blockIdx.y & 31) * 128;
    int h = blockIdx.x;
    gemm64_body(half ? A2 : A1, Wh + (size_t)h * DHID * 64, 64,
                half ? C2 : C1, DHID, DHID, m0, h * 64);
}

__global__ __launch_bounds__(256) void k_gemm64d(const float* __restrict__ A1,
                                                 const float* __restrict__ A2,
                                                 const float* __restrict__ B,
                                                 float* __restrict__ C1,
                                                 float* __restrict__ C2) {
    int half = blockIdx.y >> 5;
    int m0 = (blockIdx.y & 31) * 128;
    gemm64_body(half ? A2 : A1, B + blockIdx.x * 64, DHID,
                half ? C2 : C1, DHID, DHID, m0, blockIdx.x * 64);
}

// ---- hypergraph gathers (vectorized, norm fused into edges) ----
__global__ void k_gather_edges() {
    int e = blockIdx.x * 4 + (threadIdx.x >> 5);
    int lane = threadIdx.x & 31;
    float4 a0 = {0, 0, 0, 0}, a1 = {0, 0, 0, 0};
    for (int k = 0; k < KP1; k++) {
        int i = g_idx[e * KP1 + k];
        float w = g_dv[i];
        const float4* r = (const float4*)&g_XT[(size_t)i * DHID];
        float4 x0 = r[lane], x1 = r[lane + 32];
        a0.x += w * x0.x; a0.y += w * x0.y; a0.z += w * x0.z; a0.w += w * x0.w;
        a1.x += w * x1.x; a1.y += w * x1.y; a1.z += w * x1.z; a1.w += w * x1.w;
    }
    a0.x *= DE_C; a0.y *= DE_C; a0.z *= DE_C; a0.w *= DE_C;
    a1.x *= DE_C; a1.y *= DE_C; a1.z *= DE_C; a1.w *= DE_C;
    float4* o = (float4*)&g_Xe[(size_t)e * DHID];
    o[lane] = a0; o[lane + 32] = a1;
    float nq = a0.x * a0.x + a0.y * a0.y + a0.z * a0.z + a0.w * a0.w
             + a1.x * a1.x + a1.y * a1.y + a1.z * a1.z + a1.w * a1.w;
    for (int of = 16; of; of >>= 1) nq += __shfl_xor_sync(0xffffffffu, nq, of);
    if (lane == 0) g_nrm[e] = sqrtf(nq);
}

__global__ void k_gather_nodes() {
    int i = blockIdx.x * 4 + (threadIdx.x >> 5);
    int lane = threadIdx.x & 31;
    int beg = g_roff[i], end = g_roff[i + 1];
    float4 a0 = {0, 0, 0, 0}, a1 = {0, 0, 0, 0};
    for (int k = beg; k < end; k++) {
        const float4* r = (const float4*)&g_Xe[(size_t)g_redge[k] * DHID];
        float4 x0 = r[lane], x1 = r[lane + 32];
        a0.x += x0.x; a0.y += x0.y; a0.z += x0.z; a0.w += x0.w;
        a1.x += x1.x; a1.y += x1.y; a1.z += x1.z; a1.w += x1.w;
    }
    float s = g_dv[i] * DE_C;
    a0.x *= s; a0.y *= s; a0.z *= s; a0.w *= s;
    a1.x *= s; a1.y *= s; a1.z *= s; a1.w *= s;
    float4* o = (float4*)&g_E[(size_t)i * DHID];
    o[lane] = a0; o[lane + 32] = a1;
}

__global__ void k_rownorm(const float* __restrict__ Xf) {
    int row = blockIdx.x * 4 + (threadIdx.x >> 5);
    int lane = threadIdx.x & 31;
    const float4* r = (const float4*)&Xf[(size_t)row * DHID];
    float4 x0 = r[lane], x1 = r[lane + 32];
    float a = x0.x * x0.x + x0.y * x0.y + x0.z * x0.z + x0.w * x0.w
            + x1.x * x1.x + x1.y * x1.y + x1.z * x1.z + x1.w * x1.w;
    for (int o = 16; o; o >>= 1) a += __shfl_xor_sync(0xffffffffu, a, o);
    if (lane == 0) g_nrm[row] = sqrtf(a);
}

// density: 2-way unrolled neighbor dot products
__global__ void k_density(const float* __restrict__ Xf) {
    __shared__ float xs[DHID];
    __shared__ float ps[8];
    int i = blockIdx.x, t = threadIdx.x;
    xs[t] = Xf[(size_t)i * DHID + t];
    __syncthreads();
    int lane = t & 31, wp = t >> 5;
    const float4* xs4 = (const float4*)xs;
    float4 x0 = xs4[lane], x1 = xs4[lane + 32];
    const int* nbr = (const int*)g_dist + (size_t)i * NPTS;
    int n = g_ncnt[i];
    float ni = g_nrm[i], part = 0.f;
    for (int e0 = wp; e0 < n; e0 += 16) {
        int e1 = e0 + 8;
        bool have2 = (e1 < n);
        int j1 = nbr[e0];
        int j2 = have2 ? nbr[e1] : j1;
        const float4* r1 = (const float4*)&Xf[(size_t)j1 * DHID];
        const float4* r2 = (const float4*)&Xf[(size_t)j2 * DHID];
        float4 a0 = r1[lane], a1 = r1[lane + 32];
        float4 b0 = r2[lane], b1 = r2[lane + 32];
        float d1 = x0.x * a0.x + x0.y * a0.y + x0.z * a0.z + x0.w * a0.w
                 + x1.x * a1.x + x1.y * a1.y + x1.z * a1.z + x1.w * a1.w;
        float d2 = x0.x * b0.x + x0.y * b0.y + x0.z * b0.z + x0.w * b0.w
                 + x1.x * b1.x + x1.y * b1.y + x1.z * b1.z + x1.w * b1.w;
#pragma unroll
        for (int o = 16; o; o >>= 1) {
            d1 += __shfl_xor_sync(0xffffffffu, d1, o);
            d2 += __shfl_xor_sync(0xffffffffu, d2, o);
        }
        if (lane == 0) {
            float c1 = d1 / (ni * g_nrm[j1]);
            if (c1 > SIGMA_C) part += c1;
            if (have2) {
                float c2 = d2 / (ni * g_nrm[j2]);
                if (c2 > SIGMA_C) part += c2;
            }
        }
    }
    if (lane == 0) ps[wp] = part;
    __syncthreads();
    if (t == 0) {
        float a = 0.f;
        for (int q = 0; q < 8; q++) a += ps[q];
        g_rho[i] = a;
    }
}

// rhoe + fused maxima of rho and rhoe
__global__ void k_rhoe(int rslot, int reslot) {
    __shared__ float sm1[8], sm2[8];
    int e = blockIdx.x * 256 + threadIdx.x;
    float r = 0.f;
    for (int k = 0; k < KP1; k++) r += g_rho[g_idx[e * KP1 + k]];
    g_rhoe[e] = r;
    float rr = g_rho[e];
    for (int o = 16; o; o >>= 1) {
        r = fmaxf(r, __shfl_xor_sync(0xffffffffu, r, o));
        rr = fmaxf(rr, __shfl_xor_sync(0xffffffffu, rr, o));
    }
    int t = threadIdx.x;
    if ((t & 31) == 0) { sm1[t >> 5] = rr; sm2[t >> 5] = r; }
    __syncthreads();
    if (t == 0) {
        float m1 = sm1[0], m2 = sm2[0];
        for (int q = 1; q < 8; q++) { m1 = fmaxf(m1, sm1[q]); m2 = fmaxf(m2, sm2[q]); }
        atomicMax(&g_smax[rslot], encf(m1));
        atomicMax(&g_smax[reslot], encf(m2));
    }
}

// all-heads s/t matvec (D=64, float2) + fused per-slot max
__global__ void k_svtv4(const float* __restrict__ Ms, const float* __restrict__ Mt,
                        const float* __restrict__ av, int sb) {
    __shared__ float sm[8];
    int w = (blockIdx.x * 256 + threadIdx.x) >> 5;
    int lane = threadIdx.x & 31;
    int row = w & (NPTS - 1);
    int g = w >> 12;
    int h = g & 3, which = g >> 2;
    const float* M = which ? Mt : Ms;
    const float2* a2 = (const float2*)(av + (size_t)h * 2 * DHEAD + which * DHEAD);
    const float2* r2 = (const float2*)(M + (size_t)row * DHID + h * DHEAD);
    float2 rv = r2[lane], av2 = a2[lane];
    float p = rv.x * av2.x + rv.y * av2.y;
    for (int o = 16; o; o >>= 1) p += __shfl_xor_sync(0xffffffffu, p, o);
    if (lane == 0) {
        (which ? g_tvh : g_svh)[h * NPTS + row] = p;
        sm[(threadIdx.x >> 5)] = p;
    }
    __syncthreads();
    if (threadIdx.x == 0) {
        float m = sm[0];
        for (int q = 1; q < 8; q++) m = fmaxf(m, sm[q]);
        atomicMax(&g_smax[sb + which * 4 + h], encf(m));
    }
}

// final s/t matvec D=256 + fused max
__global__ void k_svtv1(const float* __restrict__ Ms, const float* __restrict__ as,
                        const float* __restrict__ Mt, const float* __restrict__ at, int sb) {
    __shared__ float sm[8];
    int w = (blockIdx.x * 256 + threadIdx.x) >> 5;
    int lane = threadIdx.x & 31;
    int row = w & (NPTS - 1);
    int which = w >> 12;
    const float* M = which ? Mt : Ms;
    const float* a = which ? at : as;
    const float4* r = (const float4*)(M + (size_t)row * DHID);
    const float4* a4 = (const float4*)a;
    float4 r0 = r[lane], r1 = r[lane + 32];
    float4 b0 = a4[lane], b1 = a4[lane + 32];
    float p = r0.x * b0.x + r0.y * b0.y + r0.z * b0.z + r0.w * b0.w
            + r1.x * b1.x + r1.y * b1.y + r1.z * b1.z + r1.w * b1.w;
    for (int o = 16; o; o >>= 1) p += __shfl_xor_sync(0xffffffffu, p, o);
    if (lane == 0) {
        (which ? g_tvh : g_svh)[row] = p;
        sm[(threadIdx.x >> 5)] = p;
    }
    __syncthreads();
    if (threadIdx.x == 0) {
        float m = sm[0];
        for (int q = 1; q < 8; q++) m = fmaxf(m, sm[q]);
        atomicMax(&g_smax[sb + which], encf(m));
    }
}

__device__ __forceinline__ float lrelu(float x) { return x > 0.f ? x : 0.2f * x; }
__device__ __forceinline__ float elu1(float x) { return x > 0.f ? x : expm1f(x); }

// attention: grid (1024, nheads); float2-vectorized value gathers
template <int D>
__global__ void k_att4(const float* __restrict__ rho, int rslot,
                       const float* __restrict__ valb, int ldv,
                       float* __restrict__ outb, int ldo, int hstride, int sb, int nh) {
    int h = blockIdx.y;
    int row = blockIdx.x * 4 + (threadIdx.x >> 5);
    int lane = threadIdx.x & 31;
    const float* sA = g_svh + h * NPTS;
    const float* tA = g_tvh + h * NPTS;
    float smx = decf(g_smax[sb + h]);
    float tmx = decf(g_smax[sb + nh + h]);
    float ax_max = lrelu(smx + tmx);
    float rt = rho[row] / decf(g_smax[rslot]) * ax_max;
    float si = sA[row];
    int beg = g_roff[row], end = g_roff[row + 1];
    int deg = end - beg;
    const float* val = valb + h * hstride;
    float* out = outb + h * hstride;
    const int C2 = D / 64;
    float2 acc[C2];
#pragma unroll
    for (int j = 0; j < C2; j++) acc[j] = make_float2(0.f, 0.f);
    float iz;
    if (deg <= 32) {
        int mye = (lane < deg) ? g_redge[beg + lane] : 0;
        float st = (lane < deg) ? (lrelu(si + tA[mye]) + rt) : -FLT_MAX;
        float m = st;
        for (int o = 16; o; o >>= 1) m = fmaxf(m, __shfl_xor_sync(0xffffffffu, m, o));
        float myw = (lane < deg) ? expf(st - m) : 0.f;
        float Z = myw;
        for (int o = 16; o; o >>= 1) Z += __shfl_xor_sync(0xffffffffu, Z, o);
        for (int k = 0; k < deg; k++) {
            int e = __shfl_sync(0xffffffffu, mye, k);
            float wt = __shfl_sync(0xffffffffu, myw, k);
            const float2* v2 = (const float2*)&val[(size_t)e * ldv];
#pragma unroll
            for (int j = 0; j < C2; j++) {
                float2 x = v2[lane + j * 32];
                acc[j].x += wt * x.x; acc[j].y += wt * x.y;
            }
        }
        iz = 1.f / Z;
    } else {
        float m = -FLT_MAX;
        for (int k = beg + lane; k < end; k += 32)
            m = fmaxf(m, lrelu(si + tA[g_redge[k]]) + rt);
        for (int o = 16; o; o >>= 1) m = fmaxf(m, __shfl_xor_sync(0xffffffffu, m, o));
        float Z = 0.f;
        for (int k = beg + lane; k < end; k += 32)
            Z += expf(lrelu(si + tA[g_redge[k]]) + rt - m);
        for (int o = 16; o; o >>= 1) Z += __shfl_xor_sync(0xffffffffu, Z, o);
        for (int k = beg; k < end; k++) {
            int e = g_redge[k];
            float wt = expf(lrelu(si + tA[e]) + rt - m);
            const float2* v2 = (const float2*)&val[(size_t)e * ldv];
#pragma unroll
            for (int j = 0; j < C2; j++) {
                float2 x = v2[lane + j * 32];
                acc[j].x += wt * x.x; acc[j].y += wt * x.y;
            }
        }
        iz = 1.f / Z;
    }
    float2* o2 = (float2*)&out[(size_t)row * ldo];
#pragma unroll
    for (int j = 0; j < C2; j++) {
        float2 r;
        r.x = elu1(acc[j].x * iz);
        r.y = elu1(acc[j].y * iz);
        o2[lane + j * 32] = r;
    }
}

// ---------------- host orchestration ----------------
extern "C" void kernel_launch(void* const* d_in, const int* in_sizes, int n_in,
                              void* d_out, int out_size) {
    const float* X     = (const float*)d_in[0];
    const float* theta = (const float*)d_in[1];
    const float* Wh    = (const float*)d_in[2];
    const float* axh   = (const float*)d_in[3];
    const float* aeh   = (const float*)d_in[4];
    const float* W2    = (const float*)d_in[5];
    const float* ax2   = (const float*)d_in[6];
    const float* ae2   = (const float*)d_in[7];
    float* out = (float*)d_out;
    (void)in_sizes; (void)n_in; (void)out_size;

    void* vp;
    cudaGetSymbolAddress(&vp, g_XT);   float* XT   = (float*)vp;
    cudaGetSymbolAddress(&vp, g_Xe);   float* Xe   = (float*)vp;
    cudaGetSymbolAddress(&vp, g_E);    float* E    = (float*)vp;
    cudaGetSymbolAddress(&vp, g_rho);  float* rho  = (float*)vp;
    cudaGetSymbolAddress(&vp, g_rhoe); float* rhoe = (float*)vp;
    cudaGetSymbolAddress(&vp, g_P);    float* P    = (float*)vp;
    cudaGetSymbolAddress(&vp, g_Q);    float* Q    = (float*)vp;
    cudaGetSymbolAddress(&vp, g_Enew); float* Enew = (float*)vp;
    cudaGetSymbolAddress(&vp, g_Xcat); float* Xcat = (float*)vp;

    // profiled slot #4 = k_gemm64 (X@theta)
    k_rowsq<<<NPTS / 4, 128>>>(X);          // also zeroes deg/smax
    k_aat_dist_sym<<<528, 256>>>(X);
    k_topk4<<<NPTS / 2, 256>>>();
    k_gemm64<<<dim3(4, 32), 256>>>(X, theta, XT, DIN, DHID);   // profiled

    k_scanfill<<<1, 1024>>>();
    k_gather_edges<<<NPTS / 4, 128>>>();
    k_gather_nodes<<<NPTS / 4, 128>>>();
    k_nbr<<<NPTS, 128>>>();

    // densities (stage 1)
    k_density<<<NPTS, 256>>>(Xe);
    k_rhoe<<<16, 256>>>(20, 21);

    // all-head projections
    k_gemm64h2<<<dim3(4, 64), 256>>>(Xe, E, Wh, P, Q);

    // attention pass 1
    k_svtv4<<<4096, 256>>>(P, Q, axh, 0);
    k_att4<DHEAD><<<dim3(NPTS / 4, MH), 128>>>(rho, 20, P, DHID, Enew, DHID, DHEAD, 0, 4);

    // attention pass 2
    k_svtv4<<<4096, 256>>>(Q, P, aeh, 8);
    k_att4<DHEAD><<<dim3(NPTS / 4, MH), 128>>>(rhoe, 21, Enew, DHID, Xcat, DHID, DHEAD, 8, 4);

    // final DA-HGAN layer
    k_rownorm<<<NPTS / 4, 128>>>(Xcat);
    k_density<<<NPTS, 256>>>(Xcat);
    k_rhoe<<<16, 256>>>(22, 23);

    k_gemm64d<<<dim3(4, 64), 256>>>(Xcat, E, W2, P, Q);

    k_svtv1<<<1024, 256>>>(P, ax2, Q, ax2 + DHID, 16);
    k_att4<DHID><<<dim3(NPTS / 4, 1), 128>>>(rho, 22, P, DHID, Enew, DHID, 0, 16, 1);

    k_svtv1<<<1024, 256>>>(Q, ae2, P, ae2 + DHID, 18);
    k_att4<DHID><<<dim3(NPTS / 4, 1), 128>>>(rhoe, 23, Enew, DHID, out, DHID, 0, 18, 1);
}

// round 10
// speedup vs baseline: 1.0018x; 1.0018x over previous
#include <cuda_runtime.h>
#include <math.h>
#include <float.h>

// ---------------- problem constants ----------------
#define NPTS  4096
#define DIN   784
#define DHID  256
#define MH    4
#define DHEAD 64
#define KP1   11
#define SIGMA_C 0.1f
#define DE_C  0.30151134457776363f   // 1/sqrt(11)

// ---------------- device scratch ----------------
__device__ float g_dist[(size_t)NPTS * NPTS];  // 64MB; after topk reused as int nbr[4096][4096]
__device__ float g_sq[NPTS];
__device__ int   g_idx[NPTS * KP1];
__device__ int   g_deg[NPTS];
__device__ float g_dv[NPTS];
__device__ int   g_roff[NPTS + 1];
__device__ int   g_cursor[NPTS];
__device__ int   g_redge[NPTS * KP1];
__device__ int   g_ncnt[NPTS];
__device__ float g_XT[NPTS * DHID];
__device__ float g_Xe[NPTS * DHID];
__device__ float g_E[NPTS * DHID];
__device__ float g_nrm[NPTS];
__device__ float g_rho[NPTS];
__device__ float g_rhoe[NPTS];
__device__ float g_P[NPTS * DHID];
__device__ float g_Q[NPTS * DHID];
__device__ float g_svh[MH * NPTS];
__device__ float g_tvh[MH * NPTS];
__device__ float g_Enew[NPTS * DHID];
__device__ float g_Xcat[NPTS * DHID];
__device__ unsigned g_smax[32];   // encoded float maxima

__device__ __forceinline__ unsigned encf(float f) {
    unsigned u = __float_as_uint(f);
    return (u & 0x80000000u) ? ~u : (u | 0x80000000u);
}
__device__ __forceinline__ float decf(unsigned u) {
    return __uint_as_float((u & 0x80000000u) ? (u & 0x7fffffffu) : ~u);
}

// ---------------- rowsq + fused zero-init ----------------
__global__ void k_rowsq(const float* __restrict__ X) {
    int gid = blockIdx.x * 128 + threadIdx.x;
    if (gid < NPTS) g_deg[gid] = 0;
    if (gid < 32) g_smax[gid] = 0u;
    int row = blockIdx.x * 4 + (threadIdx.x >> 5);
    int lane = threadIdx.x & 31;
    const float4* r = (const float4*)&X[(size_t)row * DIN];
    float a = 0.f;
    for (int c = lane; c < DIN / 4; c += 32) {
        float4 v = r[c];
        a += v.x * v.x + v.y * v.y + v.z * v.z + v.w * v.w;
    }
    for (int o = 16; o; o >>= 1) a += __shfl_xor_sync(0xffffffffu, a, o);
    if (lane == 0) g_sq[row] = a;
}

// ---- symmetric dist GEMM: upper-tri 128x128 blocks, mirrored f4 writes ----
__global__ __launch_bounds__(256) void k_aat_dist_sym(const float* __restrict__ A) {
    __shared__ float As[2][16][128];
    __shared__ float Bs[2][16][128];
    int b = blockIdx.x, by = 0;
    while (b >= 32 - by) { b -= 32 - by; ++by; }
    int bx = by + b;
    int row0 = by * 128, col0 = bx * 128;
    int t = threadIdx.x;
    int ty = t >> 4, tx = t & 15;
    int ra = t >> 2, qa = (t & 3) * 4;

    float4 pa0, pa1, pb0, pb1;
    pa0 = *(const float4*)&A[(size_t)(row0 + ra) * DIN + qa];
    pa1 = *(const float4*)&A[(size_t)(row0 + ra + 64) * DIN + qa];
    pb0 = *(const float4*)&A[(size_t)(col0 + ra) * DIN + qa];
    pb1 = *(const float4*)&A[(size_t)(col0 + ra + 64) * DIN + qa];
    As[0][qa + 0][ra] = pa0.x; As[0][qa + 1][ra] = pa0.y; As[0][qa + 2][ra] = pa0.z; As[0][qa + 3][ra] = pa0.w;
    As[0][qa + 0][ra + 64] = pa1.x; As[0][qa + 1][ra + 64] = pa1.y; As[0][qa + 2][ra + 64] = pa1.z; As[0][qa + 3][ra + 64] = pa1.w;
    Bs[0][qa + 0][ra] = pb0.x; Bs[0][qa + 1][ra] = pb0.y; Bs[0][qa + 2][ra] = pb0.z; Bs[0][qa + 3][ra] = pb0.w;
    Bs[0][qa + 0][ra + 64] = pb1.x; Bs[0][qa + 1][ra + 64] = pb1.y; Bs[0][qa + 2][ra + 64] = pb1.z; Bs[0][qa + 3][ra + 64] = pb1.w;
    __syncthreads();

    float acc[8][8];
#pragma unroll
    for (int i = 0; i < 8; i++)
#pragma unroll
        for (int j = 0; j < 8; j++) acc[i][j] = 0.f;

    const int nIt = DIN / 16;
    for (int it = 0; it < nIt; ++it) {
        int k0n = (it + 1) * 16;
        if (it + 1 < nIt) {
            pa0 = *(const float4*)&A[(size_t)(row0 + ra) * DIN + k0n + qa];
            pa1 = *(const float4*)&A[(size_t)(row0 + ra + 64) * DIN + k0n + qa];
            pb0 = *(const float4*)&A[(size_t)(col0 + ra) * DIN + k0n + qa];
            pb1 = *(const float4*)&A[(size_t)(col0 + ra + 64) * DIN + k0n + qa];
        }
        int buf = it & 1;
#pragma unroll
        for (int kk = 0; kk < 16; ++kk) {
            float4 a0 = *(const float4*)&As[buf][kk][ty * 8];
            float4 a1 = *(const float4*)&As[buf][kk][ty * 8 + 4];
            float4 b0 = *(const float4*)&Bs[buf][kk][tx * 8];
            float4 b1 = *(const float4*)&Bs[buf][kk][tx * 8 + 4];
            float ar[8] = {a0.x, a0.y, a0.z, a0.w, a1.x, a1.y, a1.z, a1.w};
            float br[8] = {b0.x, b0.y, b0.z, b0.w, b1.x, b1.y, b1.z, b1.w};
#pragma unroll
            for (int i = 0; i < 8; i++)
#pragma unroll
                for (int j = 0; j < 8; j++) acc[i][j] += ar[i] * br[j];
        }
        if (it + 1 < nIt) {
            int nb = buf ^ 1;
            As[nb][qa + 0][ra] = pa0.x; As[nb][qa + 1][ra] = pa0.y; As[nb][qa + 2][ra] = pa0.z; As[nb][qa + 3][ra] = pa0.w;
            As[nb][qa + 0][ra + 64] = pa1.x; As[nb][qa + 1][ra + 64] = pa1.y; As[nb][qa + 2][ra + 64] = pa1.z; As[nb][qa + 3][ra + 64] = pa1.w;
            Bs[nb][qa + 0][ra] = pb0.x; Bs[nb][qa + 1][ra] = pb0.y; Bs[nb][qa + 2][ra] = pb0.z; Bs[nb][qa + 3][ra] = pb0.w;
            Bs[nb][qa + 0][ra + 64] = pb1.x; Bs[nb][qa + 1][ra + 64] = pb1.y; Bs[nb][qa + 2][ra + 64] = pb1.z; Bs[nb][qa + 3][ra + 64] = pb1.w;
        }
        __syncthreads();
    }

    float si_[8], sj_[8];
#pragma unroll
    for (int i = 0; i < 8; i++) si_[i] = g_sq[row0 + ty * 8 + i];
#pragma unroll
    for (int j = 0; j < 8; j++) sj_[j] = g_sq[col0 + tx * 8 + j];

#pragma unroll
    for (int i = 0; i < 8; i++) {
        int gi = row0 + ty * 8 + i;
        float4 w0, w1;
        w0.x = fabsf(si_[i] + sj_[0] - 2.f * acc[i][0]);
        w0.y = fabsf(si_[i] + sj_[1] - 2.f * acc[i][1]);
        w0.z = fabsf(si_[i] + sj_[2] - 2.f * acc[i][2]);
        w0.w = fabsf(si_[i] + sj_[3] - 2.f * acc[i][3]);
        w1.x = fabsf(si_[i] + sj_[4] - 2.f * acc[i][4]);
        w1.y = fabsf(si_[i] + sj_[5] - 2.f * acc[i][5]);
        w1.z = fabsf(si_[i] + sj_[6] - 2.f * acc[i][6]);
        w1.w = fabsf(si_[i] + sj_[7] - 2.f * acc[i][7]);
        *(float4*)&g_dist[(size_t)gi * NPTS + col0 + tx * 8] = w0;
        *(float4*)&g_dist[(size_t)gi * NPTS + col0 + tx * 8 + 4] = w1;
    }
#pragma unroll
    for (int j = 0; j < 8; j++) {
        int gj = col0 + tx * 8 + j;
        float4 w0, w1;
        w0.x = fabsf(si_[0] + sj_[j] - 2.f * acc[0][j]);
        w0.y = fabsf(si_[1] + sj_[j] - 2.f * acc[1][j]);
        w0.z = fabsf(si_[2] + sj_[j] - 2.f * acc[2][j]);
        w0.w = fabsf(si_[3] + sj_[j] - 2.f * acc[3][j]);
        w1.x = fabsf(si_[4] + sj_[j] - 2.f * acc[4][j]);
        w1.y = fabsf(si_[5] + sj_[j] - 2.f * acc[5][j]);
        w1.z = fabsf(si_[6] + sj_[j] - 2.f * acc[6][j]);
        w1.w = fabsf(si_[7] + sj_[j] - 2.f * acc[7][j]);
        *(float4*)&g_dist[(size_t)gj * NPTS + row0 + ty * 8] = w0;
        *(float4*)&g_dist[(size_t)gj * NPTS + row0 + ty * 8 + 4] = w1;
    }
}

// ---- 4-warps-per-row top-11: batched loads (MLP=8) + smem candidate merge ----
__device__ __forceinline__ bool pless(float av, int ai, float bv, int bi) {
    return av < bv || (av == bv && ai < bi);
}

__global__ __launch_bounds__(256) void k_topk4() {
    __shared__ float sv[2][4 * KP1];
    __shared__ int   si_[2][4 * KP1];
    int wid = threadIdx.x >> 5;        // 0..7
    int lane = threadIdx.x & 31;
    int rloc = wid >> 2;               // 0/1 : row within block
    int q = wid & 3;                   // quarter
    int row = blockIdx.x * 2 + rloc;
    const float4* drow = (const float4*)&g_dist[(size_t)row * NPTS];

    // batched loads: 8 independent float4s in flight per lane
    float4 buf[8];
#pragma unroll
    for (int s = 0; s < 8; s++) buf[s] = drow[q * 256 + s * 32 + lane];

    float lv[KP1]; int li[KP1];
#pragma unroll
    for (int p = 0; p < KP1; p++) { lv[p] = FLT_MAX; li[p] = 0x7fffffff; }
#pragma unroll
    for (int s = 0; s < 8; s++) {
        float vv[4] = {buf[s].x, buf[s].y, buf[s].z, buf[s].w};
        int jb = (q * 256 + s * 32 + lane) * 4;
#pragma unroll
        for (int c = 0; c < 4; c++) {
            float v = vv[c]; int j = jb + c;
            if (pless(v, j, lv[KP1 - 1], li[KP1 - 1])) {
                lv[KP1 - 1] = v; li[KP1 - 1] = j;
#pragma unroll
                for (int p = KP1 - 1; p > 0; p--) {
                    if (pless(lv[p], li[p], lv[p - 1], li[p - 1])) {
                        float tv_ = lv[p]; lv[p] = lv[p - 1]; lv[p - 1] = tv_;
                        int ti_ = li[p]; li[p] = li[p - 1]; li[p - 1] = ti_;
                    }
                }
            }
        }
    }
    // warp-local top-11 extraction into smem (sorted)
    for (int it = 0; it < KP1; ++it) {
        float v = lv[0]; int ix = li[0];
#pragma unroll
        for (int o = 16; o; o >>= 1) {
            float ov = __shfl_xor_sync(0xffffffffu, v, o);
            int oi = __shfl_xor_sync(0xffffffffu, ix, o);
            if (pless(ov, oi, v, ix)) { v = ov; ix = oi; }
        }
        if (li[0] == ix) {  // unique winner lane pops its head
#pragma unroll
            for (int p = 0; p < KP1 - 1; p++) { lv[p] = lv[p + 1]; li[p] = li[p + 1]; }
            lv[KP1 - 1] = FLT_MAX; li[KP1 - 1] = 0x7fffffff;
        }
        if (lane == 0) { sv[rloc][q * KP1 + it] = v; si_[rloc][q * KP1 + it] = ix; }
    }
    __syncthreads();
    // merge 44 candidates (warp q==0 of each row); 2 candidates/lane (lane, lane+22)
    if (q == 0) {
        float c0 = (lane < 22) ? sv[rloc][lane] : FLT_MAX;
        int   i0 = (lane < 22) ? si_[rloc][lane] : 0x7fffffff;
        float c1 = (lane < 22) ? sv[rloc][lane + 22] : FLT_MAX;
        int   i1 = (lane < 22) ? si_[rloc][lane + 22] : 0x7fffffff;
        for (int it = 0; it < KP1; ++it) {
            float v; int ix;
            if (pless(c0, i0, c1, i1)) { v = c0; ix = i0; } else { v = c1; ix = i1; }
#pragma unroll
            for (int o = 16; o; o >>= 1) {
                float ov = __shfl_xor_sync(0xffffffffu, v, o);
                int oi = __shfl_xor_sync(0xffffffffu, ix, o);
                if (pless(ov, oi, v, ix)) { v = ov; ix = oi; }
            }
            if (i0 == ix) { c0 = FLT_MAX; i0 = 0x7fffffff; }
            else if (i1 == ix) { c1 = FLT_MAX; i1 = 0x7fffffff; }
            if (lane == 0) {
                g_idx[row * KP1 + it] = ix;
                atomicAdd(&g_deg[ix], 1);
            }
        }
    }
}

// parallel scan of deg + dv + cursor + CSR fill, single block
__global__ void k_scanfill() {
    __shared__ int s[1024];
    int t = threadIdx.x;
    int base = t * 4;
    int v0 = g_deg[base], v1 = g_deg[base + 1], v2 = g_deg[base + 2], v3 = g_deg[base + 3];
    int sum = v0 + v1 + v2 + v3;
    s[t] = sum;
    __syncthreads();
    for (int off = 1; off < 1024; off <<= 1) {
        int x = (t >= off) ? s[t - off] : 0;
        __syncthreads();
        s[t] += x;
        __syncthreads();
    }
    int run = s[t] - sum;
    g_roff[base] = run; g_cursor[base] = run; g_dv[base] = rsqrtf((float)v0); run += v0;
    g_roff[base + 1] = run; g_cursor[base + 1] = run; g_dv[base + 1] = rsqrtf((float)v1); run += v1;
    g_roff[base + 2] = run; g_cursor[base + 2] = run; g_dv[base + 2] = rsqrtf((float)v2); run += v2;
    g_roff[base + 3] = run; g_cursor[base + 3] = run; g_dv[base + 3] = rsqrtf((float)v3); run += v3;
    if (t == 1023) g_roff[NPTS] = run;
    __syncthreads();
    for (int p = t; p < NPTS * KP1; p += 1024) {
        int i = g_idx[p];
        int pos = atomicAdd(&g_cursor[i], 1);
        g_redge[pos] = p / KP1;
    }
}

// dedup'd ascending neighbor lists into g_dist region
__global__ void k_nbr() {
    __shared__ unsigned bm[128];
    __shared__ int wsum[4];
    int i = blockIdx.x, t = threadIdx.x;
    bm[t] = 0u;
    __syncthreads();
    int beg = g_roff[i];
    int cnt = (g_roff[i + 1] - beg) * KP1;
    for (int p = t; p < cnt; p += 128) {
        int e = g_redge[beg + p / KP1];
        int m = g_idx[e * KP1 + p % KP1];
        atomicOr(&bm[m >> 5], 1u << (m & 31));
    }
    __syncthreads();
    if (t == 0) bm[i >> 5] &= ~(1u << (i & 31));
    __syncthreads();
    unsigned w = bm[t];
    int pc = __popc(w);
    int lane = t & 31, wid = t >> 5;
    int sc = pc;
    for (int o = 1; o < 32; o <<= 1) {
        int x = __shfl_up_sync(0xffffffffu, sc, o);
        if (lane >= o) sc += x;
    }
    if (lane == 31) wsum[wid] = sc;
    __syncthreads();
    int woff = 0;
    for (int q = 0; q < wid; q++) woff += wsum[q];
    int off = woff + sc - pc;
    int* nbr = (int*)g_dist + (size_t)i * NPTS;
    while (w) {
        int b = __ffs(w) - 1; w &= w - 1;
        nbr[off++] = t * 32 + b;
    }
    if (t == 127) g_ncnt[i] = woff + sc;
}

// ---- 128x64 GEMM, double buffered ----
__device__ __forceinline__ void gemm64_body(const float* __restrict__ A,
                                            const float* __restrict__ B, int ldb,
                                            float* __restrict__ C, int ldc,
                                            int K, int m0, int n0b) {
    __shared__ float As[2][16][128];
    __shared__ float Bs[2][16][64];
    int t = threadIdx.x;
    int ty = t >> 4, tx = t & 15;
    int ra = t >> 1, qa = (t & 1) * 8;
    int kb = t >> 4, cb = (t & 15) * 4;

    float4 pa0, pa1, pb;
    pa0 = *(const float4*)&A[(size_t)(m0 + ra) * K + qa];
    pa1 = *(const float4*)&A[(size_t)(m0 + ra) * K + qa + 4];
    pb = *(const float4*)&B[(size_t)kb * ldb + cb];
    As[0][qa + 0][ra] = pa0.x; As[0][qa + 1][ra] = pa0.y; As[0][qa + 2][ra] = pa0.z; As[0][qa + 3][ra] = pa0.w;
    As[0][qa + 4][ra] = pa1.x; As[0][qa + 5][ra] = pa1.y; As[0][qa + 6][ra] = pa1.z; As[0][qa + 7][ra] = pa1.w;
    *(float4*)&Bs[0][kb][cb] = pb;
    __syncthreads();

    float acc[8][4];
#pragma unroll
    for (int i = 0; i < 8; i++)
#pragma unroll
        for (int j = 0; j < 4; j++) acc[i][j] = 0.f;

    int nIt = K / 16;
    for (int it = 0; it < nIt; ++it) {
        int k0n = (it + 1) * 16;
        if (it + 1 < nIt) {
            pa0 = *(const float4*)&A[(size_t)(m0 + ra) * K + k0n + qa];
            pa1 = *(const float4*)&A[(size_t)(m0 + ra) * K + k0n + qa + 4];
            pb = *(const float4*)&B[(size_t)(k0n + kb) * ldb + cb];
        }
        int buf = it & 1;
#pragma unroll
        for (int kk = 0; kk < 16; ++kk) {
            float4 a0 = *(const float4*)&As[buf][kk][ty * 8];
            float4 a1 = *(const float4*)&As[buf][kk][ty * 8 + 4];
            float4 b0 = *(const float4*)&Bs[buf][kk][tx * 4];
            float ar[8] = {a0.x, a0.y, a0.z, a0.w, a1.x, a1.y, a1.z, a1.w};
            float br[4] = {b0.x, b0.y, b0.z, b0.w};
#pragma unroll
            for (int i = 0; i < 8; i++)
#pragma unroll
                for (int j = 0; j < 4; j++) acc[i][j] += ar[i] * br[j];
        }
        if (it + 1 < nIt) {
            int nb = buf ^ 1;
            As[nb][qa + 0][ra] = pa0.x; As[nb][qa + 1][ra] = pa0.y; As[nb][qa + 2][ra] = pa0.z; As[nb][qa + 3][ra] = pa0.w;
            As[nb][qa + 4][ra] = pa1.x; As[nb][qa + 5][ra] = pa1.y; As[nb][qa + 6][ra] = pa1.z; As[nb][qa + 7][ra] = pa1.w;
            *(float4*)&Bs[nb][kb][cb] = pb;
        }
        __syncthreads();
    }
#pragma unroll
    for (int i = 0; i < 8; i++) {
        float4 w0 = {acc[i][0], acc[i][1], acc[i][2], acc[i][3]};
        *(float4*)&C[(size_t)(m0 + ty * 8 + i) * ldc + n0b + tx * 4] = w0;
    }
}

__global__ __launch_bounds__(256) void k_gemm64(const float* __restrict__ A,
                                                const float* __restrict__ B,
                                                float* __restrict__ C, int K, int Np) {
    gemm64_body(A, B + blockIdx.x * 64, Np, C, Np, K, blockIdx.y * 128, blockIdx.x * 64);
}

__global__ __launch_bounds__(256) void k_gemm64h2(const float* __restrict__ A1,
                                                  const float* __restrict__ A2,
                                                  const float* __restrict__ Wh,
                                                  float* __restrict__ C1,
                                                  float* __restrict__ C2) {
    int half = blockIdx.y >> 5;
    int m0 = (blockIdx.y & 31) * 128;
    int h = blockIdx.x;
    gemm64_body(half ? A2 : A1, Wh + (size_t)h * DHID * 64, 64,
                half ? C2 : C1, DHID, DHID, m0, h * 64);
}

__global__ __launch_bounds__(256) void k_gemm64d(const float* __restrict__ A1,
                                                 const float* __restrict__ A2,
                                                 const float* __restrict__ B,
                                                 float* __restrict__ C1,
                                                 float* __restrict__ C2) {
    int half = blockIdx.y >> 5;
    int m0 = (blockIdx.y & 31) * 128;
    gemm64_body(half ? A2 : A1, B + blockIdx.x * 64, DHID,
                half ? C2 : C1, DHID, DHID, m0, blockIdx.x * 64);
}

// ---- hypergraph gathers (vectorized, norm fused into edges) ----
__global__ void k_gather_edges() {
    int e = blockIdx.x * 4 + (threadIdx.x >> 5);
    int lane = threadIdx.x & 31;
    float4 a0 = {0, 0, 0, 0}, a1 = {0, 0, 0, 0};
    for (int k = 0; k < KP1; k++) {
        int i = g_idx[e * KP1 + k];
        float w = g_dv[i];
        const float4* r = (const float4*)&g_XT[(size_t)i * DHID];
        float4 x0 = r[lane], x1 = r[lane + 32];
        a0.x += w * x0.x; a0.y += w * x0.y; a0.z += w * x0.z; a0.w += w * x0.w;
        a1.x += w * x1.x; a1.y += w * x1.y; a1.z += w * x1.z; a1.w += w * x1.w;
    }
    a0.x *= DE_C; a0.y *= DE_C; a0.z *= DE_C; a0.w *= DE_C;
    a1.x *= DE_C; a1.y *= DE_C; a1.z *= DE_C; a1.w *= DE_C;
    float4* o = (float4*)&g_Xe[(size_t)e * DHID];
    o[lane] = a0; o[lane + 32] = a1;
    float nq = a0.x * a0.x + a0.y * a0.y + a0.z * a0.z + a0.w * a0.w
             + a1.x * a1.x + a1.y * a1.y + a1.z * a1.z + a1.w * a1.w;
    for (int of = 16; of; of >>= 1) nq += __shfl_xor_sync(0xffffffffu, nq, of);
    if (lane == 0) g_nrm[e] = sqrtf(nq);
}

__global__ void k_gather_nodes() {
    int i = blockIdx.x * 4 + (threadIdx.x >> 5);
    int lane = threadIdx.x & 31;
    int beg = g_roff[i], end = g_roff[i + 1];
    float4 a0 = {0, 0, 0, 0}, a1 = {0, 0, 0, 0};
    for (int k = beg; k < end; k++) {
        const float4* r = (const float4*)&g_Xe[(size_t)g_redge[k] * DHID];
        float4 x0 = r[lane], x1 = r[lane + 32];
        a0.x += x0.x; a0.y += x0.y; a0.z += x0.z; a0.w += x0.w;
        a1.x += x1.x; a1.y += x1.y; a1.z += x1.z; a1.w += x1.w;
    }
    float s = g_dv[i] * DE_C;
    a0.x *= s; a0.y *= s; a0.z *= s; a0.w *= s;
    a1.x *= s; a1.y *= s; a1.z *= s; a1.w *= s;
    float4* o = (float4*)&g_E[(size_t)i * DHID];
    o[lane] = a0; o[lane + 32] = a1;
}

__global__ void k_rownorm(const float* __restrict__ Xf) {
    int row = blockIdx.x * 4 + (threadIdx.x >> 5);
    int lane = threadIdx.x & 31;
    const float4* r = (const float4*)&Xf[(size_t)row * DHID];
    float4 x0 = r[lane], x1 = r[lane + 32];
    float a = x0.x * x0.x + x0.y * x0.y + x0.z * x0.z + x0.w * x0.w
            + x1.x * x1.x + x1.y * x1.y + x1.z * x1.z + x1.w * x1.w;
    for (int o = 16; o; o >>= 1) a += __shfl_xor_sync(0xffffffffu, a, o);
    if (lane == 0) g_nrm[row] = sqrtf(a);
}

// density: 2-way unrolled neighbor dot products
__global__ void k_density(const float* __restrict__ Xf) {
    __shared__ float xs[DHID];
    __shared__ float ps[8];
    int i = blockIdx.x, t = threadIdx.x;
    xs[t] = Xf[(size_t)i * DHID + t];
    __syncthreads();
    int lane = t & 31, wp = t >> 5;
    const float4* xs4 = (const float4*)xs;
    float4 x0 = xs4[lane], x1 = xs4[lane + 32];
    const int* nbr = (const int*)g_dist + (size_t)i * NPTS;
    int n = g_ncnt[i];
    float ni = g_nrm[i], part = 0.f;
    for (int e0 = wp; e0 < n; e0 += 16) {
        int e1 = e0 + 8;
        bool have2 = (e1 < n);
        int j1 = nbr[e0];
        int j2 = have2 ? nbr[e1] : j1;
        const float4* r1 = (const float4*)&Xf[(size_t)j1 * DHID];
        const float4* r2 = (const float4*)&Xf[(size_t)j2 * DHID];
        float4 a0 = r1[lane], a1 = r1[lane + 32];
        float4 b0 = r2[lane], b1 = r2[lane + 32];
        float d1 = x0.x * a0.x + x0.y * a0.y + x0.z * a0.z + x0.w * a0.w
                 + x1.x * a1.x + x1.y * a1.y + x1.z * a1.z + x1.w * a1.w;
        float d2 = x0.x * b0.x + x0.y * b0.y + x0.z * b0.z + x0.w * b0.w
                 + x1.x * b1.x + x1.y * b1.y + x1.z * b1.z + x1.w * b1.w;
#pragma unroll
        for (int o = 16; o; o >>= 1) {
            d1 += __shfl_xor_sync(0xffffffffu, d1, o);
            d2 += __shfl_xor_sync(0xffffffffu, d2, o);
        }
        if (lane == 0) {
            float c1 = d1 / (ni * g_nrm[j1]);
            if (c1 > SIGMA_C) part += c1;
            if (have2) {
                float c2 = d2 / (ni * g_nrm[j2]);
                if (c2 > SIGMA_C) part += c2;
            }
        }
    }
    if (lane == 0) ps[wp] = part;
    __syncthreads();
    if (t == 0) {
        float a = 0.f;
        for (int q = 0; q < 8; q++) a += ps[q];
        g_rho[i] = a;
    }
}

// rhoe + fused maxima of rho and rhoe
__global__ void k_rhoe(int rslot, int reslot) {
    __shared__ float sm1[8], sm2[8];
    int e = blockIdx.x * 256 + threadIdx.x;
    float r = 0.f;
    for (int k = 0; k < KP1; k++) r += g_rho[g_idx[e * KP1 + k]];
    g_rhoe[e] = r;
    float rr = g_rho[e];
    for (int o = 16; o; o >>= 1) {
        r = fmaxf(r, __shfl_xor_sync(0xffffffffu, r, o));
        rr = fmaxf(rr, __shfl_xor_sync(0xffffffffu, rr, o));
    }
    int t = threadIdx.x;
    if ((t & 31) == 0) { sm1[t >> 5] = rr; sm2[t >> 5] = r; }
    __syncthreads();
    if (t == 0) {
        float m1 = sm1[0], m2 = sm2[0];
        for (int q = 1; q < 8; q++) { m1 = fmaxf(m1, sm1[q]); m2 = fmaxf(m2, sm2[q]); }
        atomicMax(&g_smax[rslot], encf(m1));
        atomicMax(&g_smax[reslot], encf(m2));
    }
}

// all-heads s/t matvec (D=64, float2) + fused per-slot max
__global__ void k_svtv4(const float* __restrict__ Ms, const float* __restrict__ Mt,
                        const float* __restrict__ av, int sb) {
    __shared__ float sm[8];
    int w = (blockIdx.x * 256 + threadIdx.x) >> 5;
    int lane = threadIdx.x & 31;
    int row = w & (NPTS - 1);
    int g = w >> 12;
    int h = g & 3, which = g >> 2;
    const float* M = which ? Mt : Ms;
    const float2* a2 = (const float2*)(av + (size_t)h * 2 * DHEAD + which * DHEAD);
    const float2* r2 = (const float2*)(M + (size_t)row * DHID + h * DHEAD);
    float2 rv = r2[lane], av2 = a2[lane];
    float p = rv.x * av2.x + rv.y * av2.y;
    for (int o = 16; o; o >>= 1) p += __shfl_xor_sync(0xffffffffu, p, o);
    if (lane == 0) {
        (which ? g_tvh : g_svh)[h * NPTS + row] = p;
        sm[(threadIdx.x >> 5)] = p;
    }
    __syncthreads();
    if (threadIdx.x == 0) {
        float m = sm[0];
        for (int q = 1; q < 8; q++) m = fmaxf(m, sm[q]);
        atomicMax(&g_smax[sb + which * 4 + h], encf(m));
    }
}

// final s/t matvec D=256 + fused max
__global__ void k_svtv1(const float* __restrict__ Ms, const float* __restrict__ as,
                        const float* __restrict__ Mt, const float* __restrict__ at, int sb) {
    __shared__ float sm[8];
    int w = (blockIdx.x * 256 + threadIdx.x) >> 5;
    int lane = threadIdx.x & 31;
    int row = w & (NPTS - 1);
    int which = w >> 12;
    const float* M = which ? Mt : Ms;
    const float* a = which ? at : as;
    const float4* r = (const float4*)(M + (size_t)row * DHID);
    const float4* a4 = (const float4*)a;
    float4 r0 = r[lane], r1 = r[lane + 32];
    float4 b0 = a4[lane], b1 = a4[lane + 32];
    float p = r0.x * b0.x + r0.y * b0.y + r0.z * b0.z + r0.w * b0.w
            + r1.x * b1.x + r1.y * b1.y + r1.z * b1.z + r1.w * b1.w;
    for (int o = 16; o; o >>= 1) p += __shfl_xor_sync(0xffffffffu, p, o);
    if (lane == 0) {
        (which ? g_tvh : g_svh)[row] = p;
        sm[(threadIdx.x >> 5)] = p;
    }
    __syncthreads();
    if (threadIdx.x == 0) {
        float m = sm[0];
        for (int q = 1; q < 8; q++) m = fmaxf(m, sm[q]);
        atomicMax(&g_smax[sb + which], encf(m));
    }
}

__device__ __forceinline__ float lrelu(float x) { return x > 0.f ? x : 0.2f * x; }
__device__ __forceinline__ float elu1(float x) { return x > 0.f ? x : expm1f(x); }

// attention: grid (1024, nheads); float2-vectorized value gathers
template <int D>
__global__ void k_att4(const float* __restrict__ rho, int rslot,
                       const float* __restrict__ valb, int ldv,
                       float* __restrict__ outb, int ldo, int hstride, int sb, int nh) {
    int h = blockIdx.y;
    int row = blockIdx.x * 4 + (threadIdx.x >> 5);
    int lane = threadIdx.x & 31;
    const float* sA = g_svh + h * NPTS;
    const float* tA = g_tvh + h * NPTS;
    float smx = decf(g_smax[sb + h]);
    float tmx = decf(g_smax[sb + nh + h]);
    float ax_max = lrelu(smx + tmx);
    float rt = rho[row] / decf(g_smax[rslot]) * ax_max;
    float si = sA[row];
    int beg = g_roff[row], end = g_roff[row + 1];
    int deg = end - beg;
    const float* val = valb + h * hstride;
    float* out = outb + h * hstride;
    const int C2 = D / 64;
    float2 acc[C2];
#pragma unroll
    for (int j = 0; j < C2; j++) acc[j] = make_float2(0.f, 0.f);
    float iz;
    if (deg <= 32) {
        int mye = (lane < deg) ? g_redge[beg + lane] : 0;
        float st = (lane < deg) ? (lrelu(si + tA[mye]) + rt) : -FLT_MAX;
        float m = st;
        for (int o = 16; o; o >>= 1) m = fmaxf(m, __shfl_xor_sync(0xffffffffu, m, o));
        float myw = (lane < deg) ? expf(st - m) : 0.f;
        float Z = myw;
        for (int o = 16; o; o >>= 1) Z += __shfl_xor_sync(0xffffffffu, Z, o);
        for (int k = 0; k < deg; k++) {
            int e = __shfl_sync(0xffffffffu, mye, k);
            float wt = __shfl_sync(0xffffffffu, myw, k);
            const float2* v2 = (const float2*)&val[(size_t)e * ldv];
#pragma unroll
            for (int j = 0; j < C2; j++) {
                float2 x = v2[lane + j * 32];
                acc[j].x += wt * x.x; acc[j].y += wt * x.y;
            }
        }
        iz = 1.f / Z;
    } else {
        float m = -FLT_MAX;
        for (int k = beg + lane; k < end; k += 32)
            m = fmaxf(m, lrelu(si + tA[g_redge[k]]) + rt);
        for (int o = 16; o; o >>= 1) m = fmaxf(m, __shfl_xor_sync(0xffffffffu, m, o));
        float Z = 0.f;
        for (int k = beg + lane; k < end; k += 32)
            Z += expf(lrelu(si + tA[g_redge[k]]) + rt - m);
        for (int o = 16; o; o >>= 1) Z += __shfl_xor_sync(0xffffffffu, Z, o);
        for (int k = beg; k < end; k++) {
            int e = g_redge[k];
            float wt = expf(lrelu(si + tA[e]) + rt - m);
            const float2* v2 = (const float2*)&val[(size_t)e * ldv];
#pragma unroll
            for (int j = 0; j < C2; j++) {
                float2 x = v2[lane + j * 32];
                acc[j].x += wt * x.x; acc[j].y += wt * x.y;
            }
        }
        iz = 1.f / Z;
    }
    float2* o2 = (float2*)&out[(size_t)row * ldo];
#pragma unroll
    for (int j = 0; j < C2; j++) {
        float2 r;
        r.x = elu1(acc[j].x * iz);
        r.y = elu1(acc[j].y * iz);
        o2[lane + j * 32] = r;
    }
}

// ---------------- host orchestration ----------------
extern "C" void kernel_launch(void* const* d_in, const int* in_sizes, int n_in,
                              void* d_out, int out_size) {
    const float* X     = (const float*)d_in[0];
    const float* theta = (const float*)d_in[1];
    const float* Wh    = (const float*)d_in[2];
    const float* axh   = (const float*)d_in[3];
    const float* aeh   = (const float*)d_in[4];
    const float* W2    = (const float*)d_in[5];
    const float* ax2   = (const float*)d_in[6];
    const float* ae2   = (const float*)d_in[7];
    float* out = (float*)d_out;
    (void)in_sizes; (void)n_in; (void)out_size;

    void* vp;
    cudaGetSymbolAddress(&vp, g_XT);   float* XT   = (float*)vp;
    cudaGetSymbolAddress(&vp, g_Xe);   float* Xe   = (float*)vp;
    cudaGetSymbolAddress(&vp, g_E);    float* E    = (float*)vp;
    cudaGetSymbolAddress(&vp, g_rho);  float* rho  = (float*)vp;
    cudaGetSymbolAddress(&vp, g_rhoe); float* rhoe = (float*)vp;
    cudaGetSymbolAddress(&vp, g_P);    float* P    = (float*)vp;
    cudaGetSymbolAddress(&vp, g_Q);    float* Q    = (float*)vp;
    cudaGetSymbolAddress(&vp, g_Enew); float* Enew = (float*)vp;
    cudaGetSymbolAddress(&vp, g_Xcat); float* Xcat = (float*)vp;

    // profiled slot #4 = k_gemm64 (X@theta)
    k_rowsq<<<NPTS / 4, 128>>>(X);          // also zeroes deg/smax
    k_aat_dist_sym<<<528, 256>>>(X);
    k_topk4<<<NPTS / 2, 256>>>();
    k_gemm64<<<dim3(4, 32), 256>>>(X, theta, XT, DIN, DHID);   // profiled

    k_scanfill<<<1, 1024>>>();
    k_gather_edges<<<NPTS / 4, 128>>>();
    k_gather_nodes<<<NPTS / 4, 128>>>();
    k_nbr<<<NPTS, 128>>>();

    // densities (stage 1)
    k_density<<<NPTS, 256>>>(Xe);
    k_rhoe<<<16, 256>>>(20, 21);

    // all-head projections
    k_gemm64h2<<<dim3(4, 64), 256>>>(Xe, E, Wh, P, Q);

    // attention pass 1
    k_svtv4<<<4096, 256>>>(P, Q, axh, 0);
    k_att4<DHEAD><<<dim3(NPTS / 4, MH), 128>>>(rho, 20, P, DHID, Enew, DHID, DHEAD, 0, 4);

    // attention pass 2
    k_svtv4<<<4096, 256>>>(Q, P, aeh, 8);
    k_att4<DHEAD><<<dim3(NPTS / 4, MH), 128>>>(rhoe, 21, Enew, DHID, Xcat, DHID, DHEAD, 8, 4);

    // final DA-HGAN layer
    k_rownorm<<<NPTS / 4, 128>>>(Xcat);
    k_density<<<NPTS, 256>>>(Xcat);
    k_rhoe<<<16, 256>>>(22, 23);

    k_gemm64d<<<dim3(4, 64), 256>>>(Xcat, E, W2, P, Q);

    k_svtv1<<<1024, 256>>>(P, ax2, Q, ax2 + DHID, 16);
    k_att4<DHID><<<dim3(NPTS / 4, 1), 128>>>(rho, 22, P, DHID, Enew, DHID, 0, 16, 1);

    k_svtv1<<<1024, 256>>>(Q, ae2, P, ae2 + DHID, 18);
    k_att4<DHID><<<dim3(NPTS / 4, 1), 128>>>(rhoe, 23, Enew, DHID, out, DHID, 0, 18, 1);
}

// round 12
// speedup vs baseline: 1.0294x; 1.0276x over previous
#include <cuda_runtime.h>
#include <math.h>
#include <float.h>

// ---------------- problem constants ----------------
#define NPTS  4096
#define DIN   784
#define DHID  256
#define MH    4
#define DHEAD 64
#define KP1   11
#define SIGMA_C 0.1f
#define DE_C  0.30151134457776363f   // 1/sqrt(11)

// ---------------- device scratch ----------------
__device__ float g_dist[(size_t)NPTS * NPTS];  // 64MB; after topk reused as int nbr[4096][4096]
__device__ float g_sq[NPTS];
__device__ int   g_idx[NPTS * KP1];
__device__ int   g_deg[NPTS];
__device__ float g_dv[NPTS];
__device__ int   g_roff[NPTS + 1];
__device__ int   g_cursor[NPTS];
__device__ int   g_redge[NPTS * KP1];
__device__ int   g_ncnt[NPTS];
__device__ float g_XT[NPTS * DHID];
__device__ float g_Xe[NPTS * DHID];
__device__ float g_E[NPTS * DHID];
__device__ float g_nrm[NPTS];
__device__ float g_rho[NPTS];
__device__ float g_rhoe[NPTS];
__device__ float g_P[NPTS * DHID];
__device__ float g_Q[NPTS * DHID];
__device__ float g_svh[MH * NPTS];
__device__ float g_tvh[MH * NPTS];
__device__ float g_svh2[MH * NPTS];   // double buffer for overlapped pass2
__device__ float g_tvh2[MH * NPTS];
__device__ float g_Enew[NPTS * DHID];
__device__ float g_Xcat[NPTS * DHID];
__device__ unsigned g_smax[32];   // encoded float maxima

__device__ __forceinline__ unsigned encf(float f) {
    unsigned u = __float_as_uint(f);
    return (u & 0x80000000u) ? ~u : (u | 0x80000000u);
}
__device__ __forceinline__ float decf(unsigned u) {
    return __uint_as_float((u & 0x80000000u) ? (u & 0x7fffffffu) : ~u);
}

// ---------------- rowsq + fused zero-init ----------------
__global__ void k_rowsq(const float* __restrict__ X) {
    int gid = blockIdx.x * 128 + threadIdx.x;
    if (gid < NPTS) g_deg[gid] = 0;
    if (gid < 32) g_smax[gid] = 0u;
    int row = blockIdx.x * 4 + (threadIdx.x >> 5);
    int lane = threadIdx.x & 31;
    const float4* r = (const float4*)&X[(size_t)row * DIN];
    float a = 0.f;
    for (int c = lane; c < DIN / 4; c += 32) {
        float4 v = r[c];
        a += v.x * v.x + v.y * v.y + v.z * v.z + v.w * v.w;
    }
    for (int o = 16; o; o >>= 1) a += __shfl_xor_sync(0xffffffffu, a, o);
    if (lane == 0) g_sq[row] = a;
}

// ---- symmetric dist GEMM: upper-tri 128x128 blocks, mirrored f4 writes ----
__global__ __launch_bounds__(256) void k_aat_dist_sym(const float* __restrict__ A) {
    __shared__ float As[2][16][128];
    __shared__ float Bs[2][16][128];
    int b = blockIdx.x, by = 0;
    while (b >= 32 - by) { b -= 32 - by; ++by; }
    int bx = by + b;
    int row0 = by * 128, col0 = bx * 128;
    int t = threadIdx.x;
    int ty = t >> 4, tx = t & 15;
    int ra = t >> 2, qa = (t & 3) * 4;

    float4 pa0, pa1, pb0, pb1;
    pa0 = *(const float4*)&A[(size_t)(row0 + ra) * DIN + qa];
    pa1 = *(const float4*)&A[(size_t)(row0 + ra + 64) * DIN + qa];
    pb0 = *(const float4*)&A[(size_t)(col0 + ra) * DIN + qa];
    pb1 = *(const float4*)&A[(size_t)(col0 + ra + 64) * DIN + qa];
    As[0][qa + 0][ra] = pa0.x; As[0][qa + 1][ra] = pa0.y; As[0][qa + 2][ra] = pa0.z; As[0][qa + 3][ra] = pa0.w;
    As[0][qa + 0][ra + 64] = pa1.x; As[0][qa + 1][ra + 64] = pa1.y; As[0][qa + 2][ra + 64] = pa1.z; As[0][qa + 3][ra + 64] = pa1.w;
    Bs[0][qa + 0][ra] = pb0.x; Bs[0][qa + 1][ra] = pb0.y; Bs[0][qa + 2][ra] = pb0.z; Bs[0][qa + 3][ra] = pb0.w;
    Bs[0][qa + 0][ra + 64] = pb1.x; Bs[0][qa + 1][ra + 64] = pb1.y; Bs[0][qa + 2][ra + 64] = pb1.z; Bs[0][qa + 3][ra + 64] = pb1.w;
    __syncthreads();

    float acc[8][8];
#pragma unroll
    for (int i = 0; i < 8; i++)
#pragma unroll
        for (int j = 0; j < 8; j++) acc[i][j] = 0.f;

    const int nIt = DIN / 16;
    for (int it = 0; it < nIt; ++it) {
        int k0n = (it + 1) * 16;
        if (it + 1 < nIt) {
            pa0 = *(const float4*)&A[(size_t)(row0 + ra) * DIN + k0n + qa];
            pa1 = *(const float4*)&A[(size_t)(row0 + ra + 64) * DIN + k0n + qa];
            pb0 = *(const float4*)&A[(size_t)(col0 + ra) * DIN + k0n + qa];
            pb1 = *(const float4*)&A[(size_t)(col0 + ra + 64) * DIN + k0n + qa];
        }
        int buf = it & 1;
#pragma unroll
        for (int kk = 0; kk < 16; ++kk) {
            float4 a0 = *(const float4*)&As[buf][kk][ty * 8];
            float4 a1 = *(const float4*)&As[buf][kk][ty * 8 + 4];
            float4 b0 = *(const float4*)&Bs[buf][kk][tx * 8];
            float4 b1 = *(const float4*)&Bs[buf][kk][tx * 8 + 4];
            float ar[8] = {a0.x, a0.y, a0.z, a0.w, a1.x, a1.y, a1.z, a1.w};
            float br[8] = {b0.x, b0.y, b0.z, b0.w, b1.x, b1.y, b1.z, b1.w};
#pragma unroll
            for (int i = 0; i < 8; i++)
#pragma unroll
                for (int j = 0; j < 8; j++) acc[i][j] += ar[i] * br[j];
        }
        if (it + 1 < nIt) {
            int nb = buf ^ 1;
            As[nb][qa + 0][ra] = pa0.x; As[nb][qa + 1][ra] = pa0.y; As[nb][qa + 2][ra] = pa0.z; As[nb][qa + 3][ra] = pa0.w;
            As[nb][qa + 0][ra + 64] = pa1.x; As[nb][qa + 1][ra + 64] = pa1.y; As[nb][qa + 2][ra + 64] = pa1.z; As[nb][qa + 3][ra + 64] = pa1.w;
            Bs[nb][qa + 0][ra] = pb0.x; Bs[nb][qa + 1][ra] = pb0.y; Bs[nb][qa + 2][ra] = pb0.z; Bs[nb][qa + 3][ra] = pb0.w;
            Bs[nb][qa + 0][ra + 64] = pb1.x; Bs[nb][qa + 1][ra + 64] = pb1.y; Bs[nb][qa + 2][ra + 64] = pb1.z; Bs[nb][qa + 3][ra + 64] = pb1.w;
        }
        __syncthreads();
    }

    float si_[8], sj_[8];
#pragma unroll
    for (int i = 0; i < 8; i++) si_[i] = g_sq[row0 + ty * 8 + i];
#pragma unroll
    for (int j = 0; j < 8; j++) sj_[j] = g_sq[col0 + tx * 8 + j];

#pragma unroll
    for (int i = 0; i < 8; i++) {
        int gi = row0 + ty * 8 + i;
        float4 w0, w1;
        w0.x = fabsf(si_[i] + sj_[0] - 2.f * acc[i][0]);
        w0.y = fabsf(si_[i] + sj_[1] - 2.f * acc[i][1]);
        w0.z = fabsf(si_[i] + sj_[2] - 2.f * acc[i][2]);
        w0.w = fabsf(si_[i] + sj_[3] - 2.f * acc[i][3]);
        w1.x = fabsf(si_[i] + sj_[4] - 2.f * acc[i][4]);
        w1.y = fabsf(si_[i] + sj_[5] - 2.f * acc[i][5]);
        w1.z = fabsf(si_[i] + sj_[6] - 2.f * acc[i][6]);
        w1.w = fabsf(si_[i] + sj_[7] - 2.f * acc[i][7]);
        *(float4*)&g_dist[(size_t)gi * NPTS + col0 + tx * 8] = w0;
        *(float4*)&g_dist[(size_t)gi * NPTS + col0 + tx * 8 + 4] = w1;
    }
#pragma unroll
    for (int j = 0; j < 8; j++) {
        int gj = col0 + tx * 8 + j;
        float4 w0, w1;
        w0.x = fabsf(si_[0] + sj_[j] - 2.f * acc[0][j]);
        w0.y = fabsf(si_[1] + sj_[j] - 2.f * acc[1][j]);
        w0.z = fabsf(si_[2] + sj_[j] - 2.f * acc[2][j]);
        w0.w = fabsf(si_[3] + sj_[j] - 2.f * acc[3][j]);
        w1.x = fabsf(si_[4] + sj_[j] - 2.f * acc[4][j]);
        w1.y = fabsf(si_[5] + sj_[j] - 2.f * acc[5][j]);
        w1.z = fabsf(si_[6] + sj_[j] - 2.f * acc[6][j]);
        w1.w = fabsf(si_[7] + sj_[j] - 2.f * acc[7][j]);
        *(float4*)&g_dist[(size_t)gj * NPTS + row0 + ty * 8] = w0;
        *(float4*)&g_dist[(size_t)gj * NPTS + row0 + ty * 8 + 4] = w1;
    }
}

// ---- warp-per-row top-11 (R7 version, known-good) ----
__device__ __forceinline__ bool pless(float av, int ai, float bv, int bi) {
    return av < bv || (av == bv && ai < bi);
}

__global__ __launch_bounds__(256) void k_topk_warp() {
    int row = blockIdx.x * 8 + (threadIdx.x >> 5);
    int lane = threadIdx.x & 31;
    const float4* drow = (const float4*)&g_dist[(size_t)row * NPTS];
    float lv[KP1]; int li[KP1];
#pragma unroll
    for (int q = 0; q < KP1; q++) { lv[q] = FLT_MAX; li[q] = 0x7fffffff; }
#pragma unroll 2
    for (int s = 0; s < 32; s++) {
        int p4 = s * 32 + lane;
        float4 v4 = drow[p4];
        float vv[4] = {v4.x, v4.y, v4.z, v4.w};
        int jb = p4 * 4;
#pragma unroll
        for (int c = 0; c < 4; c++) {
            float v = vv[c]; int j = jb + c;
            if (pless(v, j, lv[KP1 - 1], li[KP1 - 1])) {
                lv[KP1 - 1] = v; li[KP1 - 1] = j;
#pragma unroll
                for (int q = KP1 - 1; q > 0; q--) {
                    if (pless(lv[q], li[q], lv[q - 1], li[q - 1])) {
                        float tv_ = lv[q]; lv[q] = lv[q - 1]; lv[q - 1] = tv_;
                        int ti_ = li[q]; li[q] = li[q - 1]; li[q - 1] = ti_;
                    }
                }
            }
        }
    }
    for (int it = 0; it < KP1; ++it) {
        float v = lv[0]; int ix = li[0];
#pragma unroll
        for (int o = 16; o; o >>= 1) {
            float ov = __shfl_xor_sync(0xffffffffu, v, o);
            int oi = __shfl_xor_sync(0xffffffffu, ix, o);
            if (pless(ov, oi, v, ix)) { v = ov; ix = oi; }
        }
        if (li[0] == ix) {
#pragma unroll
            for (int q = 0; q < KP1 - 1; q++) { lv[q] = lv[q + 1]; li[q] = li[q + 1]; }
            lv[KP1 - 1] = FLT_MAX; li[KP1 - 1] = 0x7fffffff;
        }
        if (lane == 0) {
            g_idx[row * KP1 + it] = ix;
            atomicAdd(&g_deg[ix], 1);
        }
    }
}

// parallel scan of deg + dv + cursor + CSR fill, single block
__global__ void k_scanfill() {
    __shared__ int s[1024];
    int t = threadIdx.x;
    int base = t * 4;
    int v0 = g_deg[base], v1 = g_deg[base + 1], v2 = g_deg[base + 2], v3 = g_deg[base + 3];
    int sum = v0 + v1 + v2 + v3;
    s[t] = sum;
    __syncthreads();
    for (int off = 1; off < 1024; off <<= 1) {
        int x = (t >= off) ? s[t - off] : 0;
        __syncthreads();
        s[t] += x;
        __syncthreads();
    }
    int run = s[t] - sum;
    g_roff[base] = run; g_cursor[base] = run; g_dv[base] = rsqrtf((float)v0); run += v0;
    g_roff[base + 1] = run; g_cursor[base + 1] = run; g_dv[base + 1] = rsqrtf((float)v1); run += v1;
    g_roff[base + 2] = run; g_cursor[base + 2] = run; g_dv[base + 2] = rsqrtf((float)v2); run += v2;
    g_roff[base + 3] = run; g_cursor[base + 3] = run; g_dv[base + 3] = rsqrtf((float)v3); run += v3;
    if (t == 1023) g_roff[NPTS] = run;
    __syncthreads();
    for (int p = t; p < NPTS * KP1; p += 1024) {
        int i = g_idx[p];
        int pos = atomicAdd(&g_cursor[i], 1);
        g_redge[pos] = p / KP1;
    }
}

// dedup'd ascending neighbor lists into g_dist region
__global__ void k_nbr() {
    __shared__ unsigned bm[128];
    __shared__ int wsum[4];
    int i = blockIdx.x, t = threadIdx.x;
    bm[t] = 0u;
    __syncthreads();
    int beg = g_roff[i];
    int cnt = (g_roff[i + 1] - beg) * KP1;
    for (int p = t; p < cnt; p += 128) {
        int e = g_redge[beg + p / KP1];
        int m = g_idx[e * KP1 + p % KP1];
        atomicOr(&bm[m >> 5], 1u << (m & 31));
    }
    __syncthreads();
    if (t == 0) bm[i >> 5] &= ~(1u << (i & 31));
    __syncthreads();
    unsigned w = bm[t];
    int pc = __popc(w);
    int lane = t & 31, wid = t >> 5;
    int sc = pc;
    for (int o = 1; o < 32; o <<= 1) {
        int x = __shfl_up_sync(0xffffffffu, sc, o);
        if (lane >= o) sc += x;
    }
    if (lane == 31) wsum[wid] = sc;
    __syncthreads();
    int woff = 0;
    for (int q = 0; q < wid; q++) woff += wsum[q];
    int off = woff + sc - pc;
    int* nbr = (int*)g_dist + (size_t)i * NPTS;
    while (w) {
        int b = __ffs(w) - 1; w &= w - 1;
        nbr[off++] = t * 32 + b;
    }
    if (t == 127) g_ncnt[i] = woff + sc;
}

// ---- 128x64 GEMM body (for the 256-col projections) ----
__device__ __forceinline__ void gemm64_body(const float* __restrict__ A,
                                            const float* __restrict__ B, int ldb,
                                            float* __restrict__ C, int ldc,
                                            int K, int m0, int n0b) {
    __shared__ float As[2][16][128];
    __shared__ float Bs[2][16][64];
    int t = threadIdx.x;
    int ty = t >> 4, tx = t & 15;
    int ra = t >> 1, qa = (t & 1) * 8;
    int kb = t >> 4, cb = (t & 15) * 4;

    float4 pa0, pa1, pb;
    pa0 = *(const float4*)&A[(size_t)(m0 + ra) * K + qa];
    pa1 = *(const float4*)&A[(size_t)(m0 + ra) * K + qa + 4];
    pb = *(const float4*)&B[(size_t)kb * ldb + cb];
    As[0][qa + 0][ra] = pa0.x; As[0][qa + 1][ra] = pa0.y; As[0][qa + 2][ra] = pa0.z; As[0][qa + 3][ra] = pa0.w;
    As[0][qa + 4][ra] = pa1.x; As[0][qa + 5][ra] = pa1.y; As[0][qa + 6][ra] = pa1.z; As[0][qa + 7][ra] = pa1.w;
    *(float4*)&Bs[0][kb][cb] = pb;
    __syncthreads();

    float acc[8][4];
#pragma unroll
    for (int i = 0; i < 8; i++)
#pragma unroll
        for (int j = 0; j < 4; j++) acc[i][j] = 0.f;

    int nIt = K / 16;
    for (int it = 0; it < nIt; ++it) {
        int k0n = (it + 1) * 16;
        if (it + 1 < nIt) {
            pa0 = *(const float4*)&A[(size_t)(m0 + ra) * K + k0n + qa];
            pa1 = *(const float4*)&A[(size_t)(m0 + ra) * K + k0n + qa + 4];
            pb = *(const float4*)&B[(size_t)(k0n + kb) * ldb + cb];
        }
        int buf = it & 1;
#pragma unroll
        for (int kk = 0; kk < 16; ++kk) {
            float4 a0 = *(const float4*)&As[buf][kk][ty * 8];
            float4 a1 = *(const float4*)&As[buf][kk][ty * 8 + 4];
            float4 b0 = *(const float4*)&Bs[buf][kk][tx * 4];
            float ar[8] = {a0.x, a0.y, a0.z, a0.w, a1.x, a1.y, a1.z, a1.w};
            float br[4] = {b0.x, b0.y, b0.z, b0.w};
#pragma unroll
            for (int i = 0; i < 8; i++)
#pragma unroll
                for (int j = 0; j < 4; j++) acc[i][j] += ar[i] * br[j];
        }
        if (it + 1 < nIt) {
            int nb = buf ^ 1;
            As[nb][qa + 0][ra] = pa0.x; As[nb][qa + 1][ra] = pa0.y; As[nb][qa + 2][ra] = pa0.z; As[nb][qa + 3][ra] = pa0.w;
            As[nb][qa + 4][ra] = pa1.x; As[nb][qa + 5][ra] = pa1.y; As[nb][qa + 6][ra] = pa1.z; As[nb][qa + 7][ra] = pa1.w;
            *(float4*)&Bs[nb][kb][cb] = pb;
        }
        __syncthreads();
    }
#pragma unroll
    for (int i = 0; i < 8; i++) {
        float4 w0 = {acc[i][0], acc[i][1], acc[i][2], acc[i][3]};
        *(float4*)&C[(size_t)(m0 + ty * 8 + i) * ldc + n0b + tx * 4] = w0;
    }
}

// ---- 64x64 GEMM (XT: more blocks, fewer regs) ----
__global__ __launch_bounds__(256) void k_gemm64x(const float* __restrict__ A,
                                                 const float* __restrict__ B,
                                                 float* __restrict__ C, int K, int Np) {
    __shared__ float As[2][16][64];
    __shared__ float Bs[2][16][64];
    int t = threadIdx.x;
    int m0 = blockIdx.y * 64, n0 = blockIdx.x * 64;
    int ty = t >> 4, tx = t & 15;
    int ra = t >> 2, qa = (t & 3) * 4;
    int kb = t >> 4, cb = (t & 15) * 4;

    float4 pa, pb;
    pa = *(const float4*)&A[(size_t)(m0 + ra) * K + qa];
    pb = *(const float4*)&B[(size_t)kb * Np + n0 + cb];
    As[0][qa + 0][ra] = pa.x; As[0][qa + 1][ra] = pa.y; As[0][qa + 2][ra] = pa.z; As[0][qa + 3][ra] = pa.w;
    *(float4*)&Bs[0][kb][cb] = pb;
    __syncthreads();

    float acc[4][4];
#pragma unroll
    for (int i = 0; i < 4; i++)
#pragma unroll
        for (int j = 0; j < 4; j++) acc[i][j] = 0.f;

    int nIt = K / 16;
    for (int it = 0; it < nIt; ++it) {
        int k0n = (it + 1) * 16;
        if (it + 1 < nIt) {
            pa = *(const float4*)&A[(size_t)(m0 + ra) * K + k0n + qa];
            pb = *(const float4*)&B[(size_t)(k0n + kb) * Np + n0 + cb];
        }
        int buf = it & 1;
#pragma unroll
        for (int kk = 0; kk < 16; ++kk) {
            float4 a0 = *(const float4*)&As[buf][kk][ty * 4];
            float4 b0 = *(const float4*)&Bs[buf][kk][tx * 4];
            float ar[4] = {a0.x, a0.y, a0.z, a0.w};
            float br[4] = {b0.x, b0.y, b0.z, b0.w};
#pragma unroll
            for (int i = 0; i < 4; i++)
#pragma unroll
                for (int j = 0; j < 4; j++) acc[i][j] += ar[i] * br[j];
        }
        if (it + 1 < nIt) {
            int nb = buf ^ 1;
            As[nb][qa + 0][ra] = pa.x; As[nb][qa + 1][ra] = pa.y; As[nb][qa + 2][ra] = pa.z; As[nb][qa + 3][ra] = pa.w;
            *(float4*)&Bs[nb][kb][cb] = pb;
        }
        __syncthreads();
    }
#pragma unroll
    for (int i = 0; i < 4; i++) {
        float4 w0 = {acc[i][0], acc[i][1], acc[i][2], acc[i][3]};
        *(float4*)&C[(size_t)(m0 + ty * 4 + i) * Np + n0 + tx * 4] = w0;
    }
}

__global__ __launch_bounds__(256) void k_gemm64h2(const float* __restrict__ A1,
                                                  const float* __restrict__ A2,
                                                  const float* __restrict__ Wh,
                                                  float* __restrict__ C1,
                                                  float* __restrict__ C2) {
    int half = blockIdx.y >> 5;
    int m0 = (blockIdx.y & 31) * 128;
    int h = blockIdx.x;
    gemm64_body(half ? A2 : A1, Wh + (size_t)h * DHID * 64, 64,
                half ? C2 : C1, DHID, DHID, m0, h * 64);
}

__global__ __launch_bounds__(256) void k_gemm64d(const float* __restrict__ A1,
                                                 const float* __restrict__ A2,
                                                 const float* __restrict__ B,
                                                 float* __restrict__ C1,
                                                 float* __restrict__ C2) {
    int half = blockIdx.y >> 5;
    int m0 = (blockIdx.y & 31) * 128;
    gemm64_body(half ? A2 : A1, B + blockIdx.x * 64, DHID,
                half ? C2 : C1, DHID, DHID, m0, blockIdx.x * 64);
}

// ---- hypergraph gathers ----
__global__ void k_gather_edges() {
    int e = blockIdx.x * 4 + (threadIdx.x >> 5);
    int lane = threadIdx.x & 31;
    float4 a0 = {0, 0, 0, 0}, a1 = {0, 0, 0, 0};
    for (int k = 0; k < KP1; k++) {
        int i = g_idx[e * KP1 + k];
        float w = g_dv[i];
        const float4* r = (const float4*)&g_XT[(size_t)i * DHID];
        float4 x0 = r[lane], x1 = r[lane + 32];
        a0.x += w * x0.x; a0.y += w * x0.y; a0.z += w * x0.z; a0.w += w * x0.w;
        a1.x += w * x1.x; a1.y += w * x1.y; a1.z += w * x1.z; a1.w += w * x1.w;
    }
    a0.x *= DE_C; a0.y *= DE_C; a0.z *= DE_C; a0.w *= DE_C;
    a1.x *= DE_C; a1.y *= DE_C; a1.z *= DE_C; a1.w *= DE_C;
    float4* o = (float4*)&g_Xe[(size_t)e * DHID];
    o[lane] = a0; o[lane + 32] = a1;
    float nq = a0.x * a0.x + a0.y * a0.y + a0.z * a0.z + a0.w * a0.w
             + a1.x * a1.x + a1.y * a1.y + a1.z * a1.z + a1.w * a1.w;
    for (int of = 16; of; of >>= 1) nq += __shfl_xor_sync(0xffffffffu, nq, of);
    if (lane == 0) g_nrm[e] = sqrtf(nq);
}

__global__ void k_gather_nodes() {
    int i = blockIdx.x * 4 + (threadIdx.x >> 5);
    int lane = threadIdx.x & 31;
    int beg = g_roff[i], end = g_roff[i + 1];
    float4 a0 = {0, 0, 0, 0}, a1 = {0, 0, 0, 0};
    for (int k = beg; k < end; k++) {
        const float4* r = (const float4*)&g_Xe[(size_t)g_redge[k] * DHID];
        float4 x0 = r[lane], x1 = r[lane + 32];
        a0.x += x0.x; a0.y += x0.y; a0.z += x0.z; a0.w += x0.w;
        a1.x += x1.x; a1.y += x1.y; a1.z += x1.z; a1.w += x1.w;
    }
    float s = g_dv[i] * DE_C;
    a0.x *= s; a0.y *= s; a0.z *= s; a0.w *= s;
    a1.x *= s; a1.y *= s; a1.z *= s; a1.w *= s;
    float4* o = (float4*)&g_E[(size_t)i * DHID];
    o[lane] = a0; o[lane + 32] = a1;
}

// rownorm: 256 threads, 8 rows/block
__global__ void k_rownorm(const float* __restrict__ Xf) {
    int row = blockIdx.x * 8 + (threadIdx.x >> 5);
    int lane = threadIdx.x & 31;
    const float4* r = (const float4*)&Xf[(size_t)row * DHID];
    float4 x0 = r[lane], x1 = r[lane + 32];
    float a = x0.x * x0.x + x0.y * x0.y + x0.z * x0.z + x0.w * x0.w
            + x1.x * x1.x + x1.y * x1.y + x1.z * x1.z + x1.w * x1.w;
    for (int o = 16; o; o >>= 1) a += __shfl_xor_sync(0xffffffffu, a, o);
    if (lane == 0) g_nrm[row] = sqrtf(a);
}

// density: 2-way unrolled neighbor dot products
__global__ void k_density(const float* __restrict__ Xf) {
    __shared__ float xs[DHID];
    __shared__ float ps[8];
    int i = blockIdx.x, t = threadIdx.x;
    xs[t] = Xf[(size_t)i * DHID + t];
    __syncthreads();
    int lane = t & 31, wp = t >> 5;
    const float4* xs4 = (const float4*)xs;
    float4 x0 = xs4[lane], x1 = xs4[lane + 32];
    const int* nbr = (const int*)g_dist + (size_t)i * NPTS;
    int n = g_ncnt[i];
    float ni = g_nrm[i], part = 0.f;
    for (int e0 = wp; e0 < n; e0 += 16) {
        int e1 = e0 + 8;
        bool have2 = (e1 < n);
        int j1 = nbr[e0];
        int j2 = have2 ? nbr[e1] : j1;
        const float4* r1 = (const float4*)&Xf[(size_t)j1 * DHID];
        const float4* r2 = (const float4*)&Xf[(size_t)j2 * DHID];
        float4 a0 = r1[lane], a1 = r1[lane + 32];
        float4 b0 = r2[lane], b1 = r2[lane + 32];
        float d1 = x0.x * a0.x + x0.y * a0.y + x0.z * a0.z + x0.w * a0.w
                 + x1.x * a1.x + x1.y * a1.y + x1.z * a1.z + x1.w * a1.w;
        float d2 = x0.x * b0.x + x0.y * b0.y + x0.z * b0.z + x0.w * b0.w
                 + x1.x * b1.x + x1.y * b1.y + x1.z * b1.z + x1.w * b1.w;
#pragma unroll
        for (int o = 16; o; o >>= 1) {
            d1 += __shfl_xor_sync(0xffffffffu, d1, o);
            d2 += __shfl_xor_sync(0xffffffffu, d2, o);
        }
        if (lane == 0) {
            float c1 = d1 / (ni * g_nrm[j1]);
            if (c1 > SIGMA_C) part += c1;
            if (have2) {
                float c2 = d2 / (ni * g_nrm[j2]);
                if (c2 > SIGMA_C) part += c2;
            }
        }
    }
    if (lane == 0) ps[wp] = part;
    __syncthreads();
    if (t == 0) {
        float a = 0.f;
        for (int q = 0; q < 8; q++) a += ps[q];
        g_rho[i] = a;
    }
}

// rhoe + fused maxima of rho and rhoe
__global__ void k_rhoe(int rslot, int reslot) {
    __shared__ float sm1[8], sm2[8];
    int e = blockIdx.x * 256 + threadIdx.x;
    float r = 0.f;
    for (int k = 0; k < KP1; k++) r += g_rho[g_idx[e * KP1 + k]];
    g_rhoe[e] = r;
    float rr = g_rho[e];
    for (int o = 16; o; o >>= 1) {
        r = fmaxf(r, __shfl_xor_sync(0xffffffffu, r, o));
        rr = fmaxf(rr, __shfl_xor_sync(0xffffffffu, rr, o));
    }
    int t = threadIdx.x;
    if ((t & 31) == 0) { sm1[t >> 5] = rr; sm2[t >> 5] = r; }
    __syncthreads();
    if (t == 0) {
        float m1 = sm1[0], m2 = sm2[0];
        for (int q = 1; q < 8; q++) { m1 = fmaxf(m1, sm1[q]); m2 = fmaxf(m2, sm2[q]); }
        atomicMax(&g_smax[rslot], encf(m1));
        atomicMax(&g_smax[reslot], encf(m2));
    }
}

// ---- s/t matvec device bodies (take virtual block id) ----
__device__ __forceinline__ void svtv4_body(int vb, const float* __restrict__ Ms,
                                           const float* __restrict__ Mt,
                                           const float* __restrict__ av, int sb,
                                           float* sOut, float* tOut) {
    __shared__ float sm4[8];
    int w = vb * 8 + (threadIdx.x >> 5);
    int lane = threadIdx.x & 31;
    int row = w & (NPTS - 1);
    int g = w >> 12;
    int h = g & 3, which = g >> 2;
    const float* M = which ? Mt : Ms;
    const float2* a2 = (const float2*)(av + (size_t)h * 2 * DHEAD + which * DHEAD);
    const float2* r2 = (const float2*)(M + (size_t)row * DHID + h * DHEAD);
    float2 rv = r2[lane], av2 = a2[lane];
    float p = rv.x * av2.x + rv.y * av2.y;
    for (int o = 16; o; o >>= 1) p += __shfl_xor_sync(0xffffffffu, p, o);
    if (lane == 0) {
        (which ? tOut : sOut)[h * NPTS + row] = p;
        sm4[(threadIdx.x >> 5)] = p;
    }
    __syncthreads();
    if (threadIdx.x == 0) {
        float m = sm4[0];
        for (int q = 1; q < 8; q++) m = fmaxf(m, sm4[q]);
        atomicMax(&g_smax[sb + which * 4 + h], encf(m));
    }
}

__device__ __forceinline__ void svtv1_body(int vb, const float* __restrict__ Ms,
                                           const float* __restrict__ as,
                                           const float* __restrict__ Mt,
                                           const float* __restrict__ at, int sb,
                                           float* sOut, float* tOut) {
    __shared__ float sm1b[8];
    int w = vb * 8 + (threadIdx.x >> 5);
    int lane = threadIdx.x & 31;
    int row = w & (NPTS - 1);
    int which = w >> 12;
    const float* M = which ? Mt : Ms;
    const float* a = which ? at : as;
    const float4* r = (const float4*)(M + (size_t)row * DHID);
    const float4* a4 = (const float4*)a;
    float4 r0 = r[lane], r1 = r[lane + 32];
    float4 b0 = a4[lane], b1 = a4[lane + 32];
    float p = r0.x * b0.x + r0.y * b0.y + r0.z * b0.z + r0.w * b0.w
            + r1.x * b1.x + r1.y * b1.y + r1.z * b1.z + r1.w * b1.w;
    for (int o = 16; o; o >>= 1) p += __shfl_xor_sync(0xffffffffu, p, o);
    if (lane == 0) {
        (which ? tOut : sOut)[row] = p;
        sm1b[(threadIdx.x >> 5)] = p;
    }
    __syncthreads();
    if (threadIdx.x == 0) {
        float m = sm1b[0];
        for (int q = 1; q < 8; q++) m = fmaxf(m, sm1b[q]);
        atomicMax(&g_smax[sb + which], encf(m));
    }
}

__global__ void k_svtv4(const float* __restrict__ Ms, const float* __restrict__ Mt,
                        const float* __restrict__ av, int sb,
                        float* sOut, float* tOut) {
    svtv4_body(blockIdx.x, Ms, Mt, av, sb, sOut, tOut);
}

__global__ void k_svtv1(const float* __restrict__ Ms, const float* __restrict__ as,
                        const float* __restrict__ Mt, const float* __restrict__ at,
                        int sb, float* sOut, float* tOut) {
    svtv1_body(blockIdx.x, Ms, as, Mt, at, sb, sOut, tOut);
}

__device__ __forceinline__ float lrelu(float x) { return x > 0.f ? x : 0.2f * x; }
__device__ __forceinline__ float elu1(float x) { return x > 0.f ? x : expm1f(x); }

// attention body: 256 threads, 8 warp-tasks/block; task = (h, row)
template <int D>
__device__ __forceinline__ void att4_body(int vb, const float* __restrict__ rho, int rslot,
                                          const float* __restrict__ valb, int ldv,
                                          float* __restrict__ outb, int ldo, int hstride,
                                          const float* sBase, const float* tBase,
                                          int sb, int nh) {
    int task = vb * 8 + (threadIdx.x >> 5);
    int lane = threadIdx.x & 31;
    int row = task & (NPTS - 1);
    int h = task >> 12;
    const float* sA = sBase + h * NPTS;
    const float* tA = tBase + h * NPTS;
    float smx = decf(g_smax[sb + h]);
    float tmx = decf(g_smax[sb + nh + h]);
    float ax_max = lrelu(smx + tmx);
    float rt = rho[row] / decf(g_smax[rslot]) * ax_max;
    float si = sA[row];
    int beg = g_roff[row], end = g_roff[row + 1];
    int deg = end - beg;
    const float* val = valb + h * hstride;
    float* out = outb + h * hstride;
    const int C2 = D / 64;
    float2 acc[C2];
#pragma unroll
    for (int j = 0; j < C2; j++) acc[j] = make_float2(0.f, 0.f);
    float iz;
    if (deg <= 32) {
        int mye = (lane < deg) ? g_redge[beg + lane] : 0;
        float st = (lane < deg) ? (lrelu(si + tA[mye]) + rt) : -FLT_MAX;
        float m = st;
        for (int o = 16; o; o >>= 1) m = fmaxf(m, __shfl_xor_sync(0xffffffffu, m, o));
        float myw = (lane < deg) ? expf(st - m) : 0.f;
        float Z = myw;
        for (int o = 16; o; o >>= 1) Z += __shfl_xor_sync(0xffffffffu, Z, o);
        for (int k = 0; k < deg; k++) {
            int e = __shfl_sync(0xffffffffu, mye, k);
            float wt = __shfl_sync(0xffffffffu, myw, k);
            const float2* v2 = (const float2*)&val[(size_t)e * ldv];
#pragma unroll
            for (int j = 0; j < C2; j++) {
                float2 x = v2[lane + j * 32];
                acc[j].x += wt * x.x; acc[j].y += wt * x.y;
            }
        }
        iz = 1.f / Z;
    } else {
        float m = -FLT_MAX;
        for (int k = beg + lane; k < end; k += 32)
            m = fmaxf(m, lrelu(si + tA[g_redge[k]]) + rt);
        for (int o = 16; o; o >>= 1) m = fmaxf(m, __shfl_xor_sync(0xffffffffu, m, o));
        float Z = 0.f;
        for (int k = beg + lane; k < end; k += 32)
            Z += expf(lrelu(si + tA[g_redge[k]]) + rt - m);
        for (int o = 16; o; o >>= 1) Z += __shfl_xor_sync(0xffffffffu, Z, o);
        for (int k = beg; k < end; k++) {
            int e = g_redge[k];
            float wt = expf(lrelu(si + tA[e]) + rt - m);
            const float2* v2 = (const float2*)&val[(size_t)e * ldv];
#pragma unroll
            for (int j = 0; j < C2; j++) {
                float2 x = v2[lane + j * 32];
                acc[j].x += wt * x.x; acc[j].y += wt * x.y;
            }
        }
        iz = 1.f / Z;
    }
    float2* o2 = (float2*)&out[(size_t)row * ldo];
#pragma unroll
    for (int j = 0; j < C2; j++) {
        float2 r;
        r.x = elu1(acc[j].x * iz);
        r.y = elu1(acc[j].y * iz);
        o2[lane + j * 32] = r;
    }
}

template <int D>
__global__ void k_att4x(const float* __restrict__ rho, int rslot,
                        const float* __restrict__ valb, int ldv,
                        float* __restrict__ outb, int ldo, int hstride,
                        const float* sBase, const float* tBase, int sb, int nh) {
    att4_body<D>(blockIdx.x, rho, rslot, valb, ldv, outb, ldo, hstride, sBase, tBase, sb, nh);
}

// fused: att4<64> pass1 (2048 vblocks) || svtv4 pass2 (4096 vblocks)
__global__ void k_att1_svtv2(const float* __restrict__ rho,
                             const float* __restrict__ P,
                             const float* __restrict__ Q,
                             float* __restrict__ Enew,
                             const float* __restrict__ aeh,
                             const float* svh, const float* tvh,
                             float* svh2, float* tvh2) {
    int vb = blockIdx.x;
    if (vb < 2048)
        att4_body<DHEAD>(vb, rho, 20, P, DHID, Enew, DHID, DHEAD, svh, tvh, 0, 4);
    else
        svtv4_body(vb - 2048, Q, P, aeh, 8, svh2, tvh2);
}

// fused: att4<256> final pass1 (512 vblocks) || svtv1 pass2 (1024 vblocks)
__global__ void k_attf1_svtv2(const float* __restrict__ rho,
                              const float* __restrict__ P,
                              const float* __restrict__ Q,
                              float* __restrict__ Enew,
                              const float* __restrict__ ae2,
                              const float* svh, const float* tvh,
                              float* svh2, float* tvh2) {
    int vb = blockIdx.x;
    if (vb < 512)
        att4_body<DHID>(vb, rho, 22, P, DHID, Enew, DHID, 0, svh, tvh, 16, 1);
    else
        svtv1_body(vb - 512, Q, ae2, P, ae2 + DHID, 18, svh2, tvh2);
}

// ---------------- host orchestration ----------------
extern "C" void kernel_launch(void* const* d_in, const int* in_sizes, int n_in,
                              void* d_out, int out_size) {
    const float* X     = (const float*)d_in[0];
    const float* theta = (const float*)d_in[1];
    const float* Wh    = (const float*)d_in[2];
    const float* axh   = (const float*)d_in[3];
    const float* aeh   = (const float*)d_in[4];
    const float* W2    = (const float*)d_in[5];
    const float* ax2   = (const float*)d_in[6];
    const float* ae2   = (const float*)d_in[7];
    float* out = (float*)d_out;
    (void)in_sizes; (void)n_in; (void)out_size;

    void* vp;
    cudaGetSymbolAddress(&vp, g_XT);   float* XT   = (float*)vp;
    cudaGetSymbolAddress(&vp, g_Xe);   float* Xe   = (float*)vp;
    cudaGetSymbolAddress(&vp, g_E);    float* E    = (float*)vp;
    cudaGetSymbolAddress(&vp, g_rho);  float* rho  = (float*)vp;
    cudaGetSymbolAddress(&vp, g_rhoe); float* rhoe = (float*)vp;
    cudaGetSymbolAddress(&vp, g_P);    float* P    = (float*)vp;
    cudaGetSymbolAddress(&vp, g_Q);    float* Q    = (float*)vp;
    cudaGetSymbolAddress(&vp, g_Enew); float* Enew = (float*)vp;
    cudaGetSymbolAddress(&vp, g_Xcat); float* Xcat = (float*)vp;
    cudaGetSymbolAddress(&vp, g_svh);  float* svh  = (float*)vp;
    cudaGetSymbolAddress(&vp, g_tvh);  float* tvh  = (float*)vp;
    cudaGetSymbolAddress(&vp, g_svh2); float* svh2 = (float*)vp;
    cudaGetSymbolAddress(&vp, g_tvh2); float* tvh2 = (float*)vp;

    // profiled slot #4 = k_scanfill
    k_rowsq<<<NPTS / 4, 128>>>(X);
    k_aat_dist_sym<<<528, 256>>>(X);
    k_topk_warp<<<512, 256>>>();
    k_scanfill<<<1, 1024>>>();          // profiled

    k_gemm64x<<<dim3(4, 64), 256>>>(X, theta, XT, DIN, DHID);
    k_gather_edges<<<NPTS / 4, 128>>>();
    k_gather_nodes<<<NPTS / 4, 128>>>();
    k_nbr<<<NPTS, 128>>>();

    // densities (stage 1)
    k_density<<<NPTS, 256>>>(Xe);
    k_rhoe<<<16, 256>>>(20, 21);

    // all-head projections
    k_gemm64h2<<<dim3(4, 64), 256>>>(Xe, E, Wh, P, Q);

    // attention pass 1 s/t
    k_svtv4<<<4096, 256>>>(P, Q, axh, 0, svh, tvh);
    // fused: att pass1 || svtv pass2 (double-buffered)
    k_att1_svtv2<<<6144, 256>>>(rho, P, Q, Enew, aeh, svh, tvh, svh2, tvh2);
    // attention pass 2 (ldo = DHID: head h writes cols h*64..h*64+63 of Xcat)
    k_att4x<DHEAD><<<2048, 256>>>(rhoe, 21, Enew, DHID, Xcat, DHID, DHEAD, svh2, tvh2, 8, 4);

    // final DA-HGAN layer
    k_rownorm<<<NPTS / 8, 256>>>(Xcat);
    k_density<<<NPTS, 256>>>(Xcat);
    k_rhoe<<<16, 256>>>(22, 23);

    k_gemm64d<<<dim3(4, 64), 256>>>(Xcat, E, W2, P, Q);

    k_svtv1<<<1024, 256>>>(P, ax2, Q, ax2 + DHID, 16, svh, tvh);
    k_attf1_svtv2<<<1536, 256>>>(rho, P, Q, Enew, ae2, svh, tvh, svh2, tvh2);
    k_att4x<DHID><<<512, 256>>>(rhoe, 23, Enew, DHID, out, DHID, 0, svh2, tvh2, 18, 1);
}

// round 13
// speedup vs baseline: 1.0592x; 1.0290x over previous
#include <cuda_runtime.h>
#include <math.h>
#include <float.h>

// ---------------- problem constants ----------------
#define NPTS  4096
#define DIN   784
#define DHID  256
#define MH    4
#define DHEAD 64
#define KP1   11
#define SIGMA_C 0.1f
#define DE_C  0.30151134457776363f   // 1/sqrt(11)

// ---------------- device scratch ----------------
__device__ float g_dist[(size_t)NPTS * NPTS];  // 64MB; after topk reused as int nbr[4096][4096]
__device__ float g_sq[NPTS];
__device__ int   g_idx[NPTS * KP1];
__device__ int   g_deg[NPTS];
__device__ float g_dv[NPTS];
__device__ int   g_roff[NPTS + 1];
__device__ int   g_cursor[NPTS];
__device__ int   g_redge[NPTS * KP1];
__device__ int   g_ncnt[NPTS];
__device__ float g_XT[NPTS * DHID];
__device__ float g_Xe[NPTS * DHID];
__device__ float g_E[NPTS * DHID];
__device__ float g_nrm[NPTS];
__device__ float g_rho[NPTS];
__device__ float g_rhoe[NPTS];
__device__ float g_P[NPTS * DHID];
__device__ float g_Q[NPTS * DHID];
__device__ float g_svh[MH * NPTS];
__device__ float g_tvh[MH * NPTS];
__device__ float g_svh2[MH * NPTS];
__device__ float g_tvh2[MH * NPTS];
__device__ float g_Enew[NPTS * DHID];
__device__ float g_Xcat[NPTS * DHID];
__device__ unsigned g_smax[32];

__device__ __forceinline__ unsigned encf(float f) {
    unsigned u = __float_as_uint(f);
    return (u & 0x80000000u) ? ~u : (u | 0x80000000u);
}
__device__ __forceinline__ float decf(unsigned u) {
    return __uint_as_float((u & 0x80000000u) ? (u & 0x7fffffffu) : ~u);
}

// ---------------- rowsq + fused zero-init ----------------
__global__ void k_rowsq(const float* __restrict__ X) {
    int gid = blockIdx.x * 128 + threadIdx.x;
    if (gid < NPTS) g_deg[gid] = 0;
    if (gid < 32) g_smax[gid] = 0u;
    int row = blockIdx.x * 4 + (threadIdx.x >> 5);
    int lane = threadIdx.x & 31;
    const float4* r = (const float4*)&X[(size_t)row * DIN];
    float a = 0.f;
    for (int c = lane; c < DIN / 4; c += 32) {
        float4 v = r[c];
        a += v.x * v.x + v.y * v.y + v.z * v.z + v.w * v.w;
    }
    for (int o = 16; o; o >>= 1) a += __shfl_xor_sync(0xffffffffu, a, o);
    if (lane == 0) g_sq[row] = a;
}

// ---- symmetric dist GEMM: upper-tri 128x128 blocks, mirrored f4 writes ----
__global__ __launch_bounds__(256) void k_aat_dist_sym(const float* __restrict__ A) {
    __shared__ float As[2][16][128];
    __shared__ float Bs[2][16][128];
    int b = blockIdx.x, by = 0;
    while (b >= 32 - by) { b -= 32 - by; ++by; }
    int bx = by + b;
    int row0 = by * 128, col0 = bx * 128;
    int t = threadIdx.x;
    int ty = t >> 4, tx = t & 15;
    int ra = t >> 2, qa = (t & 3) * 4;

    float4 pa0, pa1, pb0, pb1;
    pa0 = *(const float4*)&A[(size_t)(row0 + ra) * DIN + qa];
    pa1 = *(const float4*)&A[(size_t)(row0 + ra + 64) * DIN + qa];
    pb0 = *(const float4*)&A[(size_t)(col0 + ra) * DIN + qa];
    pb1 = *(const float4*)&A[(size_t)(col0 + ra + 64) * DIN + qa];
    As[0][qa + 0][ra] = pa0.x; As[0][qa + 1][ra] = pa0.y; As[0][qa + 2][ra] = pa0.z; As[0][qa + 3][ra] = pa0.w;
    As[0][qa + 0][ra + 64] = pa1.x; As[0][qa + 1][ra + 64] = pa1.y; As[0][qa + 2][ra + 64] = pa1.z; As[0][qa + 3][ra + 64] = pa1.w;
    Bs[0][qa + 0][ra] = pb0.x; Bs[0][qa + 1][ra] = pb0.y; Bs[0][qa + 2][ra] = pb0.z; Bs[0][qa + 3][ra] = pb0.w;
    Bs[0][qa + 0][ra + 64] = pb1.x; Bs[0][qa + 1][ra + 64] = pb1.y; Bs[0][qa + 2][ra + 64] = pb1.z; Bs[0][qa + 3][ra + 64] = pb1.w;
    __syncthreads();

    float acc[8][8];
#pragma unroll
    for (int i = 0; i < 8; i++)
#pragma unroll
        for (int j = 0; j < 8; j++) acc[i][j] = 0.f;

    const int nIt = DIN / 16;
    for (int it = 0; it < nIt; ++it) {
        int k0n = (it + 1) * 16;
        if (it + 1 < nIt) {
            pa0 = *(const float4*)&A[(size_t)(row0 + ra) * DIN + k0n + qa];
            pa1 = *(const float4*)&A[(size_t)(row0 + ra + 64) * DIN + k0n + qa];
            pb0 = *(const float4*)&A[(size_t)(col0 + ra) * DIN + k0n + qa];
            pb1 = *(const float4*)&A[(size_t)(col0 + ra + 64) * DIN + k0n + qa];
        }
        int buf = it & 1;
#pragma unroll
        for (int kk = 0; kk < 16; ++kk) {
            float4 a0 = *(const float4*)&As[buf][kk][ty * 8];
            float4 a1 = *(const float4*)&As[buf][kk][ty * 8 + 4];
            float4 b0 = *(const float4*)&Bs[buf][kk][tx * 8];
            float4 b1 = *(const float4*)&Bs[buf][kk][tx * 8 + 4];
            float ar[8] = {a0.x, a0.y, a0.z, a0.w, a1.x, a1.y, a1.z, a1.w};
            float br[8] = {b0.x, b0.y, b0.z, b0.w, b1.x, b1.y, b1.z, b1.w};
#pragma unroll
            for (int i = 0; i < 8; i++)
#pragma unroll
                for (int j = 0; j < 8; j++) acc[i][j] += ar[i] * br[j];
        }
        if (it + 1 < nIt) {
            int nb = buf ^ 1;
            As[nb][qa + 0][ra] = pa0.x; As[nb][qa + 1][ra] = pa0.y; As[nb][qa + 2][ra] = pa0.z; As[nb][qa + 3][ra] = pa0.w;
            As[nb][qa + 0][ra + 64] = pa1.x; As[nb][qa + 1][ra + 64] = pa1.y; As[nb][qa + 2][ra + 64] = pa1.z; As[nb][qa + 3][ra + 64] = pa1.w;
            Bs[nb][qa + 0][ra] = pb0.x; Bs[nb][qa + 1][ra] = pb0.y; Bs[nb][qa + 2][ra] = pb0.z; Bs[nb][qa + 3][ra] = pb0.w;
            Bs[nb][qa + 0][ra + 64] = pb1.x; Bs[nb][qa + 1][ra + 64] = pb1.y; Bs[nb][qa + 2][ra + 64] = pb1.z; Bs[nb][qa + 3][ra + 64] = pb1.w;
        }
        __syncthreads();
    }

    float si_[8], sj_[8];
#pragma unroll
    for (int i = 0; i < 8; i++) si_[i] = g_sq[row0 + ty * 8 + i];
#pragma unroll
    for (int j = 0; j < 8; j++) sj_[j] = g_sq[col0 + tx * 8 + j];

#pragma unroll
    for (int i = 0; i < 8; i++) {
        int gi = row0 + ty * 8 + i;
        float4 w0, w1;
        w0.x = fabsf(si_[i] + sj_[0] - 2.f * acc[i][0]);
        w0.y = fabsf(si_[i] + sj_[1] - 2.f * acc[i][1]);
        w0.z = fabsf(si_[i] + sj_[2] - 2.f * acc[i][2]);
        w0.w = fabsf(si_[i] + sj_[3] - 2.f * acc[i][3]);
        w1.x = fabsf(si_[i] + sj_[4] - 2.f * acc[i][4]);
        w1.y = fabsf(si_[i] + sj_[5] - 2.f * acc[i][5]);
        w1.z = fabsf(si_[i] + sj_[6] - 2.f * acc[i][6]);
        w1.w = fabsf(si_[i] + sj_[7] - 2.f * acc[i][7]);
        *(float4*)&g_dist[(size_t)gi * NPTS + col0 + tx * 8] = w0;
        *(float4*)&g_dist[(size_t)gi * NPTS + col0 + tx * 8 + 4] = w1;
    }
#pragma unroll
    for (int j = 0; j < 8; j++) {
        int gj = col0 + tx * 8 + j;
        float4 w0, w1;
        w0.x = fabsf(si_[0] + sj_[j] - 2.f * acc[0][j]);
        w0.y = fabsf(si_[1] + sj_[j] - 2.f * acc[1][j]);
        w0.z = fabsf(si_[2] + sj_[j] - 2.f * acc[2][j]);
        w0.w = fabsf(si_[3] + sj_[j] - 2.f * acc[3][j]);
        w1.x = fabsf(si_[4] + sj_[j] - 2.f * acc[4][j]);
        w1.y = fabsf(si_[5] + sj_[j] - 2.f * acc[5][j]);
        w1.z = fabsf(si_[6] + sj_[j] - 2.f * acc[6][j]);
        w1.w = fabsf(si_[7] + sj_[j] - 2.f * acc[7][j]);
        *(float4*)&g_dist[(size_t)gj * NPTS + row0 + ty * 8] = w0;
        *(float4*)&g_dist[(size_t)gj * NPTS + row0 + ty * 8 + 4] = w1;
    }
}

// ---- warp-per-row top-11 ----
__device__ __forceinline__ bool pless(float av, int ai, float bv, int bi) {
    return av < bv || (av == bv && ai < bi);
}

__global__ __launch_bounds__(256) void k_topk_warp() {
    int row = blockIdx.x * 8 + (threadIdx.x >> 5);
    int lane = threadIdx.x & 31;
    const float4* drow = (const float4*)&g_dist[(size_t)row * NPTS];
    float lv[KP1]; int li[KP1];
#pragma unroll
    for (int q = 0; q < KP1; q++) { lv[q] = FLT_MAX; li[q] = 0x7fffffff; }
#pragma unroll 2
    for (int s = 0; s < 32; s++) {
        int p4 = s * 32 + lane;
        float4 v4 = drow[p4];
        float vv[4] = {v4.x, v4.y, v4.z, v4.w};
        int jb = p4 * 4;
#pragma unroll
        for (int c = 0; c < 4; c++) {
            float v = vv[c]; int j = jb + c;
            if (pless(v, j, lv[KP1 - 1], li[KP1 - 1])) {
                lv[KP1 - 1] = v; li[KP1 - 1] = j;
#pragma unroll
                for (int q = KP1 - 1; q > 0; q--) {
                    if (pless(lv[q], li[q], lv[q - 1], li[q - 1])) {
                        float tv_ = lv[q]; lv[q] = lv[q - 1]; lv[q - 1] = tv_;
                        int ti_ = li[q]; li[q] = li[q - 1]; li[q - 1] = ti_;
                    }
                }
            }
        }
    }
    for (int it = 0; it < KP1; ++it) {
        float v = lv[0]; int ix = li[0];
#pragma unroll
        for (int o = 16; o; o >>= 1) {
            float ov = __shfl_xor_sync(0xffffffffu, v, o);
            int oi = __shfl_xor_sync(0xffffffffu, ix, o);
            if (pless(ov, oi, v, ix)) { v = ov; ix = oi; }
        }
        if (li[0] == ix) {
#pragma unroll
            for (int q = 0; q < KP1 - 1; q++) { lv[q] = lv[q + 1]; li[q] = li[q + 1]; }
            lv[KP1 - 1] = FLT_MAX; li[KP1 - 1] = 0x7fffffff;
        }
        if (lane == 0) {
            g_idx[row * KP1 + it] = ix;
            atomicAdd(&g_deg[ix], 1);
        }
    }
}

// ---- scan only (1 block): prefix + dv + cursor ----
__global__ void k_scan() {
    __shared__ int s[1024];
    int t = threadIdx.x;
    int base = t * 4;
    int v0 = g_deg[base], v1 = g_deg[base + 1], v2 = g_deg[base + 2], v3 = g_deg[base + 3];
    int sum = v0 + v1 + v2 + v3;
    s[t] = sum;
    __syncthreads();
    for (int off = 1; off < 1024; off <<= 1) {
        int x = (t >= off) ? s[t - off] : 0;
        __syncthreads();
        s[t] += x;
        __syncthreads();
    }
    int run = s[t] - sum;
    g_roff[base] = run; g_cursor[base] = run; g_dv[base] = rsqrtf((float)v0); run += v0;
    g_roff[base + 1] = run; g_cursor[base + 1] = run; g_dv[base + 1] = rsqrtf((float)v1); run += v1;
    g_roff[base + 2] = run; g_cursor[base + 2] = run; g_dv[base + 2] = rsqrtf((float)v2); run += v2;
    g_roff[base + 3] = run; g_cursor[base + 3] = run; g_dv[base + 3] = rsqrtf((float)v3); run += v3;
    if (t == 1023) g_roff[NPTS] = run;
}

// ---- multi-block CSR fill: one entry per thread (176 x 256) ----
__global__ void k_fill() {
    int p = blockIdx.x * 256 + threadIdx.x;   // 45056 = NPTS*KP1
    int i = g_idx[p];
    int pos = atomicAdd(&g_cursor[i], 1);
    g_redge[pos] = p / KP1;
}

// ---- bodies for gather_edges and nbr (for grid fusion) ----
__device__ __forceinline__ void gather_edges_body(int vb, int t) {
    int e = vb * 4 + (t >> 5);
    int lane = t & 31;
    float4 a0 = {0, 0, 0, 0}, a1 = {0, 0, 0, 0};
    for (int k = 0; k < KP1; k++) {
        int i = g_idx[e * KP1 + k];
        float w = g_dv[i];
        const float4* r = (const float4*)&g_XT[(size_t)i * DHID];
        float4 x0 = r[lane], x1 = r[lane + 32];
        a0.x += w * x0.x; a0.y += w * x0.y; a0.z += w * x0.z; a0.w += w * x0.w;
        a1.x += w * x1.x; a1.y += w * x1.y; a1.z += w * x1.z; a1.w += w * x1.w;
    }
    a0.x *= DE_C; a0.y *= DE_C; a0.z *= DE_C; a0.w *= DE_C;
    a1.x *= DE_C; a1.y *= DE_C; a1.z *= DE_C; a1.w *= DE_C;
    float4* o = (float4*)&g_Xe[(size_t)e * DHID];
    o[lane] = a0; o[lane + 32] = a1;
    float nq = a0.x * a0.x + a0.y * a0.y + a0.z * a0.z + a0.w * a0.w
             + a1.x * a1.x + a1.y * a1.y + a1.z * a1.z + a1.w * a1.w;
    for (int of = 16; of; of >>= 1) nq += __shfl_xor_sync(0xffffffffu, nq, of);
    if (lane == 0) g_nrm[e] = sqrtf(nq);
}

__device__ __forceinline__ void nbr_body(int i, int t) {
    __shared__ unsigned bm[128];
    __shared__ int wsum[4];
    bm[t] = 0u;
    __syncthreads();
    int beg = g_roff[i];
    int cnt = (g_roff[i + 1] - beg) * KP1;
    for (int p = t; p < cnt; p += 128) {
        int e = g_redge[beg + p / KP1];
        int m = g_idx[e * KP1 + p % KP1];
        atomicOr(&bm[m >> 5], 1u << (m & 31));
    }
    __syncthreads();
    if (t == 0) bm[i >> 5] &= ~(1u << (i & 31));
    __syncthreads();
    unsigned w = bm[t];
    int pc = __popc(w);
    int lane = t & 31, wid = t >> 5;
    int sc = pc;
    for (int o = 1; o < 32; o <<= 1) {
        int x = __shfl_up_sync(0xffffffffu, sc, o);
        if (lane >= o) sc += x;
    }
    if (lane == 31) wsum[wid] = sc;
    __syncthreads();
    int woff = 0;
    for (int q = 0; q < wid; q++) woff += wsum[q];
    int off = woff + sc - pc;
    int* nbr = (int*)g_dist + (size_t)i * NPTS;
    while (w) {
        int b = __ffs(w) - 1; w &= w - 1;
        nbr[off++] = t * 32 + b;
    }
    if (t == 127) g_ncnt[i] = woff + sc;
}

// fused: gather_edges (1024 vblocks) || nbr (4096 vblocks); both 128 threads
__global__ void k_gedge_nbr() {
    if (blockIdx.x < 1024) gather_edges_body(blockIdx.x, threadIdx.x);
    else nbr_body(blockIdx.x - 1024, threadIdx.x);
}

__global__ void k_gather_nodes() {
    int i = blockIdx.x * 4 + (threadIdx.x >> 5);
    int lane = threadIdx.x & 31;
    int beg = g_roff[i], end = g_roff[i + 1];
    float4 a0 = {0, 0, 0, 0}, a1 = {0, 0, 0, 0};
    for (int k = beg; k < end; k++) {
        const float4* r = (const float4*)&g_Xe[(size_t)g_redge[k] * DHID];
        float4 x0 = r[lane], x1 = r[lane + 32];
        a0.x += x0.x; a0.y += x0.y; a0.z += x0.z; a0.w += x0.w;
        a1.x += x1.x; a1.y += x1.y; a1.z += x1.z; a1.w += x1.w;
    }
    float s = g_dv[i] * DE_C;
    a0.x *= s; a0.y *= s; a0.z *= s; a0.w *= s;
    a1.x *= s; a1.y *= s; a1.z *= s; a1.w *= s;
    float4* o = (float4*)&g_E[(size_t)i * DHID];
    o[lane] = a0; o[lane + 32] = a1;
}

// ---- 128x64 GEMM body (for the 256-col projections) ----
__device__ __forceinline__ void gemm64_body(const float* __restrict__ A,
                                            const float* __restrict__ B, int ldb,
                                            float* __restrict__ C, int ldc,
                                            int K, int m0, int n0b) {
    __shared__ float As[2][16][128];
    __shared__ float Bs[2][16][64];
    int t = threadIdx.x;
    int ty = t >> 4, tx = t & 15;
    int ra = t >> 1, qa = (t & 1) * 8;
    int kb = t >> 4, cb = (t & 15) * 4;

    float4 pa0, pa1, pb;
    pa0 = *(const float4*)&A[(size_t)(m0 + ra) * K + qa];
    pa1 = *(const float4*)&A[(size_t)(m0 + ra) * K + qa + 4];
    pb = *(const float4*)&B[(size_t)kb * ldb + cb];
    As[0][qa + 0][ra] = pa0.x; As[0][qa + 1][ra] = pa0.y; As[0][qa + 2][ra] = pa0.z; As[0][qa + 3][ra] = pa0.w;
    As[0][qa + 4][ra] = pa1.x; As[0][qa + 5][ra] = pa1.y; As[0][qa + 6][ra] = pa1.z; As[0][qa + 7][ra] = pa1.w;
    *(float4*)&Bs[0][kb][cb] = pb;
    __syncthreads();

    float acc[8][4];
#pragma unroll
    for (int i = 0; i < 8; i++)
#pragma unroll
        for (int j = 0; j < 4; j++) acc[i][j] = 0.f;

    int nIt = K / 16;
    for (int it = 0; it < nIt; ++it) {
        int k0n = (it + 1) * 16;
        if (it + 1 < nIt) {
            pa0 = *(const float4*)&A[(size_t)(m0 + ra) * K + k0n + qa];
            pa1 = *(const float4*)&A[(size_t)(m0 + ra) * K + k0n + qa + 4];
            pb = *(const float4*)&B[(size_t)(k0n + kb) * ldb + cb];
        }
        int buf = it & 1;
#pragma unroll
        for (int kk = 0; kk < 16; ++kk) {
            float4 a0 = *(const float4*)&As[buf][kk][ty * 8];
            float4 a1 = *(const float4*)&As[buf][kk][ty * 8 + 4];
            float4 b0 = *(const float4*)&Bs[buf][kk][tx * 4];
            float ar[8] = {a0.x, a0.y, a0.z, a0.w, a1.x, a1.y, a1.z, a1.w};
            float br[4] = {b0.x, b0.y, b0.z, b0.w};
#pragma unroll
            for (int i = 0; i < 8; i++)
#pragma unroll
                for (int j = 0; j < 4; j++) acc[i][j] += ar[i] * br[j];
        }
        if (it + 1 < nIt) {
            int nb = buf ^ 1;
            As[nb][qa + 0][ra] = pa0.x; As[nb][qa + 1][ra] = pa0.y; As[nb][qa + 2][ra] = pa0.z; As[nb][qa + 3][ra] = pa0.w;
            As[nb][qa + 4][ra] = pa1.x; As[nb][qa + 5][ra] = pa1.y; As[nb][qa + 6][ra] = pa1.z; As[nb][qa + 7][ra] = pa1.w;
            *(float4*)&Bs[nb][kb][cb] = pb;
        }
        __syncthreads();
    }
#pragma unroll
    for (int i = 0; i < 8; i++) {
        float4 w0 = {acc[i][0], acc[i][1], acc[i][2], acc[i][3]};
        *(float4*)&C[(size_t)(m0 + ty * 8 + i) * ldc + n0b + tx * 4] = w0;
    }
}

// ---- 64x64 GEMM (XT) ----
__global__ __launch_bounds__(256) void k_gemm64x(const float* __restrict__ A,
                                                 const float* __restrict__ B,
                                                 float* __restrict__ C, int K, int Np) {
    __shared__ float As[2][16][64];
    __shared__ float Bs[2][16][64];
    int t = threadIdx.x;
    int m0 = blockIdx.y * 64, n0 = blockIdx.x * 64;
    int ty = t >> 4, tx = t & 15;
    int ra = t >> 2, qa = (t & 3) * 4;
    int kb = t >> 4, cb = (t & 15) * 4;

    float4 pa, pb;
    pa = *(const float4*)&A[(size_t)(m0 + ra) * K + qa];
    pb = *(const float4*)&B[(size_t)kb * Np + n0 + cb];
    As[0][qa + 0][ra] = pa.x; As[0][qa + 1][ra] = pa.y; As[0][qa + 2][ra] = pa.z; As[0][qa + 3][ra] = pa.w;
    *(float4*)&Bs[0][kb][cb] = pb;
    __syncthreads();

    float acc[4][4];
#pragma unroll
    for (int i = 0; i < 4; i++)
#pragma unroll
        for (int j = 0; j < 4; j++) acc[i][j] = 0.f;

    int nIt = K / 16;
    for (int it = 0; it < nIt; ++it) {
        int k0n = (it + 1) * 16;
        if (it + 1 < nIt) {
            pa = *(const float4*)&A[(size_t)(m0 + ra) * K + k0n + qa];
            pb = *(const float4*)&B[(size_t)(k0n + kb) * Np + n0 + cb];
        }
        int buf = it & 1;
#pragma unroll
        for (int kk = 0; kk < 16; ++kk) {
            float4 a0 = *(const float4*)&As[buf][kk][ty * 4];
            float4 b0 = *(const float4*)&Bs[buf][kk][tx * 4];
            float ar[4] = {a0.x, a0.y, a0.z, a0.w};
            float br[4] = {b0.x, b0.y, b0.z, b0.w};
#pragma unroll
            for (int i = 0; i < 4; i++)
#pragma unroll
                for (int j = 0; j < 4; j++) acc[i][j] += ar[i] * br[j];
        }
        if (it + 1 < nIt) {
            int nb = buf ^ 1;
            As[nb][qa + 0][ra] = pa.x; As[nb][qa + 1][ra] = pa.y; As[nb][qa + 2][ra] = pa.z; As[nb][qa + 3][ra] = pa.w;
            *(float4*)&Bs[nb][kb][cb] = pb;
        }
        __syncthreads();
    }
#pragma unroll
    for (int i = 0; i < 4; i++) {
        float4 w0 = {acc[i][0], acc[i][1], acc[i][2], acc[i][3]};
        *(float4*)&C[(size_t)(m0 + ty * 4 + i) * Np + n0 + tx * 4] = w0;
    }
}

__global__ __launch_bounds__(256) void k_gemm64h2(const float* __restrict__ A1,
                                                  const float* __restrict__ A2,
                                                  const float* __restrict__ Wh,
                                                  float* __restrict__ C1,
                                                  float* __restrict__ C2) {
    int half = blockIdx.y >> 5;
    int m0 = (blockIdx.y & 31) * 128;
    int h = blockIdx.x;
    gemm64_body(half ? A2 : A1, Wh + (size_t)h * DHID * 64, 64,
                half ? C2 : C1, DHID, DHID, m0, h * 64);
}

__global__ __launch_bounds__(256) void k_gemm64d(const float* __restrict__ A1,
                                                 const float* __restrict__ A2,
                                                 const float* __restrict__ B,
                                                 float* __restrict__ C1,
                                                 float* __restrict__ C2) {
    int half = blockIdx.y >> 5;
    int m0 = (blockIdx.y & 31) * 128;
    gemm64_body(half ? A2 : A1, B + blockIdx.x * 64, DHID,
                half ? C2 : C1, DHID, DHID, m0, blockIdx.x * 64);
}

// rownorm: 256 threads, 8 rows/block
__global__ void k_rownorm(const float* __restrict__ Xf) {
    int row = blockIdx.x * 8 + (threadIdx.x >> 5);
    int lane = threadIdx.x & 31;
    const float4* r = (const float4*)&Xf[(size_t)row * DHID];
    float4 x0 = r[lane], x1 = r[lane + 32];
    float a = x0.x * x0.x + x0.y * x0.y + x0.z * x0.z + x0.w * x0.w
            + x1.x * x1.x + x1.y * x1.y + x1.z * x1.z + x1.w * x1.w;
    for (int o = 16; o; o >>= 1) a += __shfl_xor_sync(0xffffffffu, a, o);
    if (lane == 0) g_nrm[row] = sqrtf(a);
}

// density: 2-way unrolled neighbor dot products
__global__ void k_density(const float* __restrict__ Xf) {
    __shared__ float xs[DHID];
    __shared__ float ps[8];
    int i = blockIdx.x, t = threadIdx.x;
    xs[t] = Xf[(size_t)i * DHID + t];
    __syncthreads();
    int lane = t & 31, wp = t >> 5;
    const float4* xs4 = (const float4*)xs;
    float4 x0 = xs4[lane], x1 = xs4[lane + 32];
    const int* nbr = (const int*)g_dist + (size_t)i * NPTS;
    int n = g_ncnt[i];
    float ni = g_nrm[i], part = 0.f;
    for (int e0 = wp; e0 < n; e0 += 16) {
        int e1 = e0 + 8;
        bool have2 = (e1 < n);
        int j1 = nbr[e0];
        int j2 = have2 ? nbr[e1] : j1;
        const float4* r1 = (const float4*)&Xf[(size_t)j1 * DHID];
        const float4* r2 = (const float4*)&Xf[(size_t)j2 * DHID];
        float4 a0 = r1[lane], a1 = r1[lane + 32];
        float4 b0 = r2[lane], b1 = r2[lane + 32];
        float d1 = x0.x * a0.x + x0.y * a0.y + x0.z * a0.z + x0.w * a0.w
                 + x1.x * a1.x + x1.y * a1.y + x1.z * a1.z + x1.w * a1.w;
        float d2 = x0.x * b0.x + x0.y * b0.y + x0.z * b0.z + x0.w * b0.w
                 + x1.x * b1.x + x1.y * b1.y + x1.z * b1.z + x1.w * b1.w;
#pragma unroll
        for (int o = 16; o; o >>= 1) {
            d1 += __shfl_xor_sync(0xffffffffu, d1, o);
            d2 += __shfl_xor_sync(0xffffffffu, d2, o);
        }
        if (lane == 0) {
            float c1 = d1 / (ni * g_nrm[j1]);
            if (c1 > SIGMA_C) part += c1;
            if (have2) {
                float c2 = d2 / (ni * g_nrm[j2]);
                if (c2 > SIGMA_C) part += c2;
            }
        }
    }
    if (lane == 0) ps[wp] = part;
    __syncthreads();
    if (t == 0) {
        float a = 0.f;
        for (int q = 0; q < 8; q++) a += ps[q];
        g_rho[i] = a;
    }
}

// rhoe + fused maxima
__global__ void k_rhoe(int rslot, int reslot) {
    __shared__ float sm1[8], sm2[8];
    int e = blockIdx.x * 256 + threadIdx.x;
    float r = 0.f;
    for (int k = 0; k < KP1; k++) r += g_rho[g_idx[e * KP1 + k]];
    g_rhoe[e] = r;
    float rr = g_rho[e];
    for (int o = 16; o; o >>= 1) {
        r = fmaxf(r, __shfl_xor_sync(0xffffffffu, r, o));
        rr = fmaxf(rr, __shfl_xor_sync(0xffffffffu, rr, o));
    }
    int t = threadIdx.x;
    if ((t & 31) == 0) { sm1[t >> 5] = rr; sm2[t >> 5] = r; }
    __syncthreads();
    if (t == 0) {
        float m1 = sm1[0], m2 = sm2[0];
        for (int q = 1; q < 8; q++) { m1 = fmaxf(m1, sm1[q]); m2 = fmaxf(m2, sm2[q]); }
        atomicMax(&g_smax[rslot], encf(m1));
        atomicMax(&g_smax[reslot], encf(m2));
    }
}

// ---- s/t matvec bodies ----
__device__ __forceinline__ void svtv4_body(int vb, const float* __restrict__ Ms,
                                           const float* __restrict__ Mt,
                                           const float* __restrict__ av, int sb,
                                           float* sOut, float* tOut) {
    __shared__ float sm4[8];
    int w = vb * 8 + (threadIdx.x >> 5);
    int lane = threadIdx.x & 31;
    int row = w & (NPTS - 1);
    int g = w >> 12;
    int h = g & 3, which = g >> 2;
    const float* M = which ? Mt : Ms;
    const float2* a2 = (const float2*)(av + (size_t)h * 2 * DHEAD + which * DHEAD);
    const float2* r2 = (const float2*)(M + (size_t)row * DHID + h * DHEAD);
    float2 rv = r2[lane], av2 = a2[lane];
    float p = rv.x * av2.x + rv.y * av2.y;
    for (int o = 16; o; o >>= 1) p += __shfl_xor_sync(0xffffffffu, p, o);
    if (lane == 0) {
        (which ? tOut : sOut)[h * NPTS + row] = p;
        sm4[(threadIdx.x >> 5)] = p;
    }
    __syncthreads();
    if (threadIdx.x == 0) {
        float m = sm4[0];
        for (int q = 1; q < 8; q++) m = fmaxf(m, sm4[q]);
        atomicMax(&g_smax[sb + which * 4 + h], encf(m));
    }
}

__device__ __forceinline__ void svtv1_body(int vb, const float* __restrict__ Ms,
                                           const float* __restrict__ as,
                                           const float* __restrict__ Mt,
                                           const float* __restrict__ at, int sb,
                                           float* sOut, float* tOut) {
    __shared__ float sm1b[8];
    int w = vb * 8 + (threadIdx.x >> 5);
    int lane = threadIdx.x & 31;
    int row = w & (NPTS - 1);
    int which = w >> 12;
    const float* M = which ? Mt : Ms;
    const float* a = which ? at : as;
    const float4* r = (const float4*)(M + (size_t)row * DHID);
    const float4* a4 = (const float4*)a;
    float4 r0 = r[lane], r1 = r[lane + 32];
    float4 b0 = a4[lane], b1 = a4[lane + 32];
    float p = r0.x * b0.x + r0.y * b0.y + r0.z * b0.z + r0.w * b0.w
            + r1.x * b1.x + r1.y * b1.y + r1.z * b1.z + r1.w * b1.w;
    for (int o = 16; o; o >>= 1) p += __shfl_xor_sync(0xffffffffu, p, o);
    if (lane == 0) {
        (which ? tOut : sOut)[row] = p;
        sm1b[(threadIdx.x >> 5)] = p;
    }
    __syncthreads();
    if (threadIdx.x == 0) {
        float m = sm1b[0];
        for (int q = 1; q < 8; q++) m = fmaxf(m, sm1b[q]);
        atomicMax(&g_smax[sb + which], encf(m));
    }
}

__global__ void k_svtv4(const float* __restrict__ Ms, const float* __restrict__ Mt,
                        const float* __restrict__ av, int sb,
                        float* sOut, float* tOut) {
    svtv4_body(blockIdx.x, Ms, Mt, av, sb, sOut, tOut);
}

__global__ void k_svtv1(const float* __restrict__ Ms, const float* __restrict__ as,
                        const float* __restrict__ Mt, const float* __restrict__ at,
                        int sb, float* sOut, float* tOut) {
    svtv1_body(blockIdx.x, Ms, as, Mt, at, sb, sOut, tOut);
}

__device__ __forceinline__ float lrelu(float x) { return x > 0.f ? x : 0.2f * x; }
__device__ __forceinline__ float elu1(float x) { return x > 0.f ? x : expm1f(x); }

// attention body
template <int D>
__device__ __forceinline__ void att4_body(int vb, const float* __restrict__ rho, int rslot,
                                          const float* __restrict__ valb, int ldv,
                                          float* __restrict__ outb, int ldo, int hstride,
                                          const float* sBase, const float* tBase,
                                          int sb, int nh) {
    int task = vb * 8 + (threadIdx.x >> 5);
    int lane = threadIdx.x & 31;
    int row = task & (NPTS - 1);
    int h = task >> 12;
    const float* sA = sBase + h * NPTS;
    const float* tA = tBase + h * NPTS;
    float smx = decf(g_smax[sb + h]);
    float tmx = decf(g_smax[sb + nh + h]);
    float ax_max = lrelu(smx + tmx);
    float rt = rho[row] / decf(g_smax[rslot]) * ax_max;
    float si = sA[row];
    int beg = g_roff[row], end = g_roff[row + 1];
    int deg = end - beg;
    const float* val = valb + h * hstride;
    float* out = outb + h * hstride;
    const int C2 = D / 64;
    float2 acc[C2];
#pragma unroll
    for (int j = 0; j < C2; j++) acc[j] = make_float2(0.f, 0.f);
    float iz;
    if (deg <= 32) {
        int mye = (lane < deg) ? g_redge[beg + lane] : 0;
        float st = (lane < deg) ? (lrelu(si + tA[mye]) + rt) : -FLT_MAX;
        float m = st;
        for (int o = 16; o; o >>= 1) m = fmaxf(m, __shfl_xor_sync(0xffffffffu, m, o));
        float myw = (lane < deg) ? expf(st - m) : 0.f;
        float Z = myw;
        for (int o = 16; o; o >>= 1) Z += __shfl_xor_sync(0xffffffffu, Z, o);
        for (int k = 0; k < deg; k++) {
            int e = __shfl_sync(0xffffffffu, mye, k);
            float wt = __shfl_sync(0xffffffffu, myw, k);
            const float2* v2 = (const float2*)&val[(size_t)e * ldv];
#pragma unroll
            for (int j = 0; j < C2; j++) {
                float2 x = v2[lane + j * 32];
                acc[j].x += wt * x.x; acc[j].y += wt * x.y;
            }
        }
        iz = 1.f / Z;
    } else {
        float m = -FLT_MAX;
        for (int k = beg + lane; k < end; k += 32)
            m = fmaxf(m, lrelu(si + tA[g_redge[k]]) + rt);
        for (int o = 16; o; o >>= 1) m = fmaxf(m, __shfl_xor_sync(0xffffffffu, m, o));
        float Z = 0.f;
        for (int k = beg + lane; k < end; k += 32)
            Z += expf(lrelu(si + tA[g_redge[k]]) + rt - m);
        for (int o = 16; o; o >>= 1) Z += __shfl_xor_sync(0xffffffffu, Z, o);
        for (int k = beg; k < end; k++) {
            int e = g_redge[k];
            float wt = expf(lrelu(si + tA[e]) + rt - m);
            const float2* v2 = (const float2*)&val[(size_t)e * ldv];
#pragma unroll
            for (int j = 0; j < C2; j++) {
                float2 x = v2[lane + j * 32];
                acc[j].x += wt * x.x; acc[j].y += wt * x.y;
            }
        }
        iz = 1.f / Z;
    }
    float2* o2 = (float2*)&out[(size_t)row * ldo];
#pragma unroll
    for (int j = 0; j < C2; j++) {
        float2 r;
        r.x = elu1(acc[j].x * iz);
        r.y = elu1(acc[j].y * iz);
        o2[lane + j * 32] = r;
    }
}

template <int D>
__global__ void k_att4x(const float* __restrict__ rho, int rslot,
                        const float* __restrict__ valb, int ldv,
                        float* __restrict__ outb, int ldo, int hstride,
                        const float* sBase, const float* tBase, int sb, int nh) {
    att4_body<D>(blockIdx.x, rho, rslot, valb, ldv, outb, ldo, hstride, sBase, tBase, sb, nh);
}

// fused: att4<64> pass1 (2048 vblocks) || svtv4 pass2 (4096 vblocks)
__global__ void k_att1_svtv2(const float* __restrict__ rho,
                             const float* __restrict__ P,
                             const float* __restrict__ Q,
                             float* __restrict__ Enew,
                             const float* __restrict__ aeh,
                             const float* svh, const float* tvh,
                             float* svh2, float* tvh2) {
    int vb = blockIdx.x;
    if (vb < 2048)
        att4_body<DHEAD>(vb, rho, 20, P, DHID, Enew, DHID, DHEAD, svh, tvh, 0, 4);
    else
        svtv4_body(vb - 2048, Q, P, aeh, 8, svh2, tvh2);
}

// fused: att4<256> final pass1 (512 vblocks) || svtv1 pass2 (1024 vblocks)
__global__ void k_attf1_svtv2(const float* __restrict__ rho,
                              const float* __restrict__ P,
                              const float* __restrict__ Q,
                              float* __restrict__ Enew,
                              const float* __restrict__ ae2,
                              const float* svh, const float* tvh,
                              float* svh2, float* tvh2) {
    int vb = blockIdx.x;
    if (vb < 512)
        att4_body<DHID>(vb, rho, 22, P, DHID, Enew, DHID, 0, svh, tvh, 16, 1);
    else
        svtv1_body(vb - 512, Q, ae2, P, ae2 + DHID, 18, svh2, tvh2);
}

// ---------------- host orchestration ----------------
extern "C" void kernel_launch(void* const* d_in, const int* in_sizes, int n_in,
                              void* d_out, int out_size) {
    const float* X     = (const float*)d_in[0];
    const float* theta = (const float*)d_in[1];
    const float* Wh    = (const float*)d_in[2];
    const float* axh   = (const float*)d_in[3];
    const float* aeh   = (const float*)d_in[4];
    const float* W2    = (const float*)d_in[5];
    const float* ax2   = (const float*)d_in[6];
    const float* ae2   = (const float*)d_in[7];
    float* out = (float*)d_out;
    (void)in_sizes; (void)n_in; (void)out_size;

    void* vp;
    cudaGetSymbolAddress(&vp, g_XT);   float* XT   = (float*)vp;
    cudaGetSymbolAddress(&vp, g_Xe);   float* Xe   = (float*)vp;
    cudaGetSymbolAddress(&vp, g_E);    float* E    = (float*)vp;
    cudaGetSymbolAddress(&vp, g_rho);  float* rho  = (float*)vp;
    cudaGetSymbolAddress(&vp, g_rhoe); float* rhoe = (float*)vp;
    cudaGetSymbolAddress(&vp, g_P);    float* P    = (float*)vp;
    cudaGetSymbolAddress(&vp, g_Q);    float* Q    = (float*)vp;
    cudaGetSymbolAddress(&vp, g_Enew); float* Enew = (float*)vp;
    cudaGetSymbolAddress(&vp, g_Xcat); float* Xcat = (float*)vp;
    cudaGetSymbolAddress(&vp, g_svh);  float* svh  = (float*)vp;
    cudaGetSymbolAddress(&vp, g_tvh);  float* tvh  = (float*)vp;
    cudaGetSymbolAddress(&vp, g_svh2); float* svh2 = (float*)vp;
    cudaGetSymbolAddress(&vp, g_tvh2); float* tvh2 = (float*)vp;

    // profiled slot #4 = k_gemm64x
    k_rowsq<<<NPTS / 4, 128>>>(X);
    k_aat_dist_sym<<<528, 256>>>(X);
    k_topk_warp<<<512, 256>>>();
    k_gemm64x<<<dim3(4, 64), 256>>>(X, theta, XT, DIN, DHID);   // profiled

    k_scan<<<1, 1024>>>();
    k_fill<<<176, 256>>>();
    k_gedge_nbr<<<5120, 128>>>();
    k_gather_nodes<<<NPTS / 4, 128>>>();

    // densities (stage 1)
    k_density<<<NPTS, 256>>>(Xe);
    k_rhoe<<<16, 256>>>(20, 21);

    // all-head projections
    k_gemm64h2<<<dim3(4, 64), 256>>>(Xe, E, Wh, P, Q);

    // attention pass 1 s/t
    k_svtv4<<<4096, 256>>>(P, Q, axh, 0, svh, tvh);
    // fused: att pass1 || svtv pass2 (double-buffered)
    k_att1_svtv2<<<6144, 256>>>(rho, P, Q, Enew, aeh, svh, tvh, svh2, tvh2);
    // attention pass 2 (ldo = DHID)
    k_att4x<DHEAD><<<2048, 256>>>(rhoe, 21, Enew, DHID, Xcat, DHID, DHEAD, svh2, tvh2, 8, 4);

    // final DA-HGAN layer
    k_rownorm<<<NPTS / 8, 256>>>(Xcat);
    k_density<<<NPTS, 256>>>(Xcat);
    k_rhoe<<<16, 256>>>(22, 23);

    k_gemm64d<<<dim3(4, 64), 256>>>(Xcat, E, W2, P, Q);

    k_svtv1<<<1024, 256>>>(P, ax2, Q, ax2 + DHID, 16, svh, tvh);
    k_attf1_svtv2<<<1536, 256>>>(rho, P, Q, Enew, ae2, svh, tvh, svh2, tvh2);
    k_att4x<DHID><<<512, 256>>>(rhoe, 23, Enew, DHID, out, DHID, 0, svh2, tvh2, 18, 1);
}

// round 14
// speedup vs baseline: 1.1075x; 1.0455x over previous
#include <cuda_runtime.h>
#include <math.h>
#include <float.h>

// ---------------- problem constants ----------------
#define NPTS  4096
#define DIN   784
#define DHID  256
#define MH    4
#define DHEAD 64
#define KP1   11
#define SIGMA_C 0.1f
#define DE_C  0.30151134457776363f   // 1/sqrt(11)

// ---------------- device scratch ----------------
__device__ float g_dist[(size_t)NPTS * NPTS];  // 64MB; after topk reused as int nbr[4096][4096]
__device__ float g_sq[NPTS];
__device__ int   g_idx[NPTS * KP1];
__device__ int   g_deg[NPTS];
__device__ float g_dv[NPTS];
__device__ int   g_roff[NPTS + 1];
__device__ int   g_cursor[NPTS];
__device__ int   g_redge[NPTS * KP1];
__device__ int   g_ncnt[NPTS];
__device__ float g_XT[NPTS * DHID];
__device__ float g_Xe[NPTS * DHID];
__device__ float g_E[NPTS * DHID];
__device__ float g_nrm[NPTS];
__device__ float g_rho[NPTS];
__device__ float g_rhoe[NPTS];
__device__ float g_P[NPTS * DHID];
__device__ float g_Q[NPTS * DHID];
__device__ float g_svh[MH * NPTS];
__device__ float g_tvh[MH * NPTS];
__device__ float g_svh2[MH * NPTS];
__device__ float g_tvh2[MH * NPTS];
__device__ float g_Enew[NPTS * DHID];
__device__ float g_Xcat[NPTS * DHID];
__device__ unsigned g_smax[32];

__device__ __forceinline__ unsigned encf(float f) {
    unsigned u = __float_as_uint(f);
    return (u & 0x80000000u) ? ~u : (u | 0x80000000u);
}
__device__ __forceinline__ float decf(unsigned u) {
    return __uint_as_float((u & 0x80000000u) ? (u & 0x7fffffffu) : ~u);
}

// ---------------- rowsq + fused zero-init ----------------
__global__ void k_rowsq(const float* __restrict__ X) {
    int gid = blockIdx.x * 128 + threadIdx.x;
    if (gid < NPTS) g_deg[gid] = 0;
    if (gid < 32) g_smax[gid] = 0u;
    int row = blockIdx.x * 4 + (threadIdx.x >> 5);
    int lane = threadIdx.x & 31;
    const float4* r = (const float4*)&X[(size_t)row * DIN];
    float a = 0.f;
    for (int c = lane; c < DIN / 4; c += 32) {
        float4 v = r[c];
        a += v.x * v.x + v.y * v.y + v.z * v.z + v.w * v.w;
    }
    for (int o = 16; o; o >>= 1) a += __shfl_xor_sync(0xffffffffu, a, o);
    if (lane == 0) g_sq[row] = a;
}

// ---- symmetric dist GEMM: upper-tri 128x128 blocks, mirrored f4 writes ----
__global__ __launch_bounds__(256) void k_aat_dist_sym(const float* __restrict__ A) {
    __shared__ float As[2][16][128];
    __shared__ float Bs[2][16][128];
    int b = blockIdx.x, by = 0;
    while (b >= 32 - by) { b -= 32 - by; ++by; }
    int bx = by + b;
    int row0 = by * 128, col0 = bx * 128;
    int t = threadIdx.x;
    int ty = t >> 4, tx = t & 15;
    int ra = t >> 2, qa = (t & 3) * 4;

    float4 pa0, pa1, pb0, pb1;
    pa0 = *(const float4*)&A[(size_t)(row0 + ra) * DIN + qa];
    pa1 = *(const float4*)&A[(size_t)(row0 + ra + 64) * DIN + qa];
    pb0 = *(const float4*)&A[(size_t)(col0 + ra) * DIN + qa];
    pb1 = *(const float4*)&A[(size_t)(col0 + ra + 64) * DIN + qa];
    As[0][qa + 0][ra] = pa0.x; As[0][qa + 1][ra] = pa0.y; As[0][qa + 2][ra] = pa0.z; As[0][qa + 3][ra] = pa0.w;
    As[0][qa + 0][ra + 64] = pa1.x; As[0][qa + 1][ra + 64] = pa1.y; As[0][qa + 2][ra + 64] = pa1.z; As[0][qa + 3][ra + 64] = pa1.w;
    Bs[0][qa + 0][ra] = pb0.x; Bs[0][qa + 1][ra] = pb0.y; Bs[0][qa + 2][ra] = pb0.z; Bs[0][qa + 3][ra] = pb0.w;
    Bs[0][qa + 0][ra + 64] = pb1.x; Bs[0][qa + 1][ra + 64] = pb1.y; Bs[0][qa + 2][ra + 64] = pb1.z; Bs[0][qa + 3][ra + 64] = pb1.w;
    __syncthreads();

    float acc[8][8];
#pragma unroll
    for (int i = 0; i < 8; i++)
#pragma unroll
        for (int j = 0; j < 8; j++) acc[i][j] = 0.f;

    const int nIt = DIN / 16;
    for (int it = 0; it < nIt; ++it) {
        int k0n = (it + 1) * 16;
        if (it + 1 < nIt) {
            pa0 = *(const float4*)&A[(size_t)(row0 + ra) * DIN + k0n + qa];
            pa1 = *(const float4*)&A[(size_t)(row0 + ra + 64) * DIN + k0n + qa];
            pb0 = *(const float4*)&A[(size_t)(col0 + ra) * DIN + k0n + qa];
            pb1 = *(const float4*)&A[(size_t)(col0 + ra + 64) * DIN + k0n + qa];
        }
        int buf = it & 1;
#pragma unroll
        for (int kk = 0; kk < 16; ++kk) {
            float4 a0 = *(const float4*)&As[buf][kk][ty * 8];
            float4 a1 = *(const float4*)&As[buf][kk][ty * 8 + 4];
            float4 b0 = *(const float4*)&Bs[buf][kk][tx * 8];
            float4 b1 = *(const float4*)&Bs[buf][kk][tx * 8 + 4];
            float ar[8] = {a0.x, a0.y, a0.z, a0.w, a1.x, a1.y, a1.z, a1.w};
            float br[8] = {b0.x, b0.y, b0.z, b0.w, b1.x, b1.y, b1.z, b1.w};
#pragma unroll
            for (int i = 0; i < 8; i++)
#pragma unroll
                for (int j = 0; j < 8; j++) acc[i][j] += ar[i] * br[j];
        }
        if (it + 1 < nIt) {
            int nb = buf ^ 1;
            As[nb][qa + 0][ra] = pa0.x; As[nb][qa + 1][ra] = pa0.y; As[nb][qa + 2][ra] = pa0.z; As[nb][qa + 3][ra] = pa0.w;
            As[nb][qa + 0][ra + 64] = pa1.x; As[nb][qa + 1][ra + 64] = pa1.y; As[nb][qa + 2][ra + 64] = pa1.z; As[nb][qa + 3][ra + 64] = pa1.w;
            Bs[nb][qa + 0][ra] = pb0.x; Bs[nb][qa + 1][ra] = pb0.y; Bs[nb][qa + 2][ra] = pb0.z; Bs[nb][qa + 3][ra] = pb0.w;
            Bs[nb][qa + 0][ra + 64] = pb1.x; Bs[nb][qa + 1][ra + 64] = pb1.y; Bs[nb][qa + 2][ra + 64] = pb1.z; Bs[nb][qa + 3][ra + 64] = pb1.w;
        }
        __syncthreads();
    }

    float si_[8], sj_[8];
#pragma unroll
    for (int i = 0; i < 8; i++) si_[i] = g_sq[row0 + ty * 8 + i];
#pragma unroll
    for (int j = 0; j < 8; j++) sj_[j] = g_sq[col0 + tx * 8 + j];

#pragma unroll
    for (int i = 0; i < 8; i++) {
        int gi = row0 + ty * 8 + i;
        float4 w0, w1;
        w0.x = fabsf(si_[i] + sj_[0] - 2.f * acc[i][0]);
        w0.y = fabsf(si_[i] + sj_[1] - 2.f * acc[i][1]);
        w0.z = fabsf(si_[i] + sj_[2] - 2.f * acc[i][2]);
        w0.w = fabsf(si_[i] + sj_[3] - 2.f * acc[i][3]);
        w1.x = fabsf(si_[i] + sj_[4] - 2.f * acc[i][4]);
        w1.y = fabsf(si_[i] + sj_[5] - 2.f * acc[i][5]);
        w1.z = fabsf(si_[i] + sj_[6] - 2.f * acc[i][6]);
        w1.w = fabsf(si_[i] + sj_[7] - 2.f * acc[i][7]);
        *(float4*)&g_dist[(size_t)gi * NPTS + col0 + tx * 8] = w0;
        *(float4*)&g_dist[(size_t)gi * NPTS + col0 + tx * 8 + 4] = w1;
    }
#pragma unroll
    for (int j = 0; j < 8; j++) {
        int gj = col0 + tx * 8 + j;
        float4 w0, w1;
        w0.x = fabsf(si_[0] + sj_[j] - 2.f * acc[0][j]);
        w0.y = fabsf(si_[1] + sj_[j] - 2.f * acc[1][j]);
        w0.z = fabsf(si_[2] + sj_[j] - 2.f * acc[2][j]);
        w0.w = fabsf(si_[3] + sj_[j] - 2.f * acc[3][j]);
        w1.x = fabsf(si_[4] + sj_[j] - 2.f * acc[4][j]);
        w1.y = fabsf(si_[5] + sj_[j] - 2.f * acc[5][j]);
        w1.z = fabsf(si_[6] + sj_[j] - 2.f * acc[6][j]);
        w1.w = fabsf(si_[7] + sj_[j] - 2.f * acc[7][j]);
        *(float4*)&g_dist[(size_t)gj * NPTS + row0 + ty * 8] = w0;
        *(float4*)&g_dist[(size_t)gj * NPTS + row0 + ty * 8 + 4] = w1;
    }
}

// ---- topk + XT-GEMM fused kernel ----
__device__ __forceinline__ bool pless(float av, int ai, float bv, int bi) {
    return av < bv || (av == bv && ai < bi);
}

__device__ __forceinline__ void topk_body(int vb) {
    int row = vb * 8 + (threadIdx.x >> 5);
    int lane = threadIdx.x & 31;
    const float4* drow = (const float4*)&g_dist[(size_t)row * NPTS];
    float lv[KP1]; int li[KP1];
#pragma unroll
    for (int q = 0; q < KP1; q++) { lv[q] = FLT_MAX; li[q] = 0x7fffffff; }
#pragma unroll 2
    for (int s = 0; s < 32; s++) {
        int p4 = s * 32 + lane;
        float4 v4 = drow[p4];
        float vv[4] = {v4.x, v4.y, v4.z, v4.w};
        int jb = p4 * 4;
#pragma unroll
        for (int c = 0; c < 4; c++) {
            float v = vv[c]; int j = jb + c;
            if (pless(v, j, lv[KP1 - 1], li[KP1 - 1])) {
                lv[KP1 - 1] = v; li[KP1 - 1] = j;
#pragma unroll
                for (int q = KP1 - 1; q > 0; q--) {
                    if (pless(lv[q], li[q], lv[q - 1], li[q - 1])) {
                        float tv_ = lv[q]; lv[q] = lv[q - 1]; lv[q - 1] = tv_;
                        int ti_ = li[q]; li[q] = li[q - 1]; li[q - 1] = ti_;
                    }
                }
            }
        }
    }
    for (int it = 0; it < KP1; ++it) {
        float v = lv[0]; int ix = li[0];
#pragma unroll
        for (int o = 16; o; o >>= 1) {
            float ov = __shfl_xor_sync(0xffffffffu, v, o);
            int oi = __shfl_xor_sync(0xffffffffu, ix, o);
            if (pless(ov, oi, v, ix)) { v = ov; ix = oi; }
        }
        if (li[0] == ix) {
#pragma unroll
            for (int q = 0; q < KP1 - 1; q++) { lv[q] = lv[q + 1]; li[q] = li[q + 1]; }
            lv[KP1 - 1] = FLT_MAX; li[KP1 - 1] = 0x7fffffff;
        }
        if (lane == 0) {
            g_idx[row * KP1 + it] = ix;
            atomicAdd(&g_deg[ix], 1);
        }
    }
}

// 64x64 GEMM body (shared smem union with topk — topk uses none)
__device__ __forceinline__ void gemm64x_body(int bx, int by, const float* __restrict__ A,
                                             const float* __restrict__ B,
                                             float* __restrict__ C, int K, int Np) {
    __shared__ float As[2][16][64];
    __shared__ float Bs[2][16][64];
    int t = threadIdx.x;
    int m0 = by * 64, n0 = bx * 64;
    int ty = t >> 4, tx = t & 15;
    int ra = t >> 2, qa = (t & 3) * 4;
    int kb = t >> 4, cb = (t & 15) * 4;

    float4 pa, pb;
    pa = *(const float4*)&A[(size_t)(m0 + ra) * K + qa];
    pb = *(const float4*)&B[(size_t)kb * Np + n0 + cb];
    As[0][qa + 0][ra] = pa.x; As[0][qa + 1][ra] = pa.y; As[0][qa + 2][ra] = pa.z; As[0][qa + 3][ra] = pa.w;
    *(float4*)&Bs[0][kb][cb] = pb;
    __syncthreads();

    float acc[4][4];
#pragma unroll
    for (int i = 0; i < 4; i++)
#pragma unroll
        for (int j = 0; j < 4; j++) acc[i][j] = 0.f;

    int nIt = K / 16;
    for (int it = 0; it < nIt; ++it) {
        int k0n = (it + 1) * 16;
        if (it + 1 < nIt) {
            pa = *(const float4*)&A[(size_t)(m0 + ra) * K + k0n + qa];
            pb = *(const float4*)&B[(size_t)(k0n + kb) * Np + n0 + cb];
        }
        int buf = it & 1;
#pragma unroll
        for (int kk = 0; kk < 16; ++kk) {
            float4 a0 = *(const float4*)&As[buf][kk][ty * 4];
            float4 b0 = *(const float4*)&Bs[buf][kk][tx * 4];
            float ar[4] = {a0.x, a0.y, a0.z, a0.w};
            float br[4] = {b0.x, b0.y, b0.z, b0.w};
#pragma unroll
            for (int i = 0; i < 4; i++)
#pragma unroll
                for (int j = 0; j < 4; j++) acc[i][j] += ar[i] * br[j];
        }
        if (it + 1 < nIt) {
            int nb = buf ^ 1;
            As[nb][qa + 0][ra] = pa.x; As[nb][qa + 1][ra] = pa.y; As[nb][qa + 2][ra] = pa.z; As[nb][qa + 3][ra] = pa.w;
            *(float4*)&Bs[nb][kb][cb] = pb;
        }
        __syncthreads();
    }
#pragma unroll
    for (int i = 0; i < 4; i++) {
        float4 w0 = {acc[i][0], acc[i][1], acc[i][2], acc[i][3]};
        *(float4*)&C[(size_t)(m0 + ty * 4 + i) * Np + n0 + tx * 4] = w0;
    }
}

// fused: gemm64x (256 vblocks, scheduled first) || topk (512 vblocks)
__global__ __launch_bounds__(256) void k_topk_gemm(const float* __restrict__ X,
                                                   const float* __restrict__ theta,
                                                   float* __restrict__ XT) {
    if (blockIdx.x < 256)
        gemm64x_body(blockIdx.x & 3, blockIdx.x >> 2, X, theta, XT, DIN, DHID);
    else
        topk_body(blockIdx.x - 256);
}

// ---- scan only (1 block): prefix + dv + cursor ----
__global__ void k_scan() {
    __shared__ int s[1024];
    int t = threadIdx.x;
    int base = t * 4;
    int v0 = g_deg[base], v1 = g_deg[base + 1], v2 = g_deg[base + 2], v3 = g_deg[base + 3];
    int sum = v0 + v1 + v2 + v3;
    s[t] = sum;
    __syncthreads();
    for (int off = 1; off < 1024; off <<= 1) {
        int x = (t >= off) ? s[t - off] : 0;
        __syncthreads();
        s[t] += x;
        __syncthreads();
    }
    int run = s[t] - sum;
    g_roff[base] = run; g_cursor[base] = run; g_dv[base] = rsqrtf((float)v0); run += v0;
    g_roff[base + 1] = run; g_cursor[base + 1] = run; g_dv[base + 1] = rsqrtf((float)v1); run += v1;
    g_roff[base + 2] = run; g_cursor[base + 2] = run; g_dv[base + 2] = rsqrtf((float)v2); run += v2;
    g_roff[base + 3] = run; g_cursor[base + 3] = run; g_dv[base + 3] = rsqrtf((float)v3); run += v3;
    if (t == 1023) g_roff[NPTS] = run;
}

// ---- multi-block CSR fill ----
__global__ void k_fill() {
    int p = blockIdx.x * 256 + threadIdx.x;
    int i = g_idx[p];
    int pos = atomicAdd(&g_cursor[i], 1);
    g_redge[pos] = p / KP1;
}

// ---- gather_edges and nbr bodies ----
__device__ __forceinline__ void gather_edges_body(int vb, int t) {
    int e = vb * 4 + (t >> 5);
    int lane = t & 31;
    float4 a0 = {0, 0, 0, 0}, a1 = {0, 0, 0, 0};
    for (int k = 0; k < KP1; k++) {
        int i = g_idx[e * KP1 + k];
        float w = g_dv[i];
        const float4* r = (const float4*)&g_XT[(size_t)i * DHID];
        float4 x0 = r[lane], x1 = r[lane + 32];
        a0.x += w * x0.x; a0.y += w * x0.y; a0.z += w * x0.z; a0.w += w * x0.w;
        a1.x += w * x1.x; a1.y += w * x1.y; a1.z += w * x1.z; a1.w += w * x1.w;
    }
    a0.x *= DE_C; a0.y *= DE_C; a0.z *= DE_C; a0.w *= DE_C;
    a1.x *= DE_C; a1.y *= DE_C; a1.z *= DE_C; a1.w *= DE_C;
    float4* o = (float4*)&g_Xe[(size_t)e * DHID];
    o[lane] = a0; o[lane + 32] = a1;
    float nq = a0.x * a0.x + a0.y * a0.y + a0.z * a0.z + a0.w * a0.w
             + a1.x * a1.x + a1.y * a1.y + a1.z * a1.z + a1.w * a1.w;
    for (int of = 16; of; of >>= 1) nq += __shfl_xor_sync(0xffffffffu, nq, of);
    if (lane == 0) g_nrm[e] = sqrtf(nq);
}

__device__ __forceinline__ void nbr_body(int i, int t) {
    __shared__ unsigned bm[128];
    __shared__ int wsum[4];
    bm[t] = 0u;
    __syncthreads();
    int beg = g_roff[i];
    int cnt = (g_roff[i + 1] - beg) * KP1;
    for (int p = t; p < cnt; p += 128) {
        int e = g_redge[beg + p / KP1];
        int m = g_idx[e * KP1 + p % KP1];
        atomicOr(&bm[m >> 5], 1u << (m & 31));
    }
    __syncthreads();
    if (t == 0) bm[i >> 5] &= ~(1u << (i & 31));
    __syncthreads();
    unsigned w = bm[t];
    int pc = __popc(w);
    int lane = t & 31, wid = t >> 5;
    int sc = pc;
    for (int o = 1; o < 32; o <<= 1) {
        int x = __shfl_up_sync(0xffffffffu, sc, o);
        if (lane >= o) sc += x;
    }
    if (lane == 31) wsum[wid] = sc;
    __syncthreads();
    int woff = 0;
    for (int q = 0; q < wid; q++) woff += wsum[q];
    int off = woff + sc - pc;
    int* nbr = (int*)g_dist + (size_t)i * NPTS;
    while (w) {
        int b = __ffs(w) - 1; w &= w - 1;
        nbr[off++] = t * 32 + b;
    }
    if (t == 127) g_ncnt[i] = woff + sc;
}

// fused: gather_edges (1024 vblocks) || nbr (4096 vblocks); 128 threads
__global__ void k_gedge_nbr() {
    if (blockIdx.x < 1024) gather_edges_body(blockIdx.x, threadIdx.x);
    else nbr_body(blockIdx.x - 1024, threadIdx.x);
}

// gather_nodes body: 256 threads, 8 nodes/vblock
__device__ __forceinline__ void gather_nodes_body(int vb, int t) {
    int i = vb * 8 + (t >> 5);
    int lane = t & 31;
    int beg = g_roff[i], end = g_roff[i + 1];
    float4 a0 = {0, 0, 0, 0}, a1 = {0, 0, 0, 0};
    for (int k = beg; k < end; k++) {
        const float4* r = (const float4*)&g_Xe[(size_t)g_redge[k] * DHID];
        float4 x0 = r[lane], x1 = r[lane + 32];
        a0.x += x0.x; a0.y += x0.y; a0.z += x0.z; a0.w += x0.w;
        a1.x += x1.x; a1.y += x1.y; a1.z += x1.z; a1.w += x1.w;
    }
    float s = g_dv[i] * DE_C;
    a0.x *= s; a0.y *= s; a0.z *= s; a0.w *= s;
    a1.x *= s; a1.y *= s; a1.z *= s; a1.w *= s;
    float4* o = (float4*)&g_E[(size_t)i * DHID];
    o[lane] = a0; o[lane + 32] = a1;
}

// density body: 2-way unrolled neighbor dot products (256 threads)
__device__ __forceinline__ void density_body(int i, int t, const float* __restrict__ Xf) {
    __shared__ float xs[DHID];
    __shared__ float ps[8];
    xs[t] = Xf[(size_t)i * DHID + t];
    __syncthreads();
    int lane = t & 31, wp = t >> 5;
    const float4* xs4 = (const float4*)xs;
    float4 x0 = xs4[lane], x1 = xs4[lane + 32];
    const int* nbr = (const int*)g_dist + (size_t)i * NPTS;
    int n = g_ncnt[i];
    float ni = g_nrm[i], part = 0.f;
    for (int e0 = wp; e0 < n; e0 += 16) {
        int e1 = e0 + 8;
        bool have2 = (e1 < n);
        int j1 = nbr[e0];
        int j2 = have2 ? nbr[e1] : j1;
        const float4* r1 = (const float4*)&Xf[(size_t)j1 * DHID];
        const float4* r2 = (const float4*)&Xf[(size_t)j2 * DHID];
        float4 a0 = r1[lane], a1 = r1[lane + 32];
        float4 b0 = r2[lane], b1 = r2[lane + 32];
        float d1 = x0.x * a0.x + x0.y * a0.y + x0.z * a0.z + x0.w * a0.w
                 + x1.x * a1.x + x1.y * a1.y + x1.z * a1.z + x1.w * a1.w;
        float d2 = x0.x * b0.x + x0.y * b0.y + x0.z * b0.z + x0.w * b0.w
                 + x1.x * b1.x + x1.y * b1.y + x1.z * b1.z + x1.w * b1.w;
#pragma unroll
        for (int o = 16; o; o >>= 1) {
            d1 += __shfl_xor_sync(0xffffffffu, d1, o);
            d2 += __shfl_xor_sync(0xffffffffu, d2, o);
        }
        if (lane == 0) {
            float c1 = d1 / (ni * g_nrm[j1]);
            if (c1 > SIGMA_C) part += c1;
            if (have2) {
                float c2 = d2 / (ni * g_nrm[j2]);
                if (c2 > SIGMA_C) part += c2;
            }
        }
    }
    if (lane == 0) ps[wp] = part;
    __syncthreads();
    if (t == 0) {
        float a = 0.f;
        for (int q = 0; q < 8; q++) a += ps[q];
        g_rho[i] = a;
    }
}

// fused: gather_nodes (512 vblocks) || density stage1 (4096 vblocks)
__global__ void k_gnodes_density(const float* __restrict__ Xe) {
    if (blockIdx.x < 512) gather_nodes_body(blockIdx.x, threadIdx.x);
    else density_body(blockIdx.x - 512, threadIdx.x, Xe);
}

// standalone density (for stage 2)
__global__ void k_density(const float* __restrict__ Xf) {
    density_body(blockIdx.x, threadIdx.x, Xf);
}

// ---- 128x64 GEMM body ----
__device__ __forceinline__ void gemm64_body(const float* __restrict__ A,
                                            const float* __restrict__ B, int ldb,
                                            float* __restrict__ C, int ldc,
                                            int K, int m0, int n0b) {
    __shared__ float As[2][16][128];
    __shared__ float Bs[2][16][64];
    int t = threadIdx.x;
    int ty = t >> 4, tx = t & 15;
    int ra = t >> 1, qa = (t & 1) * 8;
    int kb = t >> 4, cb = (t & 15) * 4;

    float4 pa0, pa1, pb;
    pa0 = *(const float4*)&A[(size_t)(m0 + ra) * K + qa];
    pa1 = *(const float4*)&A[(size_t)(m0 + ra) * K + qa + 4];
    pb = *(const float4*)&B[(size_t)kb * ldb + cb];
    As[0][qa + 0][ra] = pa0.x; As[0][qa + 1][ra] = pa0.y; As[0][qa + 2][ra] = pa0.z; As[0][qa + 3][ra] = pa0.w;
    As[0][qa + 4][ra] = pa1.x; As[0][qa + 5][ra] = pa1.y; As[0][qa + 6][ra] = pa1.z; As[0][qa + 7][ra] = pa1.w;
    *(float4*)&Bs[0][kb][cb] = pb;
    __syncthreads();

    float acc[8][4];
#pragma unroll
    for (int i = 0; i < 8; i++)
#pragma unroll
        for (int j = 0; j < 4; j++) acc[i][j] = 0.f;

    int nIt = K / 16;
    for (int it = 0; it < nIt; ++it) {
        int k0n = (it + 1) * 16;
        if (it + 1 < nIt) {
            pa0 = *(const float4*)&A[(size_t)(m0 + ra) * K + k0n + qa];
            pa1 = *(const float4*)&A[(size_t)(m0 + ra) * K + k0n + qa + 4];
            pb = *(const float4*)&B[(size_t)(k0n + kb) * ldb + cb];
        }
        int buf = it & 1;
#pragma unroll
        for (int kk = 0; kk < 16; ++kk) {
            float4 a0 = *(const float4*)&As[buf][kk][ty * 8];
            float4 a1 = *(const float4*)&As[buf][kk][ty * 8 + 4];
            float4 b0 = *(const float4*)&Bs[buf][kk][tx * 4];
            float ar[8] = {a0.x, a0.y, a0.z, a0.w, a1.x, a1.y, a1.z, a1.w};
            float br[4] = {b0.x, b0.y, b0.z, b0.w};
#pragma unroll
            for (int i = 0; i < 8; i++)
#pragma unroll
                for (int j = 0; j < 4; j++) acc[i][j] += ar[i] * br[j];
        }
        if (it + 1 < nIt) {
            int nb = buf ^ 1;
            As[nb][qa + 0][ra] = pa0.x; As[nb][qa + 1][ra] = pa0.y; As[nb][qa + 2][ra] = pa0.z; As[nb][qa + 3][ra] = pa0.w;
            As[nb][qa + 4][ra] = pa1.x; As[nb][qa + 5][ra] = pa1.y; As[nb][qa + 6][ra] = pa1.z; As[nb][qa + 7][ra] = pa1.w;
            *(float4*)&Bs[nb][kb][cb] = pb;
        }
        __syncthreads();
    }
#pragma unroll
    for (int i = 0; i < 8; i++) {
        float4 w0 = {acc[i][0], acc[i][1], acc[i][2], acc[i][3]};
        *(float4*)&C[(size_t)(m0 + ty * 8 + i) * ldc + n0b + tx * 4] = w0;
    }
}

__global__ __launch_bounds__(256) void k_gemm64h2(const float* __restrict__ A1,
                                                  const float* __restrict__ A2,
                                                  const float* __restrict__ Wh,
                                                  float* __restrict__ C1,
                                                  float* __restrict__ C2) {
    int half = blockIdx.y >> 5;
    int m0 = (blockIdx.y & 31) * 128;
    int h = blockIdx.x;
    gemm64_body(half ? A2 : A1, Wh + (size_t)h * DHID * 64, 64,
                half ? C2 : C1, DHID, DHID, m0, h * 64);
}

__global__ __launch_bounds__(256) void k_gemm64d(const float* __restrict__ A1,
                                                 const float* __restrict__ A2,
                                                 const float* __restrict__ B,
                                                 float* __restrict__ C1,
                                                 float* __restrict__ C2) {
    int half = blockIdx.y >> 5;
    int m0 = (blockIdx.y & 31) * 128;
    gemm64_body(half ? A2 : A1, B + blockIdx.x * 64, DHID,
                half ? C2 : C1, DHID, DHID, m0, blockIdx.x * 64);
}

// rownorm: 256 threads, 8 rows/block
__global__ void k_rownorm(const float* __restrict__ Xf) {
    int row = blockIdx.x * 8 + (threadIdx.x >> 5);
    int lane = threadIdx.x & 31;
    const float4* r = (const float4*)&Xf[(size_t)row * DHID];
    float4 x0 = r[lane], x1 = r[lane + 32];
    float a = x0.x * x0.x + x0.y * x0.y + x0.z * x0.z + x0.w * x0.w
            + x1.x * x1.x + x1.y * x1.y + x1.z * x1.z + x1.w * x1.w;
    for (int o = 16; o; o >>= 1) a += __shfl_xor_sync(0xffffffffu, a, o);
    if (lane == 0) g_nrm[row] = sqrtf(a);
}

// rhoe + fused maxima
__global__ void k_rhoe(int rslot, int reslot) {
    __shared__ float sm1[8], sm2[8];
    int e = blockIdx.x * 256 + threadIdx.x;
    float r = 0.f;
    for (int k = 0; k < KP1; k++) r += g_rho[g_idx[e * KP1 + k]];
    g_rhoe[e] = r;
    float rr = g_rho[e];
    for (int o = 16; o; o >>= 1) {
        r = fmaxf(r, __shfl_xor_sync(0xffffffffu, r, o));
        rr = fmaxf(rr, __shfl_xor_sync(0xffffffffu, rr, o));
    }
    int t = threadIdx.x;
    if ((t & 31) == 0) { sm1[t >> 5] = rr; sm2[t >> 5] = r; }
    __syncthreads();
    if (t == 0) {
        float m1 = sm1[0], m2 = sm2[0];
        for (int q = 1; q < 8; q++) { m1 = fmaxf(m1, sm1[q]); m2 = fmaxf(m2, sm2[q]); }
        atomicMax(&g_smax[rslot], encf(m1));
        atomicMax(&g_smax[reslot], encf(m2));
    }
}

// ---- s/t matvec bodies ----
__device__ __forceinline__ void svtv4_body(int vb, const float* __restrict__ Ms,
                                           const float* __restrict__ Mt,
                                           const float* __restrict__ av, int sb,
                                           float* sOut, float* tOut) {
    __shared__ float sm4[8];
    int w = vb * 8 + (threadIdx.x >> 5);
    int lane = threadIdx.x & 31;
    int row = w & (NPTS - 1);
    int g = w >> 12;
    int h = g & 3, which = g >> 2;
    const float* M = which ? Mt : Ms;
    const float2* a2 = (const float2*)(av + (size_t)h * 2 * DHEAD + which * DHEAD);
    const float2* r2 = (const float2*)(M + (size_t)row * DHID + h * DHEAD);
    float2 rv = r2[lane], av2 = a2[lane];
    float p = rv.x * av2.x + rv.y * av2.y;
    for (int o = 16; o; o >>= 1) p += __shfl_xor_sync(0xffffffffu, p, o);
    if (lane == 0) {
        (which ? tOut : sOut)[h * NPTS + row] = p;
        sm4[(threadIdx.x >> 5)] = p;
    }
    __syncthreads();
    if (threadIdx.x == 0) {
        float m = sm4[0];
        for (int q = 1; q < 8; q++) m = fmaxf(m, sm4[q]);
        atomicMax(&g_smax[sb + which * 4 + h], encf(m));
    }
}

__device__ __forceinline__ void svtv1_body(int vb, const float* __restrict__ Ms,
                                           const float* __restrict__ as,
                                           const float* __restrict__ Mt,
                                           const float* __restrict__ at, int sb,
                                           float* sOut, float* tOut) {
    __shared__ float sm1b[8];
    int w = vb * 8 + (threadIdx.x >> 5);
    int lane = threadIdx.x & 31;
    int row = w & (NPTS - 1);
    int which = w >> 12;
    const float* M = which ? Mt : Ms;
    const float* a = which ? at : as;
    const float4* r = (const float4*)(M + (size_t)row * DHID);
    const float4* a4 = (const float4*)a;
    float4 r0 = r[lane], r1 = r[lane + 32];
    float4 b0 = a4[lane], b1 = a4[lane + 32];
    float p = r0.x * b0.x + r0.y * b0.y + r0.z * b0.z + r0.w * b0.w
            + r1.x * b1.x + r1.y * b1.y + r1.z * b1.z + r1.w * b1.w;
    for (int o = 16; o; o >>= 1) p += __shfl_xor_sync(0xffffffffu, p, o);
    if (lane == 0) {
        (which ? tOut : sOut)[row] = p;
        sm1b[(threadIdx.x >> 5)] = p;
    }
    __syncthreads();
    if (threadIdx.x == 0) {
        float m = sm1b[0];
        for (int q = 1; q < 8; q++) m = fmaxf(m, sm1b[q]);
        atomicMax(&g_smax[sb + which], encf(m));
    }
}

__global__ void k_svtv4(const float* __restrict__ Ms, const float* __restrict__ Mt,
                        const float* __restrict__ av, int sb,
                        float* sOut, float* tOut) {
    svtv4_body(blockIdx.x, Ms, Mt, av, sb, sOut, tOut);
}

__global__ void k_svtv1(const float* __restrict__ Ms, const float* __restrict__ as,
                        const float* __restrict__ Mt, const float* __restrict__ at,
                        int sb, float* sOut, float* tOut) {
    svtv1_body(blockIdx.x, Ms, as, Mt, at, sb, sOut, tOut);
}

__device__ __forceinline__ float lrelu(float x) { return x > 0.f ? x : 0.2f * x; }
__device__ __forceinline__ float elu1(float x) { return x > 0.f ? x : expm1f(x); }

// attention body
template <int D>
__device__ __forceinline__ void att4_body(int vb, const float* __restrict__ rho, int rslot,
                                          const float* __restrict__ valb, int ldv,
                                          float* __restrict__ outb, int ldo, int hstride,
                                          const float* sBase, const float* tBase,
                                          int sb, int nh) {
    int task = vb * 8 + (threadIdx.x >> 5);
    int lane = threadIdx.x & 31;
    int row = task & (NPTS - 1);
    int h = task >> 12;
    const float* sA = sBase + h * NPTS;
    const float* tA = tBase + h * NPTS;
    float smx = decf(g_smax[sb + h]);
    float tmx = decf(g_smax[sb + nh + h]);
    float ax_max = lrelu(smx + tmx);
    float rt = rho[row] / decf(g_smax[rslot]) * ax_max;
    float si = sA[row];
    int beg = g_roff[row], end = g_roff[row + 1];
    int deg = end - beg;
    const float* val = valb + h * hstride;
    float* out = outb + h * hstride;
    const int C2 = D / 64;
    float2 acc[C2];
#pragma unroll
    for (int j = 0; j < C2; j++) acc[j] = make_float2(0.f, 0.f);
    float iz;
    if (deg <= 32) {
        int mye = (lane < deg) ? g_redge[beg + lane] : 0;
        float st = (lane < deg) ? (lrelu(si + tA[mye]) + rt) : -FLT_MAX;
        float m = st;
        for (int o = 16; o; o >>= 1) m = fmaxf(m, __shfl_xor_sync(0xffffffffu, m, o));
        float myw = (lane < deg) ? expf(st - m) : 0.f;
        float Z = myw;
        for (int o = 16; o; o >>= 1) Z += __shfl_xor_sync(0xffffffffu, Z, o);
        for (int k = 0; k < deg; k++) {
            int e = __shfl_sync(0xffffffffu, mye, k);
            float wt = __shfl_sync(0xffffffffu, myw, k);
            const float2* v2 = (const float2*)&val[(size_t)e * ldv];
#pragma unroll
            for (int j = 0; j < C2; j++) {
                float2 x = v2[lane + j * 32];
                acc[j].x += wt * x.x; acc[j].y += wt * x.y;
            }
        }
        iz = 1.f / Z;
    } else {
        float m = -FLT_MAX;
        for (int k = beg + lane; k < end; k += 32)
            m = fmaxf(m, lrelu(si + tA[g_redge[k]]) + rt);
        for (int o = 16; o; o >>= 1) m = fmaxf(m, __shfl_xor_sync(0xffffffffu, m, o));
        float Z = 0.f;
        for (int k = beg + lane; k < end; k += 32)
            Z += expf(lrelu(si + tA[g_redge[k]]) + rt - m);
        for (int o = 16; o; o >>= 1) Z += __shfl_xor_sync(0xffffffffu, Z, o);
        for (int k = beg; k < end; k++) {
            int e = g_redge[k];
            float wt = expf(lrelu(si + tA[e]) + rt - m);
            const float2* v2 = (const float2*)&val[(size_t)e * ldv];
#pragma unroll
            for (int j = 0; j < C2; j++) {
                float2 x = v2[lane + j * 32];
                acc[j].x += wt * x.x; acc[j].y += wt * x.y;
            }
        }
        iz = 1.f / Z;
    }
    float2* o2 = (float2*)&out[(size_t)row * ldo];
#pragma unroll
    for (int j = 0; j < C2; j++) {
        float2 r;
        r.x = elu1(acc[j].x * iz);
        r.y = elu1(acc[j].y * iz);
        o2[lane + j * 32] = r;
    }
}

template <int D>
__global__ void k_att4x(const float* __restrict__ rho, int rslot,
                        const float* __restrict__ valb, int ldv,
                        float* __restrict__ outb, int ldo, int hstride,
                        const float* sBase, const float* tBase, int sb, int nh) {
    att4_body<D>(blockIdx.x, rho, rslot, valb, ldv, outb, ldo, hstride, sBase, tBase, sb, nh);
}

// fused: att4<64> pass1 (2048 vblocks) || svtv4 pass2 (4096 vblocks)
__global__ void k_att1_svtv2(const float* __restrict__ rho,
                             const float* __restrict__ P,
                             const float* __restrict__ Q,
                             float* __restrict__ Enew,
                             const float* __restrict__ aeh,
                             const float* svh, const float* tvh,
                             float* svh2, float* tvh2) {
    int vb = blockIdx.x;
    if (vb < 2048)
        att4_body<DHEAD>(vb, rho, 20, P, DHID, Enew, DHID, DHEAD, svh, tvh, 0, 4);
    else
        svtv4_body(vb - 2048, Q, P, aeh, 8, svh2, tvh2);
}

// fused: att4<256> final pass1 (512 vblocks) || svtv1 pass2 (1024 vblocks)
__global__ void k_attf1_svtv2(const float* __restrict__ rho,
                              const float* __restrict__ P,
                              const float* __restrict__ Q,
                              float* __restrict__ Enew,
                              const float* __restrict__ ae2,
                              const float* svh, const float* tvh,
                              float* svh2, float* tvh2) {
    int vb = blockIdx.x;
    if (vb < 512)
        att4_body<DHID>(vb, rho, 22, P, DHID, Enew, DHID, 0, svh, tvh, 16, 1);
    else
        svtv1_body(vb - 512, Q, ae2, P, ae2 + DHID, 18, svh2, tvh2);
}

// ---------------- host orchestration ----------------
extern "C" void kernel_launch(void* const* d_in, const int* in_sizes, int n_in,
                              void* d_out, int out_size) {
    const float* X     = (const float*)d_in[0];
    const float* theta = (const float*)d_in[1];
    const float* Wh    = (const float*)d_in[2];
    const float* axh   = (const float*)d_in[3];
    const float* aeh   = (const float*)d_in[4];
    const float* W2    = (const float*)d_in[5];
    const float* ax2   = (const float*)d_in[6];
    const float* ae2   = (const float*)d_in[7];
    float* out = (float*)d_out;
    (void)in_sizes; (void)n_in; (void)out_size;

    void* vp;
    cudaGetSymbolAddress(&vp, g_XT);   float* XT   = (float*)vp;
    cudaGetSymbolAddress(&vp, g_Xe);   float* Xe   = (float*)vp;
    cudaGetSymbolAddress(&vp, g_E);    float* E    = (float*)vp;
    cudaGetSymbolAddress(&vp, g_rho);  float* rho  = (float*)vp;
    cudaGetSymbolAddress(&vp, g_rhoe); float* rhoe = (float*)vp;
    cudaGetSymbolAddress(&vp, g_P);    float* P    = (float*)vp;
    cudaGetSymbolAddress(&vp, g_Q);    float* Q    = (float*)vp;
    cudaGetSymbolAddress(&vp, g_Enew); float* Enew = (float*)vp;
    cudaGetSymbolAddress(&vp, g_Xcat); float* Xcat = (float*)vp;
    cudaGetSymbolAddress(&vp, g_svh);  float* svh  = (float*)vp;
    cudaGetSymbolAddress(&vp, g_tvh);  float* tvh  = (float*)vp;
    cudaGetSymbolAddress(&vp, g_svh2); float* svh2 = (float*)vp;
    cudaGetSymbolAddress(&vp, g_tvh2); float* tvh2 = (float*)vp;

    k_rowsq<<<NPTS / 4, 128>>>(X);
    k_aat_dist_sym<<<528, 256>>>(X);
    k_topk_gemm<<<768, 256>>>(X, theta, XT);   // fused: XT-GEMM || topk
    k_scan<<<1, 1024>>>();

    k_fill<<<176, 256>>>();
    k_gedge_nbr<<<5120, 128>>>();
    k_gnodes_density<<<4608, 256>>>(Xe);       // fused: gather_nodes || density
    k_rhoe<<<16, 256>>>(20, 21);

    // all-head projections
    k_gemm64h2<<<dim3(4, 64), 256>>>(Xe, E, Wh, P, Q);

    // attention pass 1 s/t
    k_svtv4<<<4096, 256>>>(P, Q, axh, 0, svh, tvh);
    // fused: att pass1 || svtv pass2 (double-buffered)
    k_att1_svtv2<<<6144, 256>>>(rho, P, Q, Enew, aeh, svh, tvh, svh2, tvh2);
    // attention pass 2 (ldo = DHID)
    k_att4x<DHEAD><<<2048, 256>>>(rhoe, 21, Enew, DHID, Xcat, DHID, DHEAD, svh2, tvh2, 8, 4);

    // final DA-HGAN layer
    k_rownorm<<<NPTS / 8, 256>>>(Xcat);
    k_density<<<NPTS, 256>>>(Xcat);
    k_rhoe<<<16, 256>>>(22, 23);

    k_gemm64d<<<dim3(4, 64), 256>>>(Xcat, E, W2, P, Q);

    k_svtv1<<<1024, 256>>>(P, ax2, Q, ax2 + DHID, 16, svh, tvh);
    k_attf1_svtv2<<<1536, 256>>>(rho, P, Q, Enew, ae2, svh, tvh, svh2, tvh2);
    k_att4x<DHID><<<512, 256>>>(rhoe, 23, Enew, DHID, out, DHID, 0, svh2, tvh2, 18, 1);
}